// round 3
// baseline (speedup 1.0000x reference)
#include <cuda_runtime.h>
#include <math.h>
#include <stdint.h>

// ---------------- problem constants ----------------
#define NVARD 600
#define NCD   1000
#define HIDD  1024
#define BATCHD 1024
#define MLPOUTD 2200
#define GIND  4800
#define GOUTD 1600
#define MAXITERD 15
#define KKTN  750
#define GLD   1504
#define BLKD  150
#define BILD  152
#define OUT_TOTAL (BATCHD*NVARD + BATCHD + BATCHD + MAXITERD*BATCHD + MAXITERD*BATCHD)

// ---------------- fp32 scratch ----------------
__device__ float g_inp[BATCHD*NVARD];
__device__ float g_nnout[BATCHD*MLPOUTD];
__device__ float g_hst[BATCHD*HIDD];
__device__ float g_lam[BATCHD*NVARD];
__device__ float g_lamnew[BATCHD*NVARD];
__device__ float g_s[BATCHD*NCD];
__device__ float g_snew[BATCHD*NCD];
__device__ float g_res[BATCHD*NCD];
__device__ float g_xi[BATCHD*NVARD];
__device__ float g_gi[BATCHD*3*HIDD];
__device__ float g_gh[BATCHD*3*HIDD];
__device__ float g_gout[BATCHD*GOUTD];
__device__ float g_G[KKTN*GLD];
__device__ float g_P[BLKD*GLD];
__device__ float g_Ucol[KKTN*BILD];
__device__ float g_Einv[BLKD*BILD];
__device__ float g_Ct[NVARD*NCD];
__device__ float g_v0[NVARD];
__device__ float g_negg[NVARD];
__device__ float g_prim[MAXITERD*BATCHD];
__device__ float g_fp[MAXITERD*BATCHD];
__device__ double g_sum2[2];

// ---------------- tf32 (hi,lo) split scratch ----------------
__device__ float2 sW1[HIDD*NVARD];
__device__ float2 sW2[HIDD*HIDD];
__device__ float2 sW3[MLPOUTD*HIDD];
__device__ float2 sWg[HIDD*NVARD];
__device__ float2 sWih[3*HIDD*GIND];
__device__ float2 sWhh[3*HIDD*HIDD];
__device__ float2 sWout[GOUTD*HIDD];
__device__ float2 sC[NCD*NVARD];
__device__ float2 sM[NVARD*NVARD];
__device__ float2 sinp[BATCHD*NVARD];
__device__ float2 sh1[BATCHD*HIDD];
__device__ float2 sh2[BATCHD*HIDD];
__device__ float2 shst[BATCHD*HIDD];
__device__ float2 sbaug[BATCHD*NCD];
__device__ float2 su[BATCHD*NVARD];
__device__ float2 sxi[BATCHD*NVARD];
__device__ float2 sres[BATCHD*NCD];
__device__ float2 sr[BATCHD*GIND];

// ---------------- tf32 split helper ----------------
__device__ __forceinline__ void tf32_split(float x, uint32_t& hi, uint32_t& lo) {
    uint32_t h;
    asm("cvt.rna.tf32.f32 %0, %1;" : "=r"(h) : "f"(x));
    float r = x - __uint_as_float(h);
    uint32_t l;
    asm("cvt.rna.tf32.f32 %0, %1;" : "=r"(l) : "f"(r));
    hi = h; lo = l;
}

__device__ __forceinline__ float2 split2(float x) {
    uint32_t h, l;
    tf32_split(x, h, l);
    return make_float2(__uint_as_float(h), __uint_as_float(l));
}

#define MMA_TF32(ac, a, b) \
    asm volatile("mma.sync.aligned.m16n8k8.row.col.f32.tf32.tf32.f32 " \
                 "{%0,%1,%2,%3},{%4,%5,%6,%7},{%8,%9},{%0,%1,%2,%3};" \
                 : "+f"(ac[0]), "+f"(ac[1]), "+f"(ac[2]), "+f"(ac[3]) \
                 : "r"(a[0]), "r"(a[1]), "r"(a[2]), "r"(a[3]), "r"(b[0]), "r"(b[1]))

// ===================================================================
// Tensor-core GEMM, pre-split 3xTF32 operands (float2 = hi,lo)
// C = act( alpha * A @ op(B) + beta * Cin + bias ), optional split outputs
// act: 0 none, 1 relu, 2 tanh, 3 dual: C=relu(bias-acc), C2=relu(acc-bias)
// ===================================================================
template<int TBM, int TBN>
__global__ void __launch_bounds__(256)
gemm_ts_k(const float2* __restrict__ A, const float2* __restrict__ B,
          float* __restrict__ C, float* __restrict__ C2,
          float2* __restrict__ Csp, float2* __restrict__ Csp2,
          const float* __restrict__ Cin, const float* __restrict__ bias,
          int M, int N, int K, int lda, int ldb, int ldc, int ldcin,
          int transB, float alpha, float beta, int act)
{
    constexpr int WM = TBM / 2;
    constexpr int WN = TBN / 4;
    constexpr int MM = WM / 16;
    constexpr int NN = WN / 8;
    constexpr int APT = TBM * 16 / 256;
    constexpr int BPT = TBN * 16 / 256;
    constexpr int ALD = TBM + 4;
    constexpr int BLD = TBN + 4;

    extern __shared__ float2 smem2[];
    float2* As = smem2;                     // [2][16][ALD]
    float2* Bs = smem2 + 2 * 16 * ALD;      // [2][16][BLD]

    const int tid = threadIdx.x;
    const int wid = tid >> 5;
    const int lane = tid & 31;
    const int lr = lane >> 2;
    const int lc = lane & 3;
    const int warp_m = wid >> 2;
    const int warp_n = wid & 3;
    const int m0 = blockIdx.y * TBM;
    const int n0 = blockIdx.x * TBN;

    float acc[MM][NN][4];
#pragma unroll
    for (int i = 0; i < MM; i++)
#pragma unroll
        for (int j = 0; j < NN; j++)
#pragma unroll
            for (int q = 0; q < 4; q++) acc[i][j][q] = 0.f;

    const int nchunks = (K + 15) / 16;
    const float2 z2 = make_float2(0.f, 0.f);
    float2 ra[APT], rb[BPT];

    // ---- prologue: load chunk 0 ----
    {
#pragma unroll
        for (int i = 0; i < APT; i++) {
            int e = tid + i * 256;
            int m = e >> 4, k = e & 15;
            int gm = m0 + m, gk = k;
            ra[i] = (gm < M && gk < K) ? A[gm * lda + gk] : z2;
        }
        if (transB) {
#pragma unroll
            for (int i = 0; i < BPT; i++) {
                int e = tid + i * 256;
                int n = e >> 4, k = e & 15;
                int gn = n0 + n, gk = k;
                rb[i] = (gn < N && gk < K) ? B[gn * ldb + gk] : z2;
            }
        } else {
#pragma unroll
            for (int i = 0; i < BPT; i++) {
                int e = tid + i * 256;
                int k = e / TBN, n = e & (TBN - 1);
                int gn = n0 + n, gk = k;
                rb[i] = (gn < N && gk < K) ? B[gk * ldb + gn] : z2;
            }
        }
#pragma unroll
        for (int i = 0; i < APT; i++) {
            int e = tid + i * 256;
            As[(e & 15) * ALD + (e >> 4)] = ra[i];
        }
        if (transB) {
#pragma unroll
            for (int i = 0; i < BPT; i++) {
                int e = tid + i * 256;
                Bs[(e & 15) * BLD + (e >> 4)] = rb[i];
            }
        } else {
#pragma unroll
            for (int i = 0; i < BPT; i++) {
                int e = tid + i * 256;
                Bs[(e / TBN) * BLD + (e & (TBN - 1))] = rb[i];
            }
        }
        __syncthreads();
    }

    for (int ch = 0; ch < nchunks; ch++) {
        const int cur = ch & 1;
        const bool have_next = (ch + 1 < nchunks);

        if (have_next) {
            const int kk = (ch + 1) * 16;
#pragma unroll
            for (int i = 0; i < APT; i++) {
                int e = tid + i * 256;
                int m = e >> 4, k = e & 15;
                int gm = m0 + m, gk = kk + k;
                ra[i] = (gm < M && gk < K) ? A[gm * lda + gk] : z2;
            }
            if (transB) {
#pragma unroll
                for (int i = 0; i < BPT; i++) {
                    int e = tid + i * 256;
                    int n = e >> 4, k = e & 15;
                    int gn = n0 + n, gk = kk + k;
                    rb[i] = (gn < N && gk < K) ? B[gn * ldb + gk] : z2;
                }
            } else {
#pragma unroll
                for (int i = 0; i < BPT; i++) {
                    int e = tid + i * 256;
                    int k = e / TBN, n = e & (TBN - 1);
                    int gn = n0 + n, gk = kk + k;
                    rb[i] = (gn < N && gk < K) ? B[gk * ldb + gn] : z2;
                }
            }
        }

        // ---- compute on current buffer: pure LDS + MMA ----
#pragma unroll
        for (int kb = 0; kb < 16; kb += 8) {
            uint32_t ahi[MM][4], alo[MM][4];
            uint32_t bhi[NN][2], blo[NN][2];
#pragma unroll
            for (int mm = 0; mm < MM; mm++) {
                int mrow = warp_m * WM + mm * 16 + lr;
                float2 x0 = As[(cur * 16 + kb + lc) * ALD + mrow];
                float2 x1 = As[(cur * 16 + kb + lc) * ALD + mrow + 8];
                float2 x2 = As[(cur * 16 + kb + 4 + lc) * ALD + mrow];
                float2 x3 = As[(cur * 16 + kb + 4 + lc) * ALD + mrow + 8];
                ahi[mm][0] = __float_as_uint(x0.x); alo[mm][0] = __float_as_uint(x0.y);
                ahi[mm][1] = __float_as_uint(x1.x); alo[mm][1] = __float_as_uint(x1.y);
                ahi[mm][2] = __float_as_uint(x2.x); alo[mm][2] = __float_as_uint(x2.y);
                ahi[mm][3] = __float_as_uint(x3.x); alo[mm][3] = __float_as_uint(x3.y);
            }
#pragma unroll
            for (int nn = 0; nn < NN; nn++) {
                int ncol = warp_n * WN + nn * 8 + lr;
                float2 y0 = Bs[(cur * 16 + kb + lc) * BLD + ncol];
                float2 y1 = Bs[(cur * 16 + kb + 4 + lc) * BLD + ncol];
                bhi[nn][0] = __float_as_uint(y0.x); blo[nn][0] = __float_as_uint(y0.y);
                bhi[nn][1] = __float_as_uint(y1.x); blo[nn][1] = __float_as_uint(y1.y);
            }
#pragma unroll
            for (int mm = 0; mm < MM; mm++) {
#pragma unroll
                for (int nn = 0; nn < NN; nn++) {
                    MMA_TF32(acc[mm][nn], alo[mm], bhi[nn]);
                    MMA_TF32(acc[mm][nn], ahi[mm], blo[nn]);
                    MMA_TF32(acc[mm][nn], ahi[mm], bhi[nn]);
                }
            }
        }

        if (have_next) {
            const int nxt = cur ^ 1;
#pragma unroll
            for (int i = 0; i < APT; i++) {
                int e = tid + i * 256;
                As[(nxt * 16 + (e & 15)) * ALD + (e >> 4)] = ra[i];
            }
            if (transB) {
#pragma unroll
                for (int i = 0; i < BPT; i++) {
                    int e = tid + i * 256;
                    Bs[(nxt * 16 + (e & 15)) * BLD + (e >> 4)] = rb[i];
                }
            } else {
#pragma unroll
                for (int i = 0; i < BPT; i++) {
                    int e = tid + i * 256;
                    Bs[(nxt * 16 + (e / TBN)) * BLD + (e & (TBN - 1))] = rb[i];
                }
            }
        }
        __syncthreads();
    }

    // ---- epilogue ----
#pragma unroll
    for (int mm = 0; mm < MM; mm++) {
        int r0 = m0 + warp_m * WM + mm * 16 + lr;
#pragma unroll
        for (int nn = 0; nn < NN; nn++) {
            int c0 = n0 + warp_n * WN + nn * 8 + lc * 2;
#pragma unroll
            for (int q = 0; q < 4; q++) {
                int row = r0 + (q >> 1) * 8;
                int col = c0 + (q & 1);
                if (row >= M || col >= N) continue;
                float v = alpha * acc[mm][nn][q];
                if (beta != 0.f) v += beta * Cin[row * ldcin + col];
                if (act == 3) {
                    float cc = bias[col];
                    float sv = fmaxf(cc - v, 0.f);
                    float rv = fmaxf(v - cc, 0.f);
                    C[row * ldc + col] = sv;
                    C2[row * ldc + col] = rv;
                    if (Csp2) Csp2[row * ldc + col] = split2(rv);
                } else {
                    if (bias) v += bias[col];
                    if (act == 1) v = fmaxf(v, 0.f);
                    else if (act == 2) v = tanhf(v);
                    C[row * ldc + col] = v;
                    if (Csp) Csp[row * ldc + col] = split2(v);
                }
            }
        }
    }
}

// ---------------- fp32 SIMT GEMM (KKT inverse pipeline only) --------
#define BM 64
#define BN 64
#define BKK 16

__global__ void gemm_k(const float* __restrict__ A, const float* __restrict__ B,
                       float* __restrict__ C, const float* __restrict__ Cin,
                       int M, int N, int K, int lda, int ldb, int ldc, int ldcin,
                       int transB, float alpha, float beta)
{
    __shared__ float As[BKK][BM];
    __shared__ float Bs[BKK][BN];
    const int tid = threadIdx.x;
    const int tx = tid & 15, ty = tid >> 4;
    const int m0 = blockIdx.y * BM, n0 = blockIdx.x * BN;
    float acc[4][4] = {};

    for (int kk = 0; kk < K; kk += BKK) {
#pragma unroll
        for (int i = 0; i < 4; i++) {
            int e = tid + i * 256;
            int m = e >> 4, k = e & 15;
            int gm = m0 + m, gk = kk + k;
            As[k][m] = (gm < M && gk < K) ? A[gm * lda + gk] : 0.f;
        }
        if (transB) {
#pragma unroll
            for (int i = 0; i < 4; i++) {
                int e = tid + i * 256;
                int n = e >> 4, k = e & 15;
                int gn = n0 + n, gk = kk + k;
                Bs[k][n] = (gn < N && gk < K) ? B[gn * ldb + gk] : 0.f;
            }
        } else {
#pragma unroll
            for (int i = 0; i < 4; i++) {
                int e = tid + i * 256;
                int k = e >> 6, n = e & 63;
                int gn = n0 + n, gk = kk + k;
                Bs[k][n] = (gn < N && gk < K) ? B[gk * ldb + gn] : 0.f;
            }
        }
        __syncthreads();
#pragma unroll
        for (int k = 0; k < BKK; k++) {
            float a0 = As[k][ty*4+0], a1 = As[k][ty*4+1], a2 = As[k][ty*4+2], a3 = As[k][ty*4+3];
            float b0 = Bs[k][tx*4+0], b1 = Bs[k][tx*4+1], b2 = Bs[k][tx*4+2], b3 = Bs[k][tx*4+3];
            acc[0][0] += a0*b0; acc[0][1] += a0*b1; acc[0][2] += a0*b2; acc[0][3] += a0*b3;
            acc[1][0] += a1*b0; acc[1][1] += a1*b1; acc[1][2] += a1*b2; acc[1][3] += a1*b3;
            acc[2][0] += a2*b0; acc[2][1] += a2*b1; acc[2][2] += a2*b2; acc[2][3] += a2*b3;
            acc[3][0] += a3*b0; acc[3][1] += a3*b1; acc[3][2] += a3*b2; acc[3][3] += a3*b3;
        }
        __syncthreads();
    }

#pragma unroll
    for (int i = 0; i < 4; i++) {
        int row = m0 + ty*4 + i;
        if (row >= M) continue;
#pragma unroll
        for (int j = 0; j < 4; j++) {
            int col = n0 + tx*4 + j;
            if (col >= N) continue;
            float v = alpha * acc[i][j];
            if (beta != 0.f) v += beta * Cin[row * ldcin + col];
            C[row * ldc + col] = v;
        }
    }
}

// ---------------- split kernels ----------------
__global__ void split_k(const float* __restrict__ x, float2* __restrict__ y, int n) {
    int i = blockIdx.x * blockDim.x + threadIdx.x;
    if (i >= n) return;
    y[i] = split2(x[i]);
}

__global__ void packM_split_k() {
    int i = blockIdx.x * blockDim.x + threadIdx.x;
    if (i >= NVARD * NVARD) return;
    int r = i / NVARD, c = i % NVARD;
    sM[i] = split2(g_G[r * GLD + 750 + c]);
}

// ---------------- statistics / normalization ----------------
__global__ void stats_zero_k() { g_sum2[0] = 0.0; g_sum2[1] = 0.0; }

__global__ void stats_k(const float* __restrict__ x, int n) {
    float s = 0.f, ss = 0.f;
    for (int i = blockIdx.x * blockDim.x + threadIdx.x; i < n; i += gridDim.x * blockDim.x) {
        float v = x[i]; s += v; ss += v * v;
    }
    __shared__ float s1[256], s2[256];
    s1[threadIdx.x] = s; s2[threadIdx.x] = ss;
    __syncthreads();
    for (int o = 128; o > 0; o >>= 1) {
        if (threadIdx.x < o) { s1[threadIdx.x] += s1[threadIdx.x+o]; s2[threadIdx.x] += s2[threadIdx.x+o]; }
        __syncthreads();
    }
    if (threadIdx.x == 0) {
        atomicAdd(&g_sum2[0], (double)s1[0]);
        atomicAdd(&g_sum2[1], (double)s2[0]);
    }
}

__global__ void normalize_k(const float* __restrict__ x, int n) {
    double sum = g_sum2[0], sumsq = g_sum2[1];
    double mean = sum / n;
    double var = (sumsq - sum * sum / n) / (double)(n - 1);
    float istd = 1.0f / ((float)sqrt(var) + 1e-8f);
    float m = (float)mean;
    for (int i = blockIdx.x * blockDim.x + threadIdx.x; i < n; i += gridDim.x * blockDim.x) {
        float v = (x[i] - m) * istd;
        g_inp[i] = v;
        sinp[i] = split2(v);
    }
}

// ---------------- small setup kernels ----------------
__global__ void split_nnout_k() {
    int idx = blockIdx.x * blockDim.x + threadIdx.x;
    int total = BATCHD * 1600;
    if (idx >= total) return;
    int b = idx / 1600, r = idx % 1600;
    if (r < NVARD) g_lam[b * NVARD + r] = g_nnout[b * MLPOUTD + NVARD + r];
    else {
        int j = r - NVARD;
        g_s[b * NCD + j] = fmaxf(g_nnout[b * MLPOUTD + 2 * NVARD + j], 0.f);
    }
}

__global__ void transpose_C_k(const float* __restrict__ Cm) {
    int idx = blockIdx.x * blockDim.x + threadIdx.x;
    if (idx >= NVARD * NCD) return;
    int i = idx / NCD, k = idx % NCD;
    g_Ct[i * NCD + k] = Cm[k * NVARD + i];
}

__global__ void negg_k(const float* __restrict__ gv) {
    int j = blockIdx.x * blockDim.x + threadIdx.x;
    if (j < NVARD) g_negg[j] = -gv[j];
}

__global__ void init_G_k() {
    int idx = blockIdx.x * blockDim.x + threadIdx.x;
    if (idx >= KKTN * GLD) return;
    int r = idx / GLD, c = idx % GLD;
    float v = 0.f;
    if (c >= 750) {
        if (c - 750 == r) v = 1.f;
    } else if (r >= 600 && c < 600) {
        int rr = r - 600, t = rr / 3, i = rr % 3;
        if (c / 12 == t && (c % 12) % 3 == i) v = 1.f;
    } else if (r < 600 && c >= 600) {
        int cc = c - 600, t = cc / 3, i = cc % 3;
        if (r / 12 == t && (r % 12) % 3 == i) v = 1.f;
    }
    g_G[idx] = v;
}

__global__ void v0_k() {
    int j = blockIdx.x * blockDim.x + threadIdx.x;
    if (j >= NVARD) return;
    float beq = 30.0f * 9.81f;
    float acc = 0.f;
    for (int t = 0; t < 50; t++) acc += g_G[j * GLD + 750 + 600 + 3 * t + 2];
    g_v0[j] = beq * acc;
}

// ---------------- blocked Gauss-Jordan helpers ----------------
__global__ void copy_cols_k(int kb) {
    int idx = blockIdx.x * blockDim.x + threadIdx.x;
    if (idx >= KKTN * BLKD) return;
    int r = idx / BLKD, j = idx % BLKD;
    g_Ucol[r * BILD + j] = g_G[r * GLD + kb * BLKD + j];
}

__global__ void inv_block_k(int kb) {
    extern __shared__ float s[];
    const int n = BLKD, ld = BILD;
    int tid = threadIdx.x, nt = blockDim.x;
    for (int e = tid; e < n * n; e += nt)
        s[(e / n) * ld + (e % n)] = g_Ucol[(kb * BLKD + e / n) * BILD + (e % n)];
    __shared__ float fcol[BLKD];
    __shared__ float s_ipiv;
    __syncthreads();
    for (int p = 0; p < n; p++) {
        if (tid == 0) s_ipiv = 1.0f / s[p * ld + p];
        __syncthreads();
        float ipiv = s_ipiv;
        for (int j = tid; j < n; j += nt) if (j != p) s[p * ld + j] *= ipiv;
        for (int r = tid; r < n; r += nt) fcol[r] = (r == p) ? 0.f : s[r * ld + p];
        __syncthreads();
        for (int e = tid; e < n * n; e += nt) {
            int r = e / n, j = e % n;
            if (r != p && j != p) s[r * ld + j] -= fcol[r] * s[p * ld + j];
        }
        __syncthreads();
        for (int r = tid; r < n; r += nt) {
            if (r == p) s[p * ld + p] = ipiv;
            else s[r * ld + p] = -fcol[r] * ipiv;
        }
        __syncthreads();
    }
    for (int e = tid; e < n * n; e += nt)
        g_Einv[(e / n) * BILD + (e % n)] = s[(e / n) * ld + (e % n)];
}

__global__ void writeback_k(int kb) {
    int idx = blockIdx.x * blockDim.x + threadIdx.x;
    if (idx >= BLKD * GLD) return;
    int r = idx / GLD, j = idx % GLD;
    g_G[(kb * BLKD + r) * GLD + j] = g_P[idx];
    if (j < BILD) g_Ucol[(kb * BLKD + r) * BILD + j] = 0.f;
}

// ---------------- iteration elementwise kernels ----------------
__global__ void baug_k(const float* __restrict__ cvec) {
    int idx = blockIdx.x * blockDim.x + threadIdx.x;
    if (idx >= BATCHD * NCD) return;
    int j = idx % NCD;
    sbaug[idx] = split2(cvec[j] - g_s[idx]);
}

__global__ void rownorm_k(const float* __restrict__ v, int ncols, float* __restrict__ out) {
    int b = blockIdx.x;
    float acc = 0.f;
    for (int j = threadIdx.x; j < ncols; j += blockDim.x) {
        float t = v[b * ncols + j]; acc += t * t;
    }
    __shared__ float sm[256];
    sm[threadIdx.x] = acc; __syncthreads();
    for (int o = 128; o > 0; o >>= 1) {
        if (threadIdx.x < o) sm[threadIdx.x] += sm[threadIdx.x + o];
        __syncthreads();
    }
    if (threadIdx.x == 0) out[b] = sqrtf(sm[0]);
}

__global__ void concat_r_k() {
    int idx = blockIdx.x * blockDim.x + threadIdx.x;
    if (idx >= BATCHD * GIND) return;
    int b = idx / GIND, q = idx % GIND;
    float v;
    if (q < 1000)       v = g_s[b * NCD + q];
    else if (q < 1600)  v = g_lam[b * NVARD + (q - 1000)];
    else if (q < 2600)  v = g_snew[b * NCD + (q - 1600)];
    else if (q < 3200)  v = g_lamnew[b * NVARD + (q - 2600)];
    else if (q < 4200)  v = g_snew[b * NCD + (q - 3200)] - g_s[b * NCD + (q - 3200)];
    else                v = g_lamnew[b * NVARD + (q - 4200)] - g_lam[b * NVARD + (q - 4200)];
    sr[idx] = split2(v);
}

__device__ __forceinline__ float sigmoidf(float x) { return 1.0f / (1.0f + expf(-x)); }

__global__ void gru_k() {
    int idx = blockIdx.x * blockDim.x + threadIdx.x;
    if (idx >= BATCHD * HIDD) return;
    int b = idx >> 10, j = idx & 1023;
    int base = b * 3 * HIDD + j;
    float ir = g_gi[base], iz = g_gi[base + HIDD], in_ = g_gi[base + 2 * HIDD];
    float hr = g_gh[base], hz = g_gh[base + HIDD], hn = g_gh[base + 2 * HIDD];
    float rg = sigmoidf(ir + hr);
    float z  = sigmoidf(iz + hz);
    float n  = tanhf(in_ + rg * hn);
    float h  = g_hst[idx];
    float hnew = (1.f - z) * n + z * h;
    g_hst[idx] = hnew;
    shst[idx] = split2(hnew);
}

__global__ void finalize_k(int t) {
    int b = blockIdx.x;
    float accs = 0.f, accl = 0.f;
    for (int j = threadIdx.x; j < GOUTD; j += blockDim.x) {
        float go = g_gout[b * GOUTD + j];
        if (j < NCD) {
            float sf = fmaxf(g_snew[b * NCD + j] + go, 0.f);
            float d = sf - g_s[b * NCD + j];
            accs += d * d;
            g_s[b * NCD + j] = sf;
        } else {
            int j2 = j - NCD;
            float lf = g_lamnew[b * NVARD + j2] + go;
            float d = lf - g_lam[b * NVARD + j2];
            accl += d * d;
            g_lam[b * NVARD + j2] = lf;
        }
    }
    __shared__ float sm1[256], sm2[256];
    sm1[threadIdx.x] = accs; sm2[threadIdx.x] = accl;
    __syncthreads();
    for (int o = 128; o > 0; o >>= 1) {
        if (threadIdx.x < o) { sm1[threadIdx.x] += sm1[threadIdx.x+o]; sm2[threadIdx.x] += sm2[threadIdx.x+o]; }
        __syncthreads();
    }
    if (threadIdx.x == 0)
        g_fp[t * BATCHD + b] = sqrtf(sm2[0]) + sqrtf(sm1[0]);
}

// ---------------- output assembly ----------------
__global__ void output_k(float* __restrict__ out) {
    int idx = blockIdx.x * blockDim.x + threadIdx.x;
    if (idx >= OUT_TOTAL) return;
    const int XI_END = BATCHD * NVARD;
    const int AFP_END = XI_END + BATCHD;
    const int APR_END = AFP_END + BATCHD;
    const int PH_END = APR_END + MAXITERD * BATCHD;
    if (idx < XI_END) out[idx] = g_xi[idx];
    else if (idx < AFP_END) {
        int b = idx - XI_END;
        float a = 0.f;
        for (int t = 0; t < MAXITERD; t++) a += g_fp[t * BATCHD + b];
        out[idx] = a / (float)MAXITERD;
    } else if (idx < APR_END) {
        int b = idx - AFP_END;
        float a = 0.f;
        for (int t = 0; t < MAXITERD; t++) a += g_prim[t * BATCHD + b];
        out[idx] = a / (float)MAXITERD;
    } else if (idx < PH_END) out[idx] = g_prim[idx - APR_END];
    else out[idx] = g_fp[idx - PH_END];
}

// ---------------- host side ----------------
static inline int ceil_div(int a, int b) { return (a + b - 1) / b; }

static void gemm(const float* A, const float* B, float* C, const float* Cin,
                 int M, int N, int K, int lda, int ldb, int ldc, int ldcin,
                 int transB, float alpha, float beta)
{
    dim3 grid((N + BN - 1) / BN, (M + BM - 1) / BM);
    gemm_k<<<grid, 256>>>(A, B, C, Cin, M, N, K, lda, ldb, ldc, ldcin, transB, alpha, beta);
}

static void gemm_tc(const float2* A, const float2* B, float* C, float* C2,
                    float2* Csp, float2* Csp2,
                    const float* Cin, const float* bias,
                    int M, int N, int K, int lda, int ldb, int ldc, int ldcin,
                    int transB, float alpha, float beta, int act)
{
    long tiles128 = (long)((M + 127) / 128) * ((N + 127) / 128);
    if (M >= 128 && tiles128 >= 96) {
        size_t smem = (2 * 16 * (128 + 4) * 2) * sizeof(float2);
        dim3 grid((N + 127) / 128, (M + 127) / 128);
        gemm_ts_k<128, 128><<<grid, 256, smem>>>(A, B, C, C2, Csp, Csp2, Cin, bias,
                                                 M, N, K, lda, ldb, ldc, ldcin,
                                                 transB, alpha, beta, act);
    } else {
        size_t smem = (2 * 16 * (64 + 4) * 2) * sizeof(float2);
        dim3 grid((N + 63) / 64, (M + 63) / 64);
        gemm_ts_k<64, 64><<<grid, 256, smem>>>(A, B, C, C2, Csp, Csp2, Cin, bias,
                                               M, N, K, lda, ldb, ldc, ldcin,
                                               transB, alpha, beta, act);
    }
}

extern "C" void kernel_launch(void* const* d_in, const int* in_sizes, int n_in,
                              void* d_out, int out_size) {
    const float* X    = (const float*)d_in[0];
    const float* Hm   = (const float*)d_in[1];
    const float* gv   = (const float*)d_in[2];
    const float* Cm   = (const float*)d_in[3];
    const float* cvec = (const float*)d_in[4];
    const float* W1   = (const float*)d_in[5];
    const float* b1   = (const float*)d_in[6];
    const float* W2   = (const float*)d_in[7];
    const float* b2   = (const float*)d_in[8];
    const float* W3   = (const float*)d_in[9];
    const float* b3   = (const float*)d_in[10];
    const float* Wg   = (const float*)d_in[11];
    const float* bg   = (const float*)d_in[12];
    const float* W_ih = (const float*)d_in[13];
    const float* W_hh = (const float*)d_in[14];
    const float* b_ih = (const float*)d_in[15];
    const float* b_hh = (const float*)d_in[16];
    const float* W_out= (const float*)d_in[17];
    const float* b_out= (const float*)d_in[18];
    float* out = (float*)d_out;

    // resolve device scratch addresses
    float *inp, *nnout, *hst, *lam, *lamnew, *s, *snew, *res, *xi, *gi, *gh, *gout,
          *G, *P, *Ucol, *Einv, *Ct, *v0, *negg, *prim, *fp;
    float2 *pW1, *pW2, *pW3, *pWg, *pWih, *pWhh, *pWout, *pC, *pM,
           *pinp, *ph1, *ph2, *phst, *pbaug, *pu, *pxi, *pres, *pr;
    float g_h1f_dummy; (void)g_h1f_dummy;
    cudaGetSymbolAddress((void**)&inp, g_inp);
    cudaGetSymbolAddress((void**)&nnout, g_nnout);
    cudaGetSymbolAddress((void**)&hst, g_hst);
    cudaGetSymbolAddress((void**)&lam, g_lam);
    cudaGetSymbolAddress((void**)&lamnew, g_lamnew);
    cudaGetSymbolAddress((void**)&s, g_s);
    cudaGetSymbolAddress((void**)&snew, g_snew);
    cudaGetSymbolAddress((void**)&res, g_res);
    cudaGetSymbolAddress((void**)&xi, g_xi);
    cudaGetSymbolAddress((void**)&gi, g_gi);
    cudaGetSymbolAddress((void**)&gh, g_gh);
    cudaGetSymbolAddress((void**)&gout, g_gout);
    cudaGetSymbolAddress((void**)&G, g_G);
    cudaGetSymbolAddress((void**)&P, g_P);
    cudaGetSymbolAddress((void**)&Ucol, g_Ucol);
    cudaGetSymbolAddress((void**)&Einv, g_Einv);
    cudaGetSymbolAddress((void**)&Ct, g_Ct);
    cudaGetSymbolAddress((void**)&v0, g_v0);
    cudaGetSymbolAddress((void**)&negg, g_negg);
    cudaGetSymbolAddress((void**)&prim, g_prim);
    cudaGetSymbolAddress((void**)&fp, g_fp);
    cudaGetSymbolAddress((void**)&pW1, sW1);
    cudaGetSymbolAddress((void**)&pW2, sW2);
    cudaGetSymbolAddress((void**)&pW3, sW3);
    cudaGetSymbolAddress((void**)&pWg, sWg);
    cudaGetSymbolAddress((void**)&pWih, sWih);
    cudaGetSymbolAddress((void**)&pWhh, sWhh);
    cudaGetSymbolAddress((void**)&pWout, sWout);
    cudaGetSymbolAddress((void**)&pC, sC);
    cudaGetSymbolAddress((void**)&pM, sM);
    cudaGetSymbolAddress((void**)&pinp, sinp);
    cudaGetSymbolAddress((void**)&ph1, sh1);
    cudaGetSymbolAddress((void**)&ph2, sh2);
    cudaGetSymbolAddress((void**)&phst, shst);
    cudaGetSymbolAddress((void**)&pbaug, sbaug);
    cudaGetSymbolAddress((void**)&pu, su);
    cudaGetSymbolAddress((void**)&pxi, sxi);
    cudaGetSymbolAddress((void**)&pres, sres);
    cudaGetSymbolAddress((void**)&pr, sr);

    // fp32 staging for tc outputs that need fp32 (reuse g_nnout-sized areas is risky; use dedicated)
    static float* h1f = nullptr; static float* h2f = nullptr; static float* uf = nullptr;
    // h1/h2/u fp32 targets: reuse g_gi/g_gh/g_gout scratch (free at those points)
    h1f = gi;   // [1024*1024] fits in g_gi (1024*3072)
    h2f = gh;   // fits in g_gh
    uf  = gout; // [1024*600] fits in g_gout (1024*1600)

    cudaFuncSetAttribute(inv_block_k, cudaFuncAttributeMaxDynamicSharedMemorySize,
                         BLKD * BILD * (int)sizeof(float));
    cudaFuncSetAttribute(gemm_ts_k<128, 128>, cudaFuncAttributeMaxDynamicSharedMemorySize,
                         (2 * 16 * (128 + 4) * 2) * (int)sizeof(float2));
    cudaFuncSetAttribute(gemm_ts_k<64, 64>, cudaFuncAttributeMaxDynamicSharedMemorySize,
                         (2 * 16 * (64 + 4) * 2) * (int)sizeof(float2));

    const int TPB = 256;
    const int NTOT = BATCHD * NVARD;

    // ---- split all weights (reused every iteration) ----
    split_k<<<ceil_div(HIDD * NVARD, TPB), TPB>>>(W1, pW1, HIDD * NVARD);
    split_k<<<ceil_div(HIDD * HIDD, TPB), TPB>>>(W2, pW2, HIDD * HIDD);
    split_k<<<ceil_div(MLPOUTD * HIDD, TPB), TPB>>>(W3, pW3, MLPOUTD * HIDD);
    split_k<<<ceil_div(HIDD * NVARD, TPB), TPB>>>(Wg, pWg, HIDD * NVARD);
    split_k<<<ceil_div(3 * HIDD * GIND, TPB), TPB>>>(W_ih, pWih, 3 * HIDD * GIND);
    split_k<<<ceil_div(3 * HIDD * HIDD, TPB), TPB>>>(W_hh, pWhh, 3 * HIDD * HIDD);
    split_k<<<ceil_div(GOUTD * HIDD, TPB), TPB>>>(W_out, pWout, GOUTD * HIDD);
    split_k<<<ceil_div(NCD * NVARD, TPB), TPB>>>(Cm, pC, NCD * NVARD);

    // ---- input normalization (+ split) ----
    stats_zero_k<<<1, 1>>>();
    stats_k<<<512, TPB>>>(X, NTOT);
    normalize_k<<<ceil_div(NTOT, TPB), TPB>>>(X, NTOT);

    // ---- MLP warm start (tensor cores, split chained) ----
    gemm_tc(pinp, pW1, h1f, nullptr, ph1, nullptr, nullptr, b1,
            BATCHD, HIDD, NVARD, NVARD, NVARD, HIDD, 0, 1, 1.f, 0.f, 1);
    gemm_tc(ph1, pW2, h2f, nullptr, ph2, nullptr, nullptr, b2,
            BATCHD, HIDD, HIDD, HIDD, HIDD, HIDD, 0, 1, 1.f, 0.f, 1);
    gemm_tc(ph2, pW3, nnout, nullptr, nullptr, nullptr, nullptr, b3,
            BATCHD, MLPOUTD, HIDD, HIDD, HIDD, MLPOUTD, 0, 1, 1.f, 0.f, 0);
    split_nnout_k<<<ceil_div(BATCHD * 1600, TPB), TPB>>>();
    gemm_tc(pinp, pWg, hst, nullptr, phst, nullptr, nullptr, bg,
            BATCHD, HIDD, NVARD, NVARD, NVARD, HIDD, 0, 1, 1.f, 0.f, 2);

    // ---- KKT build + blocked Gauss-Jordan inverse (fp32 SIMT) ----
    transpose_C_k<<<ceil_div(NVARD * NCD, TPB), TPB>>>(Cm);
    negg_k<<<ceil_div(NVARD, TPB), TPB>>>(gv);
    init_G_k<<<ceil_div(KKTN * GLD, TPB), TPB>>>();
    gemm(Ct, Ct, G, Hm, NVARD, NVARD, NCD, NCD, NCD, GLD, NVARD, 1, 1.f, 1.f);
    for (int kb = 0; kb < KKTN / BLKD; kb++) {
        copy_cols_k<<<ceil_div(KKTN * BLKD, TPB), TPB>>>(kb);
        inv_block_k<<<1, 1024, BLKD * BILD * sizeof(float)>>>(kb);
        gemm(Einv, G + kb * BLKD * GLD, P, nullptr,
             BLKD, GLD, BLKD, BILD, GLD, GLD, 0, 0, 1.f, 0.f);
        writeback_k<<<ceil_div(BLKD * GLD, TPB), TPB>>>(kb);
        gemm(Ucol, P, G, G,
             KKTN, GLD, BLKD, BILD, GLD, GLD, GLD, 0, -1.f, 1.f);
    }
    v0_k<<<ceil_div(NVARD, TPB), TPB>>>();
    packM_split_k<<<ceil_div(NVARD * NVARD, TPB), TPB>>>();

    // ---- 15 fixed-point iterations ----
    for (int t = 0; t < MAXITERD; t++) {
        baug_k<<<ceil_div(BATCHD * NCD, TPB), TPB>>>(cvec);
        // u = (c-s)@C + lam - g  (split output chained into xi GEMM)
        gemm_tc(pbaug, pC, uf, nullptr, pu, nullptr, lam, negg,
                BATCHD, NVARD, NCD, NCD, NVARD, NVARD, NVARD, 0, 1.f, 1.f, 0);
        // xi = u @ M + v0
        gemm_tc(pu, pM, xi, nullptr, pxi, nullptr, nullptr, v0,
                BATCHD, NVARD, NVARD, NVARD, NVARD, NVARD, 0, 0, 1.f, 0.f, 0);
        // Cx = xi @ C^T ; s_new = relu(c - Cx), res = relu(Cx - c) (+ split res)
        gemm_tc(pxi, pC, snew, res, nullptr, pres, nullptr, cvec,
                BATCHD, NCD, NVARD, NVARD, NVARD, NCD, NCD, 1, 1.f, 0.f, 3);
        rownorm_k<<<BATCHD, 256>>>(res, NCD, prim + t * BATCHD);
        // lam_new = lam - res @ C
        gemm_tc(pres, pC, lamnew, nullptr, nullptr, nullptr, lam, nullptr,
                BATCHD, NVARD, NCD, NCD, NVARD, NVARD, NVARD, 0, -1.f, 1.f, 0);
        concat_r_k<<<ceil_div(BATCHD * GIND, TPB), TPB>>>();
        // GRU gates
        gemm_tc(pr, pWih, gi, nullptr, nullptr, nullptr, nullptr, b_ih,
                BATCHD, 3 * HIDD, GIND, GIND, GIND, 3 * HIDD, 0, 1, 1.f, 0.f, 0);
        gemm_tc(phst, pWhh, gh, nullptr, nullptr, nullptr, nullptr, b_hh,
                BATCHD, 3 * HIDD, HIDD, HIDD, HIDD, 3 * HIDD, 0, 1, 1.f, 0.f, 0);
        gru_k<<<ceil_div(BATCHD * HIDD, TPB), TPB>>>();
        // output head
        gemm_tc(phst, pWout, gout, nullptr, nullptr, nullptr, nullptr, b_out,
                BATCHD, GOUTD, HIDD, HIDD, HIDD, GOUTD, 0, 1, 1.f, 0.f, 0);
        finalize_k<<<BATCHD, 256>>>(t);
    }

    output_k<<<ceil_div(OUT_TOTAL, TPB), TPB>>>(out);
    (void)in_sizes; (void)n_in; (void)out_size;
}

// round 4
// speedup vs baseline: 1.2783x; 1.2783x over previous
#include <cuda_runtime.h>
#include <math.h>
#include <stdint.h>

// ---------------- problem constants ----------------
#define NVARD 600
#define NCD   1000
#define HIDD  1024
#define BATCHD 1024
#define MLPOUTD 2200
#define GIND4 3200
#define GOUTD 1600
#define MAXITERD 15
#define KKTN  750
#define GLD   1504
#define BLKD  150
#define BILD  152
#define XBL   1600      // [baug | lam] width
#define OUT_TOTAL (BATCHD*NVARD + BATCHD + BATCHD + MAXITERD*BATCHD + MAXITERD*BATCHD)

// ---------------- fp32 scratch ----------------
__device__ float g_inp[BATCHD*NVARD];
__device__ float g_nnout[BATCHD*MLPOUTD];
__device__ float g_hst[BATCHD*HIDD];
__device__ float g_lam[BATCHD*NVARD];
__device__ float g_lamnew[BATCHD*NVARD];
__device__ float g_s[BATCHD*NCD];
__device__ float g_snew[BATCHD*NCD];
__device__ float g_res[BATCHD*NCD];
__device__ float g_xi[BATCHD*NVARD];
__device__ float g_gi[BATCHD*3*HIDD];
__device__ float g_gh[BATCHD*3*HIDD];
__device__ float g_gout[BATCHD*GOUTD];
__device__ float g_G[KKTN*GLD];
__device__ float g_P[BLKD*GLD];
__device__ float g_Ucol[KKTN*BILD];
__device__ float g_Einv[BLKD*BILD];
__device__ float g_Ct[NVARD*NCD];
__device__ float g_v0[NVARD];
__device__ float g_bxi[NVARD];
__device__ float g_prim[MAXITERD*BATCHD];
__device__ float g_fp[MAXITERD*BATCHD];
__device__ double g_sum2[2];

// ---------------- tf32 (hi,lo) split scratch ----------------
__device__ float2 sW1[HIDD*NVARD];
__device__ float2 sW2[HIDD*HIDD];
__device__ float2 sW3[MLPOUTD*HIDD];
__device__ float2 sWg[HIDD*NVARD];
__device__ float2 sWih4[3*HIDD*GIND4];
__device__ float2 sWhh[3*HIDD*HIDD];
__device__ float2 sWout[GOUTD*HIDD];
__device__ float2 sC[NCD*NVARD];
__device__ float2 sCt[NVARD*NCD];
__device__ float2 sBxi[NVARD*XBL];
__device__ float2 sbl[BATCHD*XBL];
__device__ float2 sinp[BATCHD*NVARD];
__device__ float2 sh1[BATCHD*HIDD];
__device__ float2 sh2[BATCHD*HIDD];
__device__ float2 shst[BATCHD*HIDD];
__device__ float2 sxi[BATCHD*NVARD];
__device__ float2 sres[BATCHD*NCD];
__device__ float2 sr4[BATCHD*GIND4];

// ---------------- tf32 split helper ----------------
__device__ __forceinline__ float2 split2(float x) {
    uint32_t h;
    asm("cvt.rna.tf32.f32 %0, %1;" : "=r"(h) : "f"(x));
    float r = x - __uint_as_float(h);
    uint32_t l;
    asm("cvt.rna.tf32.f32 %0, %1;" : "=r"(l) : "f"(r));
    return make_float2(__uint_as_float(h), __uint_as_float(l));
}

#define MMA_TF32(ac, a, b) \
    asm volatile("mma.sync.aligned.m16n8k8.row.col.f32.tf32.tf32.f32 " \
                 "{%0,%1,%2,%3},{%4,%5,%6,%7},{%8,%9},{%0,%1,%2,%3};" \
                 : "+f"(ac[0]), "+f"(ac[1]), "+f"(ac[2]), "+f"(ac[3]) \
                 : "r"(a[0]), "r"(a[1]), "r"(a[2]), "r"(a[3]), "r"(b[0]), "r"(b[1]))

// ===================================================================
// Tensor-core GEMM, pre-split 3xTF32 operands.  B always [N,K] (transB).
// C = act( alpha * A @ B^T + beta * Cin + bias )
// act: 0 none, 1 relu, 2 tanh, 3 dual: C=relu(bias-acc), C2=relu(acc-bias)
// ===================================================================
template<int TBM, int TBN>
__global__ void __launch_bounds__(256)
gemm_ts_k(const float2* __restrict__ A, const float2* __restrict__ B,
          float* __restrict__ C, float* __restrict__ C2,
          float2* __restrict__ Csp, float2* __restrict__ Csp2,
          const float* __restrict__ Cin, const float* __restrict__ bias,
          int M, int N, int K, int lda, int ldb, int ldc, int ldcin,
          float alpha, float beta, int act)
{
    constexpr int WM = TBM / 2;
    constexpr int WN = TBN / 4;
    constexpr int MM = WM / 16;
    constexpr int NN = WN / 8;
    constexpr int APT = TBM * 16 / 256;
    constexpr int BPT = TBN * 16 / 256;
    constexpr int ALD = TBM + 4;
    constexpr int BLD = TBN + 4;

    extern __shared__ float2 smem2[];
    float2* As = smem2;                     // [2][16][ALD]
    float2* Bs = smem2 + 2 * 16 * ALD;      // [2][16][BLD]

    const int tid = threadIdx.x;
    const int wid = tid >> 5;
    const int lane = tid & 31;
    const int lr = lane >> 2;
    const int lc = lane & 3;
    const int warp_m = wid >> 2;
    const int warp_n = wid & 3;
    const int m0 = blockIdx.y * TBM;
    const int n0 = blockIdx.x * TBN;

    float acc[MM][NN][4];
#pragma unroll
    for (int i = 0; i < MM; i++)
#pragma unroll
        for (int j = 0; j < NN; j++)
#pragma unroll
            for (int q = 0; q < 4; q++) acc[i][j][q] = 0.f;

    const int nchunks = (K + 15) / 16;
    const float2 z2 = make_float2(0.f, 0.f);
    float2 ra[APT], rb[BPT];

    // ---- prologue: load chunk 0 ----
    {
#pragma unroll
        for (int i = 0; i < APT; i++) {
            int e = tid + i * 256;
            int m = e >> 4, k = e & 15;
            int gm = m0 + m;
            ra[i] = (gm < M && k < K) ? A[gm * lda + k] : z2;
        }
#pragma unroll
        for (int i = 0; i < BPT; i++) {
            int e = tid + i * 256;
            int n = e >> 4, k = e & 15;
            int gn = n0 + n;
            rb[i] = (gn < N && k < K) ? B[gn * ldb + k] : z2;
        }
#pragma unroll
        for (int i = 0; i < APT; i++) {
            int e = tid + i * 256;
            As[(e & 15) * ALD + (e >> 4)] = ra[i];
        }
#pragma unroll
        for (int i = 0; i < BPT; i++) {
            int e = tid + i * 256;
            Bs[(e & 15) * BLD + (e >> 4)] = rb[i];
        }
        __syncthreads();
    }

    for (int ch = 0; ch < nchunks; ch++) {
        const int cur = ch & 1;
        const bool have_next = (ch + 1 < nchunks);

        if (have_next) {
            const int kk = (ch + 1) * 16;
#pragma unroll
            for (int i = 0; i < APT; i++) {
                int e = tid + i * 256;
                int m = e >> 4, k = e & 15;
                int gm = m0 + m, gk = kk + k;
                ra[i] = (gm < M && gk < K) ? A[gm * lda + gk] : z2;
            }
#pragma unroll
            for (int i = 0; i < BPT; i++) {
                int e = tid + i * 256;
                int n = e >> 4, k = e & 15;
                int gn = n0 + n, gk = kk + k;
                rb[i] = (gn < N && gk < K) ? B[gn * ldb + gk] : z2;
            }
        }

        // ---- compute: term-major MMA ordering (no acc RAW chains) ----
#pragma unroll
        for (int kb = 0; kb < 16; kb += 8) {
            uint32_t ahi[MM][4], alo[MM][4];
            uint32_t bhi[NN][2], blo[NN][2];
#pragma unroll
            for (int mm = 0; mm < MM; mm++) {
                int mrow = warp_m * WM + mm * 16 + lr;
                float2 x0 = As[(cur * 16 + kb + lc) * ALD + mrow];
                float2 x1 = As[(cur * 16 + kb + lc) * ALD + mrow + 8];
                float2 x2 = As[(cur * 16 + kb + 4 + lc) * ALD + mrow];
                float2 x3 = As[(cur * 16 + kb + 4 + lc) * ALD + mrow + 8];
                ahi[mm][0] = __float_as_uint(x0.x); alo[mm][0] = __float_as_uint(x0.y);
                ahi[mm][1] = __float_as_uint(x1.x); alo[mm][1] = __float_as_uint(x1.y);
                ahi[mm][2] = __float_as_uint(x2.x); alo[mm][2] = __float_as_uint(x2.y);
                ahi[mm][3] = __float_as_uint(x3.x); alo[mm][3] = __float_as_uint(x3.y);
            }
#pragma unroll
            for (int nn = 0; nn < NN; nn++) {
                int ncol = warp_n * WN + nn * 8 + lr;
                float2 y0 = Bs[(cur * 16 + kb + lc) * BLD + ncol];
                float2 y1 = Bs[(cur * 16 + kb + 4 + lc) * BLD + ncol];
                bhi[nn][0] = __float_as_uint(y0.x); blo[nn][0] = __float_as_uint(y0.y);
                bhi[nn][1] = __float_as_uint(y1.x); blo[nn][1] = __float_as_uint(y1.y);
            }
            // pass 1: lo*hi
#pragma unroll
            for (int mm = 0; mm < MM; mm++)
#pragma unroll
                for (int nn = 0; nn < NN; nn++)
                    MMA_TF32(acc[mm][nn], alo[mm], bhi[nn]);
            // pass 2: hi*lo
#pragma unroll
            for (int mm = 0; mm < MM; mm++)
#pragma unroll
                for (int nn = 0; nn < NN; nn++)
                    MMA_TF32(acc[mm][nn], ahi[mm], blo[nn]);
            // pass 3: hi*hi
#pragma unroll
            for (int mm = 0; mm < MM; mm++)
#pragma unroll
                for (int nn = 0; nn < NN; nn++)
                    MMA_TF32(acc[mm][nn], ahi[mm], bhi[nn]);
        }

        if (have_next) {
            const int nxt = cur ^ 1;
#pragma unroll
            for (int i = 0; i < APT; i++) {
                int e = tid + i * 256;
                As[(nxt * 16 + (e & 15)) * ALD + (e >> 4)] = ra[i];
            }
#pragma unroll
            for (int i = 0; i < BPT; i++) {
                int e = tid + i * 256;
                Bs[(nxt * 16 + (e & 15)) * BLD + (e >> 4)] = rb[i];
            }
        }
        __syncthreads();
    }

    // ---- epilogue ----
#pragma unroll
    for (int mm = 0; mm < MM; mm++) {
        int r0 = m0 + warp_m * WM + mm * 16 + lr;
#pragma unroll
        for (int nn = 0; nn < NN; nn++) {
            int c0 = n0 + warp_n * WN + nn * 8 + lc * 2;
#pragma unroll
            for (int q = 0; q < 4; q++) {
                int row = r0 + (q >> 1) * 8;
                int col = c0 + (q & 1);
                if (row >= M || col >= N) continue;
                float v = alpha * acc[mm][nn][q];
                if (beta != 0.f) v += beta * Cin[row * ldcin + col];
                if (act == 3) {
                    float cc = bias[col];
                    float sv = fmaxf(cc - v, 0.f);
                    float rv = fmaxf(v - cc, 0.f);
                    C[row * ldc + col] = sv;
                    C2[row * ldc + col] = rv;
                    if (Csp2) Csp2[row * ldc + col] = split2(rv);
                } else {
                    if (bias) v += bias[col];
                    if (act == 1) v = fmaxf(v, 0.f);
                    else if (act == 2) v = tanhf(v);
                    C[row * ldc + col] = v;
                    if (Csp) Csp[row * ldc + col] = split2(v);
                }
            }
        }
    }
}

// ---------------- fp32 SIMT GEMM (KKT pipeline only) --------
#define BM 64
#define BN 64
#define BKK 16

__global__ void gemm_k(const float* __restrict__ A, const float* __restrict__ B,
                       float* __restrict__ C, const float* __restrict__ Cin,
                       int M, int N, int K, int lda, int ldb, int ldc, int ldcin,
                       int transB, float alpha, float beta)
{
    __shared__ float As[BKK][BM];
    __shared__ float Bs[BKK][BN];
    const int tid = threadIdx.x;
    const int tx = tid & 15, ty = tid >> 4;
    const int m0 = blockIdx.y * BM, n0 = blockIdx.x * BN;
    float acc[4][4] = {};

    for (int kk = 0; kk < K; kk += BKK) {
#pragma unroll
        for (int i = 0; i < 4; i++) {
            int e = tid + i * 256;
            int m = e >> 4, k = e & 15;
            int gm = m0 + m, gk = kk + k;
            As[k][m] = (gm < M && gk < K) ? A[gm * lda + gk] : 0.f;
        }
        if (transB) {
#pragma unroll
            for (int i = 0; i < 4; i++) {
                int e = tid + i * 256;
                int n = e >> 4, k = e & 15;
                int gn = n0 + n, gk = kk + k;
                Bs[k][n] = (gn < N && gk < K) ? B[gn * ldb + gk] : 0.f;
            }
        } else {
#pragma unroll
            for (int i = 0; i < 4; i++) {
                int e = tid + i * 256;
                int k = e >> 6, n = e & 63;
                int gn = n0 + n, gk = kk + k;
                Bs[k][n] = (gn < N && gk < K) ? B[gk * ldb + gn] : 0.f;
            }
        }
        __syncthreads();
#pragma unroll
        for (int k = 0; k < BKK; k++) {
            float a0 = As[k][ty*4+0], a1 = As[k][ty*4+1], a2 = As[k][ty*4+2], a3 = As[k][ty*4+3];
            float b0 = Bs[k][tx*4+0], b1 = Bs[k][tx*4+1], b2 = Bs[k][tx*4+2], b3 = Bs[k][tx*4+3];
            acc[0][0] += a0*b0; acc[0][1] += a0*b1; acc[0][2] += a0*b2; acc[0][3] += a0*b3;
            acc[1][0] += a1*b0; acc[1][1] += a1*b1; acc[1][2] += a1*b2; acc[1][3] += a1*b3;
            acc[2][0] += a2*b0; acc[2][1] += a2*b1; acc[2][2] += a2*b2; acc[2][3] += a2*b3;
            acc[3][0] += a3*b0; acc[3][1] += a3*b1; acc[3][2] += a3*b2; acc[3][3] += a3*b3;
        }
        __syncthreads();
    }

#pragma unroll
    for (int i = 0; i < 4; i++) {
        int row = m0 + ty*4 + i;
        if (row >= M) continue;
#pragma unroll
        for (int j = 0; j < 4; j++) {
            int col = n0 + tx*4 + j;
            if (col >= N) continue;
            float v = alpha * acc[i][j];
            if (beta != 0.f) v += beta * Cin[row * ldcin + col];
            C[row * ldc + col] = v;
        }
    }
}

// ---------------- split / setup kernels ----------------
__global__ void split_k(const float* __restrict__ x, float2* __restrict__ y, int n) {
    int i = blockIdx.x * blockDim.x + threadIdx.x;
    if (i < n) y[i] = split2(x[i]);
}

__global__ void combine_Wih_k(const float* __restrict__ W) {
    int idx = blockIdx.x * blockDim.x + threadIdx.x;
    if (idx >= 3 * HIDD * GIND4) return;
    int i = idx / GIND4, j = idx % GIND4;
    const float* row = W + i * 4800;
    float v;
    if (j < 1000)       v = row[j] - row[3200 + j];
    else if (j < 1600)  v = row[j] - row[4200 + (j - 1000)];
    else if (j < 2600)  v = row[j] + row[3200 + (j - 1600)];
    else                v = row[j] + row[4200 + (j - 2600)];
    sWih4[idx] = split2(v);
}

__global__ void build_Bxi_k(const float* __restrict__ CM) {
    int idx = blockIdx.x * blockDim.x + threadIdx.x;
    if (idx >= NVARD * XBL) return;
    int n = idx / XBL, k = idx % XBL;
    float v = (k < 1000) ? CM[k * NVARD + n] : g_G[(k - 1000) * GLD + 750 + n];
    sBxi[idx] = split2(v);
}

__global__ void bias_xi_k(const float* __restrict__ gv) {
    int n = blockIdx.x * blockDim.x + threadIdx.x;
    if (n >= NVARD) return;
    float acc = 0.f;
    for (int k = 0; k < NVARD; k++) acc += gv[k] * g_G[k * GLD + 750 + n];
    g_bxi[n] = g_v0[n] - acc;
}

// ---------------- statistics / normalization ----------------
__global__ void stats_zero_k() { g_sum2[0] = 0.0; g_sum2[1] = 0.0; }

__global__ void stats_k(const float* __restrict__ x, int n) {
    float s = 0.f, ss = 0.f;
    for (int i = blockIdx.x * blockDim.x + threadIdx.x; i < n; i += gridDim.x * blockDim.x) {
        float v = x[i]; s += v; ss += v * v;
    }
    __shared__ float s1[256], s2[256];
    s1[threadIdx.x] = s; s2[threadIdx.x] = ss;
    __syncthreads();
    for (int o = 128; o > 0; o >>= 1) {
        if (threadIdx.x < o) { s1[threadIdx.x] += s1[threadIdx.x+o]; s2[threadIdx.x] += s2[threadIdx.x+o]; }
        __syncthreads();
    }
    if (threadIdx.x == 0) {
        atomicAdd(&g_sum2[0], (double)s1[0]);
        atomicAdd(&g_sum2[1], (double)s2[0]);
    }
}

__global__ void normalize_k(const float* __restrict__ x, int n) {
    double sum = g_sum2[0], sumsq = g_sum2[1];
    double mean = sum / n;
    double var = (sumsq - sum * sum / n) / (double)(n - 1);
    float istd = 1.0f / ((float)sqrt(var) + 1e-8f);
    float m = (float)mean;
    for (int i = blockIdx.x * blockDim.x + threadIdx.x; i < n; i += gridDim.x * blockDim.x) {
        float v = (x[i] - m) * istd;
        g_inp[i] = v;
        sinp[i] = split2(v);
    }
}

// ---------------- small setup kernels ----------------
__global__ void split_nnout2_k(const float* __restrict__ cvec) {
    int idx = blockIdx.x * blockDim.x + threadIdx.x;
    if (idx >= BATCHD * 1600) return;
    int b = idx / 1600, r = idx % 1600;
    if (r < NVARD) {
        float lam = g_nnout[b * MLPOUTD + NVARD + r];
        g_lam[b * NVARD + r] = lam;
        sbl[b * XBL + 1000 + r] = split2(lam);
    } else {
        int j = r - NVARD;
        float s = fmaxf(g_nnout[b * MLPOUTD + 2 * NVARD + j], 0.f);
        g_s[b * NCD + j] = s;
        sbl[b * XBL + j] = split2(cvec[j] - s);
    }
}

__global__ void transpose_C_k(const float* __restrict__ Cm) {
    int idx = blockIdx.x * blockDim.x + threadIdx.x;
    if (idx >= NVARD * NCD) return;
    int i = idx / NCD, k = idx % NCD;
    float v = Cm[k * NVARD + i];
    g_Ct[i * NCD + k] = v;
    sCt[i * NCD + k] = split2(v);
}

__global__ void init_G_k() {
    int idx = blockIdx.x * blockDim.x + threadIdx.x;
    if (idx >= KKTN * GLD) return;
    int r = idx / GLD, c = idx % GLD;
    float v = 0.f;
    if (c >= 750) {
        if (c - 750 == r) v = 1.f;
    } else if (r >= 600 && c < 600) {
        int rr = r - 600, t = rr / 3, i = rr % 3;
        if (c / 12 == t && (c % 12) % 3 == i) v = 1.f;
    } else if (r < 600 && c >= 600) {
        int cc = c - 600, t = cc / 3, i = cc % 3;
        if (r / 12 == t && (r % 12) % 3 == i) v = 1.f;
    }
    g_G[idx] = v;
}

__global__ void v0_k() {
    int j = blockIdx.x * blockDim.x + threadIdx.x;
    if (j >= NVARD) return;
    float beq = 30.0f * 9.81f;
    float acc = 0.f;
    for (int t = 0; t < 50; t++) acc += g_G[j * GLD + 750 + 600 + 3 * t + 2];
    g_v0[j] = beq * acc;
}

// ---------------- blocked Gauss-Jordan helpers ----------------
__global__ void copy_cols_k(int kb) {
    int idx = blockIdx.x * blockDim.x + threadIdx.x;
    if (idx >= KKTN * BLKD) return;
    int r = idx / BLKD, j = idx % BLKD;
    g_Ucol[r * BILD + j] = g_G[r * GLD + kb * BLKD + j];
}

__global__ void inv_block_k(int kb) {
    extern __shared__ float s[];
    const int n = BLKD, ld = BILD;
    int tid = threadIdx.x, nt = blockDim.x;
    for (int e = tid; e < n * n; e += nt)
        s[(e / n) * ld + (e % n)] = g_Ucol[(kb * BLKD + e / n) * BILD + (e % n)];
    __shared__ float fcol[BLKD];
    __shared__ float s_ipiv;
    __syncthreads();
    for (int p = 0; p < n; p++) {
        if (tid == 0) s_ipiv = 1.0f / s[p * ld + p];
        __syncthreads();
        float ipiv = s_ipiv;
        for (int j = tid; j < n; j += nt) if (j != p) s[p * ld + j] *= ipiv;
        for (int r = tid; r < n; r += nt) fcol[r] = (r == p) ? 0.f : s[r * ld + p];
        __syncthreads();
        for (int e = tid; e < n * n; e += nt) {
            int r = e / n, j = e % n;
            if (r != p && j != p) s[r * ld + j] -= fcol[r] * s[p * ld + j];
        }
        __syncthreads();
        for (int r = tid; r < n; r += nt) {
            if (r == p) s[p * ld + p] = ipiv;
            else s[r * ld + p] = -fcol[r] * ipiv;
        }
        __syncthreads();
    }
    for (int e = tid; e < n * n; e += nt)
        g_Einv[(e / n) * BILD + (e % n)] = s[(e / n) * ld + (e % n)];
}

__global__ void writeback_k(int kb) {
    int idx = blockIdx.x * blockDim.x + threadIdx.x;
    if (idx >= BLKD * GLD) return;
    int r = idx / GLD, j = idx % GLD;
    g_G[(kb * BLKD + r) * GLD + j] = g_P[idx];
    if (j < BILD) g_Ucol[(kb * BLKD + r) * BILD + j] = 0.f;
}

// ---------------- iteration elementwise kernels ----------------
__global__ void rownorm_k(const float* __restrict__ v, int ncols, float* __restrict__ out) {
    int b = blockIdx.x;
    float acc = 0.f;
    for (int j = threadIdx.x; j < ncols; j += blockDim.x) {
        float t = v[b * ncols + j]; acc += t * t;
    }
    __shared__ float sm[256];
    sm[threadIdx.x] = acc; __syncthreads();
    for (int o = 128; o > 0; o >>= 1) {
        if (threadIdx.x < o) sm[threadIdx.x] += sm[threadIdx.x + o];
        __syncthreads();
    }
    if (threadIdx.x == 0) out[b] = sqrtf(sm[0]);
}

__global__ void concat_r4_k() {
    int idx = blockIdx.x * blockDim.x + threadIdx.x;
    if (idx >= BATCHD * GIND4) return;
    int b = idx / GIND4, q = idx % GIND4;
    float v;
    if (q < 1000)       v = g_s[b * NCD + q];
    else if (q < 1600)  v = g_lam[b * NVARD + (q - 1000)];
    else if (q < 2600)  v = g_snew[b * NCD + (q - 1600)];
    else                v = g_lamnew[b * NVARD + (q - 2600)];
    sr4[idx] = split2(v);
}

__device__ __forceinline__ float sigmoidf(float x) { return 1.0f / (1.0f + expf(-x)); }

__global__ void gru_k() {
    int idx = blockIdx.x * blockDim.x + threadIdx.x;
    if (idx >= BATCHD * HIDD) return;
    int b = idx >> 10, j = idx & 1023;
    int base = b * 3 * HIDD + j;
    float ir = g_gi[base], iz = g_gi[base + HIDD], in_ = g_gi[base + 2 * HIDD];
    float hr = g_gh[base], hz = g_gh[base + HIDD], hn = g_gh[base + 2 * HIDD];
    float rg = sigmoidf(ir + hr);
    float z  = sigmoidf(iz + hz);
    float n  = tanhf(in_ + rg * hn);
    float h  = g_hst[idx];
    float hnew = (1.f - z) * n + z * h;
    g_hst[idx] = hnew;
    shst[idx] = split2(hnew);
}

// finalize: s/lam update + fp norm + write next-iteration [baug|lam] splits
__global__ void finalize2_k(int t, const float* __restrict__ cvec) {
    int b = blockIdx.x;
    float accs = 0.f, accl = 0.f;
    for (int j = threadIdx.x; j < GOUTD; j += blockDim.x) {
        float go = g_gout[b * GOUTD + j];
        if (j < NCD) {
            float sf = fmaxf(g_snew[b * NCD + j] + go, 0.f);
            float d = sf - g_s[b * NCD + j];
            accs += d * d;
            g_s[b * NCD + j] = sf;
            sbl[b * XBL + j] = split2(cvec[j] - sf);
        } else {
            int j2 = j - NCD;
            float lf = g_lamnew[b * NVARD + j2] + go;
            float d = lf - g_lam[b * NVARD + j2];
            accl += d * d;
            g_lam[b * NVARD + j2] = lf;
            sbl[b * XBL + 1000 + j2] = split2(lf);
        }
    }
    __shared__ float sm1[256], sm2[256];
    sm1[threadIdx.x] = accs; sm2[threadIdx.x] = accl;
    __syncthreads();
    for (int o = 128; o > 0; o >>= 1) {
        if (threadIdx.x < o) { sm1[threadIdx.x] += sm1[threadIdx.x+o]; sm2[threadIdx.x] += sm2[threadIdx.x+o]; }
        __syncthreads();
    }
    if (threadIdx.x == 0)
        g_fp[t * BATCHD + b] = sqrtf(sm2[0]) + sqrtf(sm1[0]);
}

// ---------------- output assembly ----------------
__global__ void output_k(float* __restrict__ out) {
    int idx = blockIdx.x * blockDim.x + threadIdx.x;
    if (idx >= OUT_TOTAL) return;
    const int XI_END = BATCHD * NVARD;
    const int AFP_END = XI_END + BATCHD;
    const int APR_END = AFP_END + BATCHD;
    const int PH_END = APR_END + MAXITERD * BATCHD;
    if (idx < XI_END) out[idx] = g_xi[idx];
    else if (idx < AFP_END) {
        int b = idx - XI_END;
        float a = 0.f;
        for (int t = 0; t < MAXITERD; t++) a += g_fp[t * BATCHD + b];
        out[idx] = a / (float)MAXITERD;
    } else if (idx < APR_END) {
        int b = idx - AFP_END;
        float a = 0.f;
        for (int t = 0; t < MAXITERD; t++) a += g_prim[t * BATCHD + b];
        out[idx] = a / (float)MAXITERD;
    } else if (idx < PH_END) out[idx] = g_prim[idx - APR_END];
    else out[idx] = g_fp[idx - PH_END];
}

// ---------------- host side ----------------
static inline int ceil_div(int a, int b) { return (a + b - 1) / b; }

static void gemm(const float* A, const float* B, float* C, const float* Cin,
                 int M, int N, int K, int lda, int ldb, int ldc, int ldcin,
                 int transB, float alpha, float beta)
{
    dim3 grid((N + BN - 1) / BN, (M + BM - 1) / BM);
    gemm_k<<<grid, 256>>>(A, B, C, Cin, M, N, K, lda, ldb, ldc, ldcin, transB, alpha, beta);
}

template<int TBM, int TBN>
static void gemm_tc(const float2* A, const float2* B, float* C, float* C2,
                    float2* Csp, float2* Csp2, const float* Cin, const float* bias,
                    int M, int N, int K, int lda, int ldb, int ldc, int ldcin,
                    float alpha, float beta, int act)
{
    size_t smem = (size_t)(2 * 16 * (TBM + 4) + 2 * 16 * (TBN + 4)) * sizeof(float2);
    dim3 grid((N + TBN - 1) / TBN, (M + TBM - 1) / TBM);
    gemm_ts_k<TBM, TBN><<<grid, 256, smem>>>(A, B, C, C2, Csp, Csp2, Cin, bias,
                                             M, N, K, lda, ldb, ldc, ldcin, alpha, beta, act);
}

extern "C" void kernel_launch(void* const* d_in, const int* in_sizes, int n_in,
                              void* d_out, int out_size) {
    const float* X    = (const float*)d_in[0];
    const float* Hm   = (const float*)d_in[1];
    const float* gv   = (const float*)d_in[2];
    const float* Cm   = (const float*)d_in[3];
    const float* cvec = (const float*)d_in[4];
    const float* W1   = (const float*)d_in[5];
    const float* b1   = (const float*)d_in[6];
    const float* W2   = (const float*)d_in[7];
    const float* b2   = (const float*)d_in[8];
    const float* W3   = (const float*)d_in[9];
    const float* b3   = (const float*)d_in[10];
    const float* Wg   = (const float*)d_in[11];
    const float* bg   = (const float*)d_in[12];
    const float* W_ih = (const float*)d_in[13];
    const float* W_hh = (const float*)d_in[14];
    const float* b_ih = (const float*)d_in[15];
    const float* b_hh = (const float*)d_in[16];
    const float* W_out= (const float*)d_in[17];
    const float* b_out= (const float*)d_in[18];
    float* out = (float*)d_out;

    float *nnout, *hst, *lam, *lamnew, *s, *snew, *res, *xi, *gi, *gh, *gout,
          *G, *P, *Ucol, *Einv, *prim, *fp, *bxi;
    float2 *pW1, *pW2, *pW3, *pWg, *pWih4, *pWhh, *pWout, *pC, *pCt, *pBxi,
           *pbl, *pinp, *ph1, *ph2, *phst, *pxi, *pres, *pr4;
    cudaGetSymbolAddress((void**)&nnout, g_nnout);
    cudaGetSymbolAddress((void**)&hst, g_hst);
    cudaGetSymbolAddress((void**)&lam, g_lam);
    cudaGetSymbolAddress((void**)&lamnew, g_lamnew);
    cudaGetSymbolAddress((void**)&s, g_s);
    cudaGetSymbolAddress((void**)&snew, g_snew);
    cudaGetSymbolAddress((void**)&res, g_res);
    cudaGetSymbolAddress((void**)&xi, g_xi);
    cudaGetSymbolAddress((void**)&gi, g_gi);
    cudaGetSymbolAddress((void**)&gh, g_gh);
    cudaGetSymbolAddress((void**)&gout, g_gout);
    cudaGetSymbolAddress((void**)&G, g_G);
    cudaGetSymbolAddress((void**)&P, g_P);
    cudaGetSymbolAddress((void**)&Ucol, g_Ucol);
    cudaGetSymbolAddress((void**)&Einv, g_Einv);
    cudaGetSymbolAddress((void**)&prim, g_prim);
    cudaGetSymbolAddress((void**)&fp, g_fp);
    cudaGetSymbolAddress((void**)&bxi, g_bxi);
    cudaGetSymbolAddress((void**)&pW1, sW1);
    cudaGetSymbolAddress((void**)&pW2, sW2);
    cudaGetSymbolAddress((void**)&pW3, sW3);
    cudaGetSymbolAddress((void**)&pWg, sWg);
    cudaGetSymbolAddress((void**)&pWih4, sWih4);
    cudaGetSymbolAddress((void**)&pWhh, sWhh);
    cudaGetSymbolAddress((void**)&pWout, sWout);
    cudaGetSymbolAddress((void**)&pC, sC);
    cudaGetSymbolAddress((void**)&pCt, sCt);
    cudaGetSymbolAddress((void**)&pBxi, sBxi);
    cudaGetSymbolAddress((void**)&pbl, sbl);
    cudaGetSymbolAddress((void**)&pinp, sinp);
    cudaGetSymbolAddress((void**)&ph1, sh1);
    cudaGetSymbolAddress((void**)&ph2, sh2);
    cudaGetSymbolAddress((void**)&phst, shst);
    cudaGetSymbolAddress((void**)&pxi, sxi);
    cudaGetSymbolAddress((void**)&pres, sres);
    cudaGetSymbolAddress((void**)&pr4, sr4);

    // fp32 GEMM outputs that are only consumed via splits reuse big scratch
    float* h1f = gi;
    float* h2f = gh;
    float* CMf = gi;   // CM computed after MLP is done with gi

    cudaFuncSetAttribute(inv_block_k, cudaFuncAttributeMaxDynamicSharedMemorySize,
                         BLKD * BILD * (int)sizeof(float));
    cudaFuncSetAttribute(gemm_ts_k<128, 128>, cudaFuncAttributeMaxDynamicSharedMemorySize,
                         (2 * 16 * 132 + 2 * 16 * 132) * (int)sizeof(float2));
    cudaFuncSetAttribute(gemm_ts_k<128, 64>, cudaFuncAttributeMaxDynamicSharedMemorySize,
                         (2 * 16 * 132 + 2 * 16 * 68) * (int)sizeof(float2));
    cudaFuncSetAttribute(gemm_ts_k<64, 64>, cudaFuncAttributeMaxDynamicSharedMemorySize,
                         (2 * 16 * 68 + 2 * 16 * 68) * (int)sizeof(float2));

    const int TPB = 256;
    const int NTOT = BATCHD * NVARD;

    // ---- weight splits / combines ----
    split_k<<<ceil_div(HIDD * NVARD, TPB), TPB>>>(W1, pW1, HIDD * NVARD);
    split_k<<<ceil_div(HIDD * HIDD, TPB), TPB>>>(W2, pW2, HIDD * HIDD);
    split_k<<<ceil_div(MLPOUTD * HIDD, TPB), TPB>>>(W3, pW3, MLPOUTD * HIDD);
    split_k<<<ceil_div(HIDD * NVARD, TPB), TPB>>>(Wg, pWg, HIDD * NVARD);
    combine_Wih_k<<<ceil_div(3 * HIDD * GIND4, TPB), TPB>>>(W_ih);
    split_k<<<ceil_div(3 * HIDD * HIDD, TPB), TPB>>>(W_hh, pWhh, 3 * HIDD * HIDD);
    split_k<<<ceil_div(GOUTD * HIDD, TPB), TPB>>>(W_out, pWout, GOUTD * HIDD);
    split_k<<<ceil_div(NCD * NVARD, TPB), TPB>>>(Cm, pC, NCD * NVARD);
    transpose_C_k<<<ceil_div(NVARD * NCD, TPB), TPB>>>(Cm);

    // ---- input normalization (+ split) ----
    stats_zero_k<<<1, 1>>>();
    stats_k<<<512, TPB>>>(X, NTOT);
    normalize_k<<<ceil_div(NTOT, TPB), TPB>>>(X, NTOT);

    // ---- MLP warm start ----
    gemm_tc<128, 64>(pinp, pW1, h1f, nullptr, ph1, nullptr, nullptr, b1,
                     BATCHD, HIDD, NVARD, NVARD, NVARD, HIDD, HIDD, 1.f, 0.f, 1);
    gemm_tc<128, 64>(ph1, pW2, h2f, nullptr, ph2, nullptr, nullptr, b2,
                     BATCHD, HIDD, HIDD, HIDD, HIDD, HIDD, HIDD, 1.f, 0.f, 1);
    gemm_tc<128, 128>(ph2, pW3, nnout, nullptr, nullptr, nullptr, nullptr, b3,
                      BATCHD, MLPOUTD, HIDD, HIDD, HIDD, MLPOUTD, MLPOUTD, 1.f, 0.f, 0);
    split_nnout2_k<<<ceil_div(BATCHD * 1600, TPB), TPB>>>(cvec);
    gemm_tc<128, 64>(pinp, pWg, hst, nullptr, phst, nullptr, nullptr, bg,
                     BATCHD, HIDD, NVARD, NVARD, NVARD, HIDD, HIDD, 1.f, 0.f, 2);

    // ---- KKT build + blocked Gauss-Jordan inverse (fp32 SIMT) ----
    init_G_k<<<ceil_div(KKTN * GLD, TPB), TPB>>>();
    float* Ct; cudaGetSymbolAddress((void**)&Ct, g_Ct);
    gemm(Ct, Ct, G, Hm, NVARD, NVARD, NCD, NCD, NCD, GLD, NVARD, 1, 1.f, 1.f);
    for (int kb = 0; kb < KKTN / BLKD; kb++) {
        copy_cols_k<<<ceil_div(KKTN * BLKD, TPB), TPB>>>(kb);
        inv_block_k<<<1, 1024, BLKD * BILD * sizeof(float)>>>(kb);
        gemm(Einv, G + kb * BLKD * GLD, P, nullptr,
             BLKD, GLD, BLKD, BILD, GLD, GLD, 0, 0, 1.f, 0.f);
        writeback_k<<<ceil_div(BLKD * GLD, TPB), TPB>>>(kb);
        gemm(Ucol, P, G, G, KKTN, GLD, BLKD, BILD, GLD, GLD, GLD, 0, -1.f, 1.f);
    }
    v0_k<<<ceil_div(NVARD, TPB), TPB>>>();
    bias_xi_k<<<ceil_div(NVARD, TPB), TPB>>>(gv);
    // CM = C @ M   (fp32), then build split [CM ; M] operand
    gemm(Cm, G + 750, CMf, nullptr, NCD, NVARD, NVARD, NVARD, GLD, NVARD, 0, 0, 1.f, 0.f);
    build_Bxi_k<<<ceil_div(NVARD * XBL, TPB), TPB>>>(CMf);

    // ---- 15 fixed-point iterations ----
    for (int t = 0; t < MAXITERD; t++) {
        // xi = [c-s | lam] @ [CM ; M]^T + (v0 - g@M)
        gemm_tc<64, 64>(pbl, pBxi, xi, nullptr, pxi, nullptr, nullptr, bxi,
                        BATCHD, NVARD, XBL, XBL, XBL, NVARD, NVARD, 1.f, 0.f, 0);
        // Cx = xi @ C^T ; s_new = relu(c - Cx), res = relu(Cx - c)
        gemm_tc<128, 64>(pxi, pC, snew, res, nullptr, pres, nullptr, cvec,
                         BATCHD, NCD, NVARD, NVARD, NVARD, NCD, NCD, 1.f, 0.f, 3);
        rownorm_k<<<BATCHD, 256>>>(res, NCD, prim + t * BATCHD);
        // lam_new = lam - res @ C
        gemm_tc<64, 64>(pres, pCt, lamnew, nullptr, nullptr, nullptr, lam, nullptr,
                        BATCHD, NVARD, NCD, NCD, NCD, NVARD, NVARD, -1.f, 1.f, 0);
        concat_r4_k<<<ceil_div(BATCHD * GIND4, TPB), TPB>>>();
        // GRU gates (combined W_ih, K=3200)
        gemm_tc<128, 128>(pr4, pWih4, gi, nullptr, nullptr, nullptr, nullptr, b_ih,
                          BATCHD, 3 * HIDD, GIND4, GIND4, GIND4, 3 * HIDD, 3 * HIDD, 1.f, 0.f, 0);
        gemm_tc<128, 128>(phst, pWhh, gh, nullptr, nullptr, nullptr, nullptr, b_hh,
                          BATCHD, 3 * HIDD, HIDD, HIDD, HIDD, 3 * HIDD, 3 * HIDD, 1.f, 0.f, 0);
        gru_k<<<ceil_div(BATCHD * HIDD, TPB), TPB>>>();
        // output head
        gemm_tc<128, 64>(phst, pWout, gout, nullptr, nullptr, nullptr, nullptr, b_out,
                         BATCHD, GOUTD, HIDD, HIDD, HIDD, GOUTD, GOUTD, 1.f, 0.f, 0);
        finalize2_k<<<BATCHD, 256>>>(t, cvec);
    }

    output_k<<<ceil_div(OUT_TOTAL, TPB), TPB>>>(out);
    (void)in_sizes; (void)n_in; (void)out_size;
}

// round 5
// speedup vs baseline: 2.2218x; 1.7381x over previous
#include <cuda_runtime.h>
#include <cuda_bf16.h>
#include <math.h>
#include <stdint.h>

// ---------------- problem constants ----------------
#define NVARD 600
#define NCD   1000
#define HIDD  1024
#define BATCHD 1024
#define MLPOUTD 2200
#define GIND4 3200
#define GOUTD 1600
#define MAXITERD 15
#define KKTN  750
#define GLD   1504
#define BLKD  150
#define BILD  152
#define XBL   1600
#define OUT_TOTAL (BATCHD*NVARD + BATCHD + BATCHD + MAXITERD*BATCHD + MAXITERD*BATCHD)

// ---------------- fp32 scratch ----------------
__device__ float g_inp[BATCHD*NVARD];
__device__ float g_nnout[BATCHD*MLPOUTD];
__device__ float g_hst[BATCHD*HIDD];
__device__ float g_lam[BATCHD*NVARD];
__device__ float g_lamnew[BATCHD*NVARD];
__device__ float g_s[BATCHD*NCD];
__device__ float g_snew[BATCHD*NCD];
__device__ float g_res[BATCHD*NCD];
__device__ float g_xi[BATCHD*NVARD];
__device__ float g_gi[BATCHD*3*HIDD];
__device__ float g_gh[BATCHD*3*HIDD];
__device__ float g_gout[BATCHD*GOUTD];
__device__ float g_G[KKTN*GLD];
__device__ float g_P[BLKD*GLD];
__device__ float g_Ucol[KKTN*BILD];
__device__ float g_Einv[BLKD*BILD];
__device__ float g_Ct[NVARD*NCD];
__device__ float g_v0[NVARD];
__device__ float g_bxi[NVARD];
__device__ float g_prim[MAXITERD*BATCHD];
__device__ float g_fp[MAXITERD*BATCHD];
__device__ double g_sum2[2];

// ---------------- packed bf16 (hi,lo) operand planes: uint2 per k-pair ----
// element layout: .x = bf16hi(x0) | bf16hi(x1)<<16 ; .y = bf16lo pair
__device__ uint2 sW1[HIDD*NVARD/2];
__device__ uint2 sW2[HIDD*HIDD/2];
__device__ uint2 sW3[MLPOUTD*HIDD/2];
__device__ uint2 sWg[HIDD*NVARD/2];
__device__ uint2 sWih4[3*HIDD*GIND4/2];
__device__ uint2 sWhh[3*HIDD*HIDD/2];
__device__ uint2 sWout[GOUTD*HIDD/2];
__device__ uint2 sC[NCD*NVARD/2];
__device__ uint2 sCt[NVARD*NCD/2];
__device__ uint2 sBxi[NVARD*XBL/2];
__device__ uint2 sbl[BATCHD*XBL/2];
__device__ uint2 sinp[BATCHD*NVARD/2];
__device__ uint2 sh1[BATCHD*HIDD/2];
__device__ uint2 sh2[BATCHD*HIDD/2];
__device__ uint2 shst[BATCHD*HIDD/2];
__device__ uint2 sxi[BATCHD*NVARD/2];
__device__ uint2 sres[BATCHD*NCD/2];
__device__ uint2 sr4[BATCHD*GIND4/2];

// ---------------- bf16 split helpers ----------------
__device__ __forceinline__ uint2 packsplit(float x0, float x1) {
    __nv_bfloat16 h0 = __float2bfloat16(x0);
    __nv_bfloat16 h1 = __float2bfloat16(x1);
    float r0 = x0 - __bfloat162float(h0);
    float r1 = x1 - __bfloat162float(h1);
    __nv_bfloat16 l0 = __float2bfloat16(r0);
    __nv_bfloat16 l1 = __float2bfloat16(r1);
    uint2 o;
    o.x = (uint32_t)__bfloat16_as_ushort(h0) | ((uint32_t)__bfloat16_as_ushort(h1) << 16);
    o.y = (uint32_t)__bfloat16_as_ushort(l0) | ((uint32_t)__bfloat16_as_ushort(l1) << 16);
    return o;
}

#define MMA_BF16(ac, a0, a1, a2, a3, b0, b1) \
    asm volatile("mma.sync.aligned.m16n8k16.row.col.f32.bf16.bf16.f32 " \
                 "{%0,%1,%2,%3},{%4,%5,%6,%7},{%8,%9},{%0,%1,%2,%3};" \
                 : "+f"(ac[0]), "+f"(ac[1]), "+f"(ac[2]), "+f"(ac[3]) \
                 : "r"(a0), "r"(a1), "r"(a2), "r"(a3), "r"(b0), "r"(b1))

// ===================================================================
// Tensor-core GEMM, 3xBF16 packed operands. B is [N, K] (row-major, i.e. B^T).
// K measured in k-pairs (Kp). C = act( alpha * A @ B^T + beta*Cin + bias )
// act: 0 none, 1 relu, 2 tanh, 3 dual: C=relu(bias-acc), C2=relu(acc-bias)
// Csp / Csp2: optional packed split of the (activated) outputs, ld = ldc/2.
// ===================================================================
#define KCH 16   // k-pairs per chunk (= 32 k)

template<int TBM, int TBN>
__global__ void __launch_bounds__(256)
gemm_bf_k(const uint2* __restrict__ A, const uint2* __restrict__ B,
          float* __restrict__ C, float* __restrict__ C2,
          uint2* __restrict__ Csp, uint2* __restrict__ Csp2,
          const float* __restrict__ Cin, const float* __restrict__ bias,
          int M, int N, int Kp, int ldap, int ldbp, int ldc, int ldcin,
          float alpha, float beta, int act)
{
    constexpr int WM = TBM / 2;
    constexpr int WN = TBN / 4;
    constexpr int MM = WM / 16;
    constexpr int NN = WN / 8;
    constexpr int APT = TBM * KCH / 256;
    constexpr int BPT = TBN * KCH / 256;
    constexpr int ALD = TBM + 4;
    constexpr int BLD = TBN + 4;

    extern __shared__ uint2 smu[];
    uint2* As = smu;                      // [2][KCH][ALD]
    uint2* Bs = smu + 2 * KCH * ALD;      // [2][KCH][BLD]

    const int tid = threadIdx.x;
    const int wid = tid >> 5;
    const int lane = tid & 31;
    const int lr = lane >> 2;
    const int lc = lane & 3;
    const int warp_m = wid >> 2;
    const int warp_n = wid & 3;
    const int m0 = blockIdx.y * TBM;
    const int n0 = blockIdx.x * TBN;

    float acc[MM][NN][4];
#pragma unroll
    for (int i = 0; i < MM; i++)
#pragma unroll
        for (int j = 0; j < NN; j++)
#pragma unroll
            for (int q = 0; q < 4; q++) acc[i][j][q] = 0.f;

    const int nchunks = (Kp + KCH - 1) / KCH;
    const uint2 z2 = make_uint2(0u, 0u);
    uint2 ra[APT], rb[BPT];

    // ---- prologue: load chunk 0 ----
    {
#pragma unroll
        for (int i = 0; i < APT; i++) {
            int e = tid + i * 256;
            int row = e >> 4, kp = e & 15;
            int gm = m0 + row;
            ra[i] = (gm < M && kp < Kp) ? A[gm * ldap + kp] : z2;
        }
#pragma unroll
        for (int i = 0; i < BPT; i++) {
            int e = tid + i * 256;
            int row = e >> 4, kp = e & 15;
            int gn = n0 + row;
            rb[i] = (gn < N && kp < Kp) ? B[gn * ldbp + kp] : z2;
        }
#pragma unroll
        for (int i = 0; i < APT; i++) {
            int e = tid + i * 256;
            As[(e & 15) * ALD + (e >> 4)] = ra[i];
        }
#pragma unroll
        for (int i = 0; i < BPT; i++) {
            int e = tid + i * 256;
            Bs[(e & 15) * BLD + (e >> 4)] = rb[i];
        }
        __syncthreads();
    }

    for (int ch = 0; ch < nchunks; ch++) {
        const int cur = ch & 1;
        const bool have_next = (ch + 1 < nchunks);

        if (have_next) {
            const int kk = (ch + 1) * KCH;
#pragma unroll
            for (int i = 0; i < APT; i++) {
                int e = tid + i * 256;
                int row = e >> 4, kp = e & 15;
                int gm = m0 + row, gk = kk + kp;
                ra[i] = (gm < M && gk < Kp) ? A[gm * ldap + gk] : z2;
            }
#pragma unroll
            for (int i = 0; i < BPT; i++) {
                int e = tid + i * 256;
                int row = e >> 4, kp = e & 15;
                int gn = n0 + row, gk = kk + kp;
                rb[i] = (gn < N && gk < Kp) ? B[gn * ldbp + gk] : z2;
            }
        }

        // ---- compute: 2 sub-chunks of 8 kpairs (one m16n8k16 set each) ----
#pragma unroll
        for (int kb = 0; kb < 2; kb++) {
            uint2 af[MM][4];
            uint2 bf[NN][2];
            const int kof = (cur * KCH + kb * 8);
#pragma unroll
            for (int mm = 0; mm < MM; mm++) {
                int mrow = warp_m * WM + mm * 16 + lr;
                af[mm][0] = As[(kof + lc) * ALD + mrow];
                af[mm][1] = As[(kof + lc) * ALD + mrow + 8];
                af[mm][2] = As[(kof + 4 + lc) * ALD + mrow];
                af[mm][3] = As[(kof + 4 + lc) * ALD + mrow + 8];
            }
#pragma unroll
            for (int nn = 0; nn < NN; nn++) {
                int ncol = warp_n * WN + nn * 8 + lr;
                bf[nn][0] = Bs[(kof + lc) * BLD + ncol];
                bf[nn][1] = Bs[(kof + 4 + lc) * BLD + ncol];
            }
            // pass 1: a_lo * b_hi
#pragma unroll
            for (int mm = 0; mm < MM; mm++)
#pragma unroll
                for (int nn = 0; nn < NN; nn++)
                    MMA_BF16(acc[mm][nn], af[mm][0].y, af[mm][1].y, af[mm][2].y, af[mm][3].y,
                             bf[nn][0].x, bf[nn][1].x);
            // pass 2: a_hi * b_lo
#pragma unroll
            for (int mm = 0; mm < MM; mm++)
#pragma unroll
                for (int nn = 0; nn < NN; nn++)
                    MMA_BF16(acc[mm][nn], af[mm][0].x, af[mm][1].x, af[mm][2].x, af[mm][3].x,
                             bf[nn][0].y, bf[nn][1].y);
            // pass 3: a_hi * b_hi
#pragma unroll
            for (int mm = 0; mm < MM; mm++)
#pragma unroll
                for (int nn = 0; nn < NN; nn++)
                    MMA_BF16(acc[mm][nn], af[mm][0].x, af[mm][1].x, af[mm][2].x, af[mm][3].x,
                             bf[nn][0].x, bf[nn][1].x);
        }

        if (have_next) {
            const int nxt = cur ^ 1;
#pragma unroll
            for (int i = 0; i < APT; i++) {
                int e = tid + i * 256;
                As[(nxt * KCH + (e & 15)) * ALD + (e >> 4)] = ra[i];
            }
#pragma unroll
            for (int i = 0; i < BPT; i++) {
                int e = tid + i * 256;
                Bs[(nxt * KCH + (e & 15)) * BLD + (e >> 4)] = rb[i];
            }
        }
        __syncthreads();
    }

    // ---- epilogue ----
    const int ldcp = ldc >> 1;
#pragma unroll
    for (int mm = 0; mm < MM; mm++) {
        int r0 = m0 + warp_m * WM + mm * 16 + lr;
#pragma unroll
        for (int nn = 0; nn < NN; nn++) {
            int c0 = n0 + warp_n * WN + nn * 8 + lc * 2;
            if (c0 >= N) continue;
            float v[4];
#pragma unroll
            for (int q = 0; q < 4; q++) {
                int row = r0 + (q >> 1) * 8;
                int col = c0 + (q & 1);
                float x = alpha * acc[mm][nn][q];
                if (beta != 0.f) x += beta * Cin[row * ldcin + col];
                v[q] = x;
            }
            if (act == 3) {
                float cc0 = bias[c0], cc1 = bias[c0 + 1];
                float s0 = fmaxf(cc0 - v[0], 0.f), s1 = fmaxf(cc1 - v[1], 0.f);
                float s2 = fmaxf(cc0 - v[2], 0.f), s3 = fmaxf(cc1 - v[3], 0.f);
                float r0v = fmaxf(v[0] - cc0, 0.f), r1v = fmaxf(v[1] - cc1, 0.f);
                float r2v = fmaxf(v[2] - cc0, 0.f), r3v = fmaxf(v[3] - cc1, 0.f);
                C[r0 * ldc + c0] = s0;       C[r0 * ldc + c0 + 1] = s1;
                C[(r0 + 8) * ldc + c0] = s2; C[(r0 + 8) * ldc + c0 + 1] = s3;
                C2[r0 * ldc + c0] = r0v;       C2[r0 * ldc + c0 + 1] = r1v;
                C2[(r0 + 8) * ldc + c0] = r2v; C2[(r0 + 8) * ldc + c0 + 1] = r3v;
                if (Csp2) {
                    Csp2[r0 * ldcp + (c0 >> 1)] = packsplit(r0v, r1v);
                    Csp2[(r0 + 8) * ldcp + (c0 >> 1)] = packsplit(r2v, r3v);
                }
            } else {
                if (bias) { v[0] += bias[c0]; v[1] += bias[c0 + 1]; v[2] += bias[c0]; v[3] += bias[c0 + 1]; }
                if (act == 1) {
#pragma unroll
                    for (int q = 0; q < 4; q++) v[q] = fmaxf(v[q], 0.f);
                } else if (act == 2) {
#pragma unroll
                    for (int q = 0; q < 4; q++) v[q] = tanhf(v[q]);
                }
                C[r0 * ldc + c0] = v[0];       C[r0 * ldc + c0 + 1] = v[1];
                C[(r0 + 8) * ldc + c0] = v[2]; C[(r0 + 8) * ldc + c0 + 1] = v[3];
                if (Csp) {
                    Csp[r0 * ldcp + (c0 >> 1)] = packsplit(v[0], v[1]);
                    Csp[(r0 + 8) * ldcp + (c0 >> 1)] = packsplit(v[2], v[3]);
                }
            }
        }
    }
}

// ---------------- fp32 SIMT GEMM (KKT pipeline only) --------
#define BM 64
#define BN 64
#define BKK 16

__global__ void gemm_k(const float* __restrict__ A, const float* __restrict__ B,
                       float* __restrict__ C, const float* __restrict__ Cin,
                       int M, int N, int K, int lda, int ldb, int ldc, int ldcin,
                       int transB, float alpha, float beta)
{
    __shared__ float As[BKK][BM];
    __shared__ float Bs[BKK][BN];
    const int tid = threadIdx.x;
    const int tx = tid & 15, ty = tid >> 4;
    const int m0 = blockIdx.y * BM, n0 = blockIdx.x * BN;
    float acc[4][4] = {};

    for (int kk = 0; kk < K; kk += BKK) {
#pragma unroll
        for (int i = 0; i < 4; i++) {
            int e = tid + i * 256;
            int m = e >> 4, k = e & 15;
            int gm = m0 + m, gk = kk + k;
            As[k][m] = (gm < M && gk < K) ? A[gm * lda + gk] : 0.f;
        }
        if (transB) {
#pragma unroll
            for (int i = 0; i < 4; i++) {
                int e = tid + i * 256;
                int n = e >> 4, k = e & 15;
                int gn = n0 + n, gk = kk + k;
                Bs[k][n] = (gn < N && gk < K) ? B[gn * ldb + gk] : 0.f;
            }
        } else {
#pragma unroll
            for (int i = 0; i < 4; i++) {
                int e = tid + i * 256;
                int k = e >> 6, n = e & 63;
                int gn = n0 + n, gk = kk + k;
                Bs[k][n] = (gn < N && gk < K) ? B[gk * ldb + gn] : 0.f;
            }
        }
        __syncthreads();
#pragma unroll
        for (int k = 0; k < BKK; k++) {
            float a0 = As[k][ty*4+0], a1 = As[k][ty*4+1], a2 = As[k][ty*4+2], a3 = As[k][ty*4+3];
            float b0 = Bs[k][tx*4+0], b1 = Bs[k][tx*4+1], b2 = Bs[k][tx*4+2], b3 = Bs[k][tx*4+3];
            acc[0][0] += a0*b0; acc[0][1] += a0*b1; acc[0][2] += a0*b2; acc[0][3] += a0*b3;
            acc[1][0] += a1*b0; acc[1][1] += a1*b1; acc[1][2] += a1*b2; acc[1][3] += a1*b3;
            acc[2][0] += a2*b0; acc[2][1] += a2*b1; acc[2][2] += a2*b2; acc[2][3] += a2*b3;
            acc[3][0] += a3*b0; acc[3][1] += a3*b1; acc[3][2] += a3*b2; acc[3][3] += a3*b3;
        }
        __syncthreads();
    }

#pragma unroll
    for (int i = 0; i < 4; i++) {
        int row = m0 + ty*4 + i;
        if (row >= M) continue;
#pragma unroll
        for (int j = 0; j < 4; j++) {
            int col = n0 + tx*4 + j;
            if (col >= N) continue;
            float v = alpha * acc[i][j];
            if (beta != 0.f) v += beta * Cin[row * ldcin + col];
            C[row * ldc + col] = v;
        }
    }
}

// ---------------- split / setup kernels ----------------
__global__ void splitpair_k(const float* __restrict__ x, uint2* __restrict__ y, int npairs) {
    int i = blockIdx.x * blockDim.x + threadIdx.x;
    if (i < npairs) y[i] = packsplit(x[2*i], x[2*i+1]);
}

__global__ void combine_Wih_k(const float* __restrict__ W) {
    int idx = blockIdx.x * blockDim.x + threadIdx.x;
    if (idx >= 3 * HIDD * GIND4 / 2) return;
    int i = idx / (GIND4/2), pp = idx % (GIND4/2);
    int j = 2 * pp;
    const float* row = W + i * 4800;
    float v0, v1;
    if (j < 1000)       { v0 = row[j] - row[3200 + j];           v1 = row[j+1] - row[3200 + j + 1]; }
    else if (j < 1600)  { v0 = row[j] - row[4200 + (j - 1000)];  v1 = row[j+1] - row[4200 + (j - 999)]; }
    else if (j < 2600)  { v0 = row[j] + row[3200 + (j - 1600)];  v1 = row[j+1] + row[3200 + (j - 1599)]; }
    else                { v0 = row[j] + row[4200 + (j - 2600)];  v1 = row[j+1] + row[4200 + (j - 2599)]; }
    sWih4[idx] = packsplit(v0, v1);
}

__global__ void build_Bxi_k(const float* __restrict__ CM) {
    int idx = blockIdx.x * blockDim.x + threadIdx.x;
    if (idx >= NVARD * XBL / 2) return;
    int n = idx / (XBL/2), kp = idx % (XBL/2);
    int k0 = 2 * kp;
    float v0, v1;
    if (k0 < 1000) { v0 = CM[k0 * NVARD + n]; v1 = CM[(k0+1) * NVARD + n]; }
    else { v0 = g_G[(k0 - 1000) * GLD + 750 + n]; v1 = g_G[(k0 - 999) * GLD + 750 + n]; }
    sBxi[idx] = packsplit(v0, v1);
}

__global__ void bias_xi_k(const float* __restrict__ gv) {
    int n = blockIdx.x * blockDim.x + threadIdx.x;
    if (n >= NVARD) return;
    float acc = 0.f;
    for (int k = 0; k < NVARD; k++) acc += gv[k] * g_G[k * GLD + 750 + n];
    g_bxi[n] = g_v0[n] - acc;
}

// ---------------- statistics / normalization ----------------
__global__ void stats_zero_k() { g_sum2[0] = 0.0; g_sum2[1] = 0.0; }

__global__ void stats_k(const float* __restrict__ x, int n) {
    float s = 0.f, ss = 0.f;
    for (int i = blockIdx.x * blockDim.x + threadIdx.x; i < n; i += gridDim.x * blockDim.x) {
        float v = x[i]; s += v; ss += v * v;
    }
    __shared__ float s1[256], s2[256];
    s1[threadIdx.x] = s; s2[threadIdx.x] = ss;
    __syncthreads();
    for (int o = 128; o > 0; o >>= 1) {
        if (threadIdx.x < o) { s1[threadIdx.x] += s1[threadIdx.x+o]; s2[threadIdx.x] += s2[threadIdx.x+o]; }
        __syncthreads();
    }
    if (threadIdx.x == 0) {
        atomicAdd(&g_sum2[0], (double)s1[0]);
        atomicAdd(&g_sum2[1], (double)s2[0]);
    }
}

__global__ void normalize_k(const float* __restrict__ x, int npairs) {
    double sum = g_sum2[0], sumsq = g_sum2[1];
    const double nn = (double)(2 * npairs);
    double mean = sum / nn;
    double var = (sumsq - sum * sum / nn) / (nn - 1.0);
    float istd = 1.0f / ((float)sqrt(var) + 1e-8f);
    float m = (float)mean;
    for (int i = blockIdx.x * blockDim.x + threadIdx.x; i < npairs; i += gridDim.x * blockDim.x) {
        float v0 = (x[2*i] - m) * istd;
        float v1 = (x[2*i+1] - m) * istd;
        g_inp[2*i] = v0; g_inp[2*i+1] = v1;
        sinp[i] = packsplit(v0, v1);
    }
}

// ---------------- small setup kernels ----------------
__global__ void split_nnout2_k(const float* __restrict__ cvec) {
    int idx = blockIdx.x * blockDim.x + threadIdx.x;
    if (idx >= BATCHD * 800) return;
    int b = idx / 800, pp = idx % 800;
    if (pp < 500) {
        int j = 2 * pp;
        float s0 = fmaxf(g_nnout[b * MLPOUTD + 1200 + j], 0.f);
        float s1 = fmaxf(g_nnout[b * MLPOUTD + 1200 + j + 1], 0.f);
        g_s[b * NCD + j] = s0; g_s[b * NCD + j + 1] = s1;
        sbl[b * 800 + pp] = packsplit(cvec[j] - s0, cvec[j+1] - s1);
    } else {
        int r = 2 * (pp - 500);
        float l0 = g_nnout[b * MLPOUTD + 600 + r];
        float l1 = g_nnout[b * MLPOUTD + 600 + r + 1];
        g_lam[b * NVARD + r] = l0; g_lam[b * NVARD + r + 1] = l1;
        sbl[b * 800 + pp] = packsplit(l0, l1);
    }
}

__global__ void transpose_C_k(const float* __restrict__ Cm) {
    int idx = blockIdx.x * blockDim.x + threadIdx.x;
    if (idx >= NVARD * NCD / 2) return;
    int i = idx / (NCD/2), kp = idx % (NCD/2);
    float v0 = Cm[(2*kp) * NVARD + i];
    float v1 = Cm[(2*kp+1) * NVARD + i];
    g_Ct[i * NCD + 2*kp] = v0;
    g_Ct[i * NCD + 2*kp+1] = v1;
    sCt[idx] = packsplit(v0, v1);
}

__global__ void init_G_k() {
    int idx = blockIdx.x * blockDim.x + threadIdx.x;
    if (idx >= KKTN * GLD) return;
    int r = idx / GLD, c = idx % GLD;
    float v = 0.f;
    if (c >= 750) {
        if (c - 750 == r) v = 1.f;
    } else if (r >= 600 && c < 600) {
        int rr = r - 600, t = rr / 3, i = rr % 3;
        if (c / 12 == t && (c % 12) % 3 == i) v = 1.f;
    } else if (r < 600 && c >= 600) {
        int cc = c - 600, t = cc / 3, i = cc % 3;
        if (r / 12 == t && (r % 12) % 3 == i) v = 1.f;
    }
    g_G[idx] = v;
}

__global__ void v0_k() {
    int j = blockIdx.x * blockDim.x + threadIdx.x;
    if (j >= NVARD) return;
    float beq = 30.0f * 9.81f;
    float acc = 0.f;
    for (int t = 0; t < 50; t++) acc += g_G[j * GLD + 750 + 600 + 3 * t + 2];
    g_v0[j] = beq * acc;
}

// ---------------- blocked Gauss-Jordan helpers ----------------
__global__ void copy_cols_k(int kb) {
    int idx = blockIdx.x * blockDim.x + threadIdx.x;
    if (idx >= KKTN * BLKD) return;
    int r = idx / BLKD, j = idx % BLKD;
    g_Ucol[r * BILD + j] = g_G[r * GLD + kb * BLKD + j];
}

__global__ void inv_block_k(int kb) {
    extern __shared__ float s[];
    const int n = BLKD, ld = BILD;
    int tid = threadIdx.x, nt = blockDim.x;
    for (int e = tid; e < n * n; e += nt)
        s[(e / n) * ld + (e % n)] = g_Ucol[(kb * BLKD + e / n) * BILD + (e % n)];
    __shared__ float fcol[BLKD];
    __shared__ float s_ipiv;
    __syncthreads();
    for (int p = 0; p < n; p++) {
        if (tid == 0) s_ipiv = 1.0f / s[p * ld + p];
        __syncthreads();
        float ipiv = s_ipiv;
        for (int j = tid; j < n; j += nt) if (j != p) s[p * ld + j] *= ipiv;
        for (int r = tid; r < n; r += nt) fcol[r] = (r == p) ? 0.f : s[r * ld + p];
        __syncthreads();
        for (int e = tid; e < n * n; e += nt) {
            int r = e / n, j = e % n;
            if (r != p && j != p) s[r * ld + j] -= fcol[r] * s[p * ld + j];
        }
        __syncthreads();
        for (int r = tid; r < n; r += nt) {
            if (r == p) s[p * ld + p] = ipiv;
            else s[r * ld + p] = -fcol[r] * ipiv;
        }
        __syncthreads();
    }
    for (int e = tid; e < n * n; e += nt)
        g_Einv[(e / n) * BILD + (e % n)] = s[(e / n) * ld + (e % n)];
}

__global__ void writeback_k(int kb) {
    int idx = blockIdx.x * blockDim.x + threadIdx.x;
    if (idx >= BLKD * GLD) return;
    int r = idx / GLD, j = idx % GLD;
    g_G[(kb * BLKD + r) * GLD + j] = g_P[idx];
    if (j < BILD) g_Ucol[(kb * BLKD + r) * BILD + j] = 0.f;
}

// ---------------- iteration elementwise kernels ----------------
__global__ void rownorm_k(const float* __restrict__ v, int ncols, float* __restrict__ out) {
    int b = blockIdx.x;
    float acc = 0.f;
    for (int j = threadIdx.x; j < ncols; j += blockDim.x) {
        float t = v[b * ncols + j]; acc += t * t;
    }
    __shared__ float sm[256];
    sm[threadIdx.x] = acc; __syncthreads();
    for (int o = 128; o > 0; o >>= 1) {
        if (threadIdx.x < o) sm[threadIdx.x] += sm[threadIdx.x + o];
        __syncthreads();
    }
    if (threadIdx.x == 0) out[b] = sqrtf(sm[0]);
}

__global__ void concat_r4_k() {
    int idx = blockIdx.x * blockDim.x + threadIdx.x;
    if (idx >= BATCHD * GIND4 / 2) return;
    int b = idx / (GIND4/2), pp = idx % (GIND4/2);
    int q = 2 * pp;
    float v0, v1;
    if (q < 1000)       { v0 = g_s[b * NCD + q];              v1 = g_s[b * NCD + q + 1]; }
    else if (q < 1600)  { v0 = g_lam[b * NVARD + q - 1000];   v1 = g_lam[b * NVARD + q - 999]; }
    else if (q < 2600)  { v0 = g_snew[b * NCD + q - 1600];    v1 = g_snew[b * NCD + q - 1599]; }
    else                { v0 = g_lamnew[b * NVARD + q - 2600];v1 = g_lamnew[b * NVARD + q - 2599]; }
    sr4[idx] = packsplit(v0, v1);
}

__device__ __forceinline__ float sigmoidf(float x) { return 1.0f / (1.0f + expf(-x)); }

__global__ void gru_k() {
    int p = blockIdx.x * blockDim.x + threadIdx.x;
    if (p >= BATCHD * HIDD / 2) return;
    int b = p / 512, jp = p % 512;
    int j = 2 * jp;
    int base = b * 3 * HIDD + j;
    float h0, h1;
#pragma unroll
    for (int e = 0; e < 2; e++) {
        float ir = g_gi[base + e], iz = g_gi[base + HIDD + e], in_ = g_gi[base + 2 * HIDD + e];
        float hr = g_gh[base + e], hz = g_gh[base + HIDD + e], hn = g_gh[base + 2 * HIDD + e];
        float rg = sigmoidf(ir + hr);
        float z  = sigmoidf(iz + hz);
        float nv = tanhf(in_ + rg * hn);
        float h  = g_hst[b * HIDD + j + e];
        float hnew = (1.f - z) * nv + z * h;
        g_hst[b * HIDD + j + e] = hnew;
        if (e == 0) h0 = hnew; else h1 = hnew;
    }
    shst[b * 512 + jp] = packsplit(h0, h1);
}

// finalize: s/lam update + fp norm + next-iteration [baug|lam] packed splits
__global__ void finalize2_k(int t, const float* __restrict__ cvec) {
    int b = blockIdx.x;
    float accs = 0.f, accl = 0.f;
    for (int pj = threadIdx.x; pj < 800; pj += blockDim.x) {
        int j = 2 * pj;
        if (j < NCD) {
            float go0 = g_gout[b * GOUTD + j], go1 = g_gout[b * GOUTD + j + 1];
            float sf0 = fmaxf(g_snew[b * NCD + j] + go0, 0.f);
            float sf1 = fmaxf(g_snew[b * NCD + j + 1] + go1, 0.f);
            float d0 = sf0 - g_s[b * NCD + j], d1 = sf1 - g_s[b * NCD + j + 1];
            accs += d0 * d0 + d1 * d1;
            g_s[b * NCD + j] = sf0; g_s[b * NCD + j + 1] = sf1;
            sbl[b * 800 + pj] = packsplit(cvec[j] - sf0, cvec[j+1] - sf1);
        } else {
            int j2 = j - NCD;
            float go0 = g_gout[b * GOUTD + j], go1 = g_gout[b * GOUTD + j + 1];
            float lf0 = g_lamnew[b * NVARD + j2] + go0;
            float lf1 = g_lamnew[b * NVARD + j2 + 1] + go1;
            float d0 = lf0 - g_lam[b * NVARD + j2], d1 = lf1 - g_lam[b * NVARD + j2 + 1];
            accl += d0 * d0 + d1 * d1;
            g_lam[b * NVARD + j2] = lf0; g_lam[b * NVARD + j2 + 1] = lf1;
            sbl[b * 800 + pj] = packsplit(lf0, lf1);
        }
    }
    __shared__ float sm1[256], sm2[256];
    sm1[threadIdx.x] = accs; sm2[threadIdx.x] = accl;
    __syncthreads();
    for (int o = 128; o > 0; o >>= 1) {
        if (threadIdx.x < o) { sm1[threadIdx.x] += sm1[threadIdx.x+o]; sm2[threadIdx.x] += sm2[threadIdx.x+o]; }
        __syncthreads();
    }
    if (threadIdx.x == 0)
        g_fp[t * BATCHD + b] = sqrtf(sm2[0]) + sqrtf(sm1[0]);
}

// ---------------- output assembly ----------------
__global__ void output_k(float* __restrict__ out) {
    int idx = blockIdx.x * blockDim.x + threadIdx.x;
    if (idx >= OUT_TOTAL) return;
    const int XI_END = BATCHD * NVARD;
    const int AFP_END = XI_END + BATCHD;
    const int APR_END = AFP_END + BATCHD;
    const int PH_END = APR_END + MAXITERD * BATCHD;
    if (idx < XI_END) out[idx] = g_xi[idx];
    else if (idx < AFP_END) {
        int b = idx - XI_END;
        float a = 0.f;
        for (int t = 0; t < MAXITERD; t++) a += g_fp[t * BATCHD + b];
        out[idx] = a / (float)MAXITERD;
    } else if (idx < APR_END) {
        int b = idx - AFP_END;
        float a = 0.f;
        for (int t = 0; t < MAXITERD; t++) a += g_prim[t * BATCHD + b];
        out[idx] = a / (float)MAXITERD;
    } else if (idx < PH_END) out[idx] = g_prim[idx - APR_END];
    else out[idx] = g_fp[idx - PH_END];
}

// ---------------- host side ----------------
static inline int ceil_div(int a, int b) { return (a + b - 1) / b; }

static void gemm(const float* A, const float* B, float* C, const float* Cin,
                 int M, int N, int K, int lda, int ldb, int ldc, int ldcin,
                 int transB, float alpha, float beta)
{
    dim3 grid((N + BN - 1) / BN, (M + BM - 1) / BM);
    gemm_k<<<grid, 256>>>(A, B, C, Cin, M, N, K, lda, ldb, ldc, ldcin, transB, alpha, beta);
}

template<int TBM, int TBN>
static void gemm_bf(const uint2* A, const uint2* B, float* C, float* C2,
                    uint2* Csp, uint2* Csp2, const float* Cin, const float* bias,
                    int M, int N, int Kp, int ldap, int ldbp, int ldc, int ldcin,
                    float alpha, float beta, int act)
{
    size_t smem = (size_t)(2 * KCH * (TBM + 4) + 2 * KCH * (TBN + 4)) * sizeof(uint2);
    dim3 grid((N + TBN - 1) / TBN, (M + TBM - 1) / TBM);
    gemm_bf_k<TBM, TBN><<<grid, 256, smem>>>(A, B, C, C2, Csp, Csp2, Cin, bias,
                                             M, N, Kp, ldap, ldbp, ldc, ldcin, alpha, beta, act);
}

extern "C" void kernel_launch(void* const* d_in, const int* in_sizes, int n_in,
                              void* d_out, int out_size) {
    const float* X    = (const float*)d_in[0];
    const float* Hm   = (const float*)d_in[1];
    const float* gv   = (const float*)d_in[2];
    const float* Cm   = (const float*)d_in[3];
    const float* cvec = (const float*)d_in[4];
    const float* W1   = (const float*)d_in[5];
    const float* b1   = (const float*)d_in[6];
    const float* W2   = (const float*)d_in[7];
    const float* b2   = (const float*)d_in[8];
    const float* W3   = (const float*)d_in[9];
    const float* b3   = (const float*)d_in[10];
    const float* Wg   = (const float*)d_in[11];
    const float* bg   = (const float*)d_in[12];
    const float* W_ih = (const float*)d_in[13];
    const float* W_hh = (const float*)d_in[14];
    const float* b_ih = (const float*)d_in[15];
    const float* b_hh = (const float*)d_in[16];
    const float* W_out= (const float*)d_in[17];
    const float* b_out= (const float*)d_in[18];
    float* out = (float*)d_out;

    float *nnout, *hst, *lam, *lamnew, *s, *snew, *res, *xi, *gi, *gh, *gout,
          *G, *P, *Ucol, *Einv, *Ct, *prim, *fp, *bxi;
    uint2 *pW1, *pW2, *pW3, *pWg, *pWih4, *pWhh, *pWout, *pC, *pCt, *pBxi,
          *pbl, *pinp, *ph1, *ph2, *phst, *pxi, *pres, *pr4;
    cudaGetSymbolAddress((void**)&nnout, g_nnout);
    cudaGetSymbolAddress((void**)&hst, g_hst);
    cudaGetSymbolAddress((void**)&lam, g_lam);
    cudaGetSymbolAddress((void**)&lamnew, g_lamnew);
    cudaGetSymbolAddress((void**)&s, g_s);
    cudaGetSymbolAddress((void**)&snew, g_snew);
    cudaGetSymbolAddress((void**)&res, g_res);
    cudaGetSymbolAddress((void**)&xi, g_xi);
    cudaGetSymbolAddress((void**)&gi, g_gi);
    cudaGetSymbolAddress((void**)&gh, g_gh);
    cudaGetSymbolAddress((void**)&gout, g_gout);
    cudaGetSymbolAddress((void**)&G, g_G);
    cudaGetSymbolAddress((void**)&P, g_P);
    cudaGetSymbolAddress((void**)&Ucol, g_Ucol);
    cudaGetSymbolAddress((void**)&Einv, g_Einv);
    cudaGetSymbolAddress((void**)&Ct, g_Ct);
    cudaGetSymbolAddress((void**)&prim, g_prim);
    cudaGetSymbolAddress((void**)&fp, g_fp);
    cudaGetSymbolAddress((void**)&bxi, g_bxi);
    cudaGetSymbolAddress((void**)&pW1, sW1);
    cudaGetSymbolAddress((void**)&pW2, sW2);
    cudaGetSymbolAddress((void**)&pW3, sW3);
    cudaGetSymbolAddress((void**)&pWg, sWg);
    cudaGetSymbolAddress((void**)&pWih4, sWih4);
    cudaGetSymbolAddress((void**)&pWhh, sWhh);
    cudaGetSymbolAddress((void**)&pWout, sWout);
    cudaGetSymbolAddress((void**)&pC, sC);
    cudaGetSymbolAddress((void**)&pCt, sCt);
    cudaGetSymbolAddress((void**)&pBxi, sBxi);
    cudaGetSymbolAddress((void**)&pbl, sbl);
    cudaGetSymbolAddress((void**)&pinp, sinp);
    cudaGetSymbolAddress((void**)&ph1, sh1);
    cudaGetSymbolAddress((void**)&ph2, sh2);
    cudaGetSymbolAddress((void**)&phst, shst);
    cudaGetSymbolAddress((void**)&pxi, sxi);
    cudaGetSymbolAddress((void**)&pres, sres);
    cudaGetSymbolAddress((void**)&pr4, sr4);

    float* h1f = gi;    // fp32 staging (only split output is consumed)
    float* h2f = gh;
    float* CMf = gi;    // C@M computed after MLP phase

    cudaFuncSetAttribute(inv_block_k, cudaFuncAttributeMaxDynamicSharedMemorySize,
                         BLKD * BILD * (int)sizeof(float));
    cudaFuncSetAttribute(gemm_bf_k<128, 128>, cudaFuncAttributeMaxDynamicSharedMemorySize,
                         (2 * KCH * 132 + 2 * KCH * 132) * (int)sizeof(uint2));
    cudaFuncSetAttribute(gemm_bf_k<128, 64>, cudaFuncAttributeMaxDynamicSharedMemorySize,
                         (2 * KCH * 132 + 2 * KCH * 68) * (int)sizeof(uint2));

    const int TPB = 256;
    const int NTOT = BATCHD * NVARD;

    // ---- weight packing ----
    splitpair_k<<<ceil_div(HIDD * NVARD / 2, TPB), TPB>>>(W1, pW1, HIDD * NVARD / 2);
    splitpair_k<<<ceil_div(HIDD * HIDD / 2, TPB), TPB>>>(W2, pW2, HIDD * HIDD / 2);
    splitpair_k<<<ceil_div(MLPOUTD * HIDD / 2, TPB), TPB>>>(W3, pW3, MLPOUTD * HIDD / 2);
    splitpair_k<<<ceil_div(HIDD * NVARD / 2, TPB), TPB>>>(Wg, pWg, HIDD * NVARD / 2);
    combine_Wih_k<<<ceil_div(3 * HIDD * GIND4 / 2, TPB), TPB>>>(W_ih);
    splitpair_k<<<ceil_div(3 * HIDD * HIDD / 2, TPB), TPB>>>(W_hh, pWhh, 3 * HIDD * HIDD / 2);
    splitpair_k<<<ceil_div(GOUTD * HIDD / 2, TPB), TPB>>>(W_out, pWout, GOUTD * HIDD / 2);
    splitpair_k<<<ceil_div(NCD * NVARD / 2, TPB), TPB>>>(Cm, pC, NCD * NVARD / 2);
    transpose_C_k<<<ceil_div(NVARD * NCD / 2, TPB), TPB>>>(Cm);

    // ---- input normalization (+ pack) ----
    stats_zero_k<<<1, 1>>>();
    stats_k<<<512, TPB>>>(X, NTOT);
    normalize_k<<<ceil_div(NTOT / 2, TPB), TPB>>>(X, NTOT / 2);

    // ---- MLP warm start ----
    gemm_bf<128, 64>(pinp, pW1, h1f, nullptr, ph1, nullptr, nullptr, b1,
                     BATCHD, HIDD, 300, 300, 300, HIDD, HIDD, 1.f, 0.f, 1);
    gemm_bf<128, 64>(ph1, pW2, h2f, nullptr, ph2, nullptr, nullptr, b2,
                     BATCHD, HIDD, 512, 512, 512, HIDD, HIDD, 1.f, 0.f, 1);
    gemm_bf<128, 128>(ph2, pW3, nnout, nullptr, nullptr, nullptr, nullptr, b3,
                      BATCHD, MLPOUTD, 512, 512, 512, MLPOUTD, MLPOUTD, 1.f, 0.f, 0);
    split_nnout2_k<<<ceil_div(BATCHD * 800, TPB), TPB>>>(cvec);
    gemm_bf<128, 64>(pinp, pWg, hst, nullptr, phst, nullptr, nullptr, bg,
                     BATCHD, HIDD, 300, 300, 300, HIDD, HIDD, 1.f, 0.f, 2);

    // ---- KKT build + blocked Gauss-Jordan inverse (fp32 SIMT) ----
    init_G_k<<<ceil_div(KKTN * GLD, TPB), TPB>>>();
    gemm(Ct, Ct, G, Hm, NVARD, NVARD, NCD, NCD, NCD, GLD, NVARD, 1, 1.f, 1.f);
    for (int kb = 0; kb < KKTN / BLKD; kb++) {
        copy_cols_k<<<ceil_div(KKTN * BLKD, TPB), TPB>>>(kb);
        inv_block_k<<<1, 1024, BLKD * BILD * sizeof(float)>>>(kb);
        gemm(Einv, G + kb * BLKD * GLD, P, nullptr,
             BLKD, GLD, BLKD, BILD, GLD, GLD, 0, 0, 1.f, 0.f);
        writeback_k<<<ceil_div(BLKD * GLD, TPB), TPB>>>(kb);
        gemm(Ucol, P, G, G, KKTN, GLD, BLKD, BILD, GLD, GLD, GLD, 0, -1.f, 1.f);
    }
    v0_k<<<ceil_div(NVARD, TPB), TPB>>>();
    bias_xi_k<<<ceil_div(NVARD, TPB), TPB>>>(gv);
    gemm(Cm, G + 750, CMf, nullptr, NCD, NVARD, NVARD, NVARD, GLD, NVARD, 0, 0, 1.f, 0.f);
    build_Bxi_k<<<ceil_div(NVARD * XBL / 2, TPB), TPB>>>(CMf);

    // ---- 15 fixed-point iterations ----
    for (int t = 0; t < MAXITERD; t++) {
        // xi = [c-s | lam] @ [CM ; M]^T + (v0 - g@M)
        gemm_bf<128, 64>(pbl, pBxi, xi, nullptr, pxi, nullptr, nullptr, bxi,
                         BATCHD, NVARD, 800, 800, 800, NVARD, NVARD, 1.f, 0.f, 0);
        // Cx = xi @ C^T ; s_new = relu(c - Cx), res = relu(Cx - c)
        gemm_bf<128, 64>(pxi, pC, snew, res, nullptr, pres, nullptr, cvec,
                         BATCHD, NCD, 300, 300, 300, NCD, NCD, 1.f, 0.f, 3);
        rownorm_k<<<BATCHD, 256>>>(res, NCD, prim + t * BATCHD);
        // lam_new = lam - res @ C
        gemm_bf<128, 64>(pres, pCt, lamnew, nullptr, nullptr, nullptr, lam, nullptr,
                         BATCHD, NVARD, 500, 500, 500, NVARD, NVARD, -1.f, 1.f, 0);
        concat_r4_k<<<ceil_div(BATCHD * GIND4 / 2, TPB), TPB>>>();
        // GRU gates (combined W_ih, K=3200)
        gemm_bf<128, 128>(pr4, pWih4, gi, nullptr, nullptr, nullptr, nullptr, b_ih,
                          BATCHD, 3 * HIDD, 1600, 1600, 1600, 3 * HIDD, 3 * HIDD, 1.f, 0.f, 0);
        gemm_bf<128, 128>(phst, pWhh, gh, nullptr, nullptr, nullptr, nullptr, b_hh,
                          BATCHD, 3 * HIDD, 512, 512, 512, 3 * HIDD, 3 * HIDD, 1.f, 0.f, 0);
        gru_k<<<ceil_div(BATCHD * HIDD / 2, TPB), TPB>>>();
        // output head
        gemm_bf<128, 64>(phst, pWout, gout, nullptr, nullptr, nullptr, nullptr, b_out,
                         BATCHD, GOUTD, 512, 512, 512, GOUTD, GOUTD, 1.f, 0.f, 0);
        finalize2_k<<<BATCHD, 256>>>(t, cvec);
    }

    output_k<<<ceil_div(OUT_TOTAL, TPB), TPB>>>(out);
    (void)in_sizes; (void)n_in; (void)out_size;
}

// round 6
// speedup vs baseline: 2.2225x; 1.0003x over previous
#include <cuda_runtime.h>
#include <cuda_bf16.h>
#include <math.h>
#include <stdint.h>

// ---------------- problem constants ----------------
#define NVARD 600
#define NCD   1000
#define HIDD  1024
#define BATCHD 1024
#define MLPOUTD 2200
#define GIND4 3200
#define GOUTD 1600
#define MAXITERD 15
#define KKTN  750
#define GLD   1504
#define BLKD  150
#define BILD  152
#define XBL   1600
#define OUT_TOTAL (BATCHD*NVARD + BATCHD + BATCHD + MAXITERD*BATCHD + MAXITERD*BATCHD)

// ---------------- fp32 scratch ----------------
__device__ float g_inp[BATCHD*NVARD];
__device__ float g_nnout[BATCHD*MLPOUTD];
__device__ float g_hst[BATCHD*HIDD];
__device__ float g_lam[BATCHD*NVARD];
__device__ float g_lamnew[BATCHD*NVARD];
__device__ float g_s[BATCHD*NCD];
__device__ float g_snew[BATCHD*NCD];
__device__ float g_res[BATCHD*NCD];
__device__ float g_xi[BATCHD*NVARD];
__device__ float g_gi[BATCHD*3*HIDD];
__device__ float g_gh[BATCHD*3*HIDD];
__device__ float g_gout[BATCHD*GOUTD];
__device__ float g_G[KKTN*GLD];
__device__ float g_P[BLKD*GLD];
__device__ float g_Ucol[KKTN*BILD];
__device__ float g_Einv[BLKD*BILD];
__device__ float g_Ct[NVARD*NCD];
__device__ float g_v0[NVARD];
__device__ float g_bxi[NVARD];
__device__ float g_prim[MAXITERD*BATCHD];
__device__ float g_fp[MAXITERD*BATCHD];
__device__ double g_sum2[2];

// ---------------- packed bf16 (hi,lo) operand planes: uint2 per k-pair ----
// element layout: .x = bf16hi(x0) | bf16hi(x1)<<16 ; .y = bf16lo pair
__device__ uint2 sW1[HIDD*NVARD/2];
__device__ uint2 sW2[HIDD*HIDD/2];
__device__ uint2 sW3[MLPOUTD*HIDD/2];
__device__ uint2 sWg[HIDD*NVARD/2];
__device__ uint2 sWih4[3*HIDD*GIND4/2];
__device__ uint2 sWhh[3*HIDD*HIDD/2];
__device__ uint2 sWout[GOUTD*HIDD/2];
__device__ uint2 sC[NCD*NVARD/2];
__device__ uint2 sCt[NVARD*NCD/2];
__device__ uint2 sBxi[NVARD*XBL/2];
__device__ uint2 sbl[BATCHD*XBL/2];
__device__ uint2 sinp[BATCHD*NVARD/2];
__device__ uint2 sh1[BATCHD*HIDD/2];
__device__ uint2 sh2[BATCHD*HIDD/2];
__device__ uint2 shst[BATCHD*HIDD/2];
__device__ uint2 sxi[BATCHD*NVARD/2];
__device__ uint2 sres[BATCHD*NCD/2];
__device__ uint2 sr4[BATCHD*GIND4/2];

// ---------------- bf16 split helpers ----------------
__device__ __forceinline__ uint2 packsplit(float x0, float x1) {
    __nv_bfloat16 h0 = __float2bfloat16(x0);
    __nv_bfloat16 h1 = __float2bfloat16(x1);
    float r0 = x0 - __bfloat162float(h0);
    float r1 = x1 - __bfloat162float(h1);
    __nv_bfloat16 l0 = __float2bfloat16(r0);
    __nv_bfloat16 l1 = __float2bfloat16(r1);
    uint2 o;
    o.x = (uint32_t)__bfloat16_as_ushort(h0) | ((uint32_t)__bfloat16_as_ushort(h1) << 16);
    o.y = (uint32_t)__bfloat16_as_ushort(l0) | ((uint32_t)__bfloat16_as_ushort(l1) << 16);
    return o;
}

#define MMA_BF16(ac, a0, a1, a2, a3, b0, b1) \
    asm volatile("mma.sync.aligned.m16n8k16.row.col.f32.bf16.bf16.f32 " \
                 "{%0,%1,%2,%3},{%4,%5,%6,%7},{%8,%9},{%0,%1,%2,%3};" \
                 : "+f"(ac[0]), "+f"(ac[1]), "+f"(ac[2]), "+f"(ac[3]) \
                 : "r"(a0), "r"(a1), "r"(a2), "r"(a3), "r"(b0), "r"(b1))

// ===================================================================
// Tensor-core GEMM, 3xBF16 packed operands. B is [N, K] (row-major, i.e. B^T).
// K measured in k-pairs (Kp). C = act( alpha * A @ B^T + beta*Cin + bias )
// act: 0 none, 1 relu, 2 tanh, 3 dual: C=relu(bias-acc), C2=relu(acc-bias)
// Csp / Csp2: optional packed split of the (activated) outputs, ld = ldc/2.
// ===================================================================
#define KCH 16   // k-pairs per chunk (= 32 k)

template<int TBM, int TBN>
__global__ void __launch_bounds__(256)
gemm_bf_k(const uint2* __restrict__ A, const uint2* __restrict__ B,
          float* __restrict__ C, float* __restrict__ C2,
          uint2* __restrict__ Csp, uint2* __restrict__ Csp2,
          const float* __restrict__ Cin, const float* __restrict__ bias,
          int M, int N, int Kp, int ldap, int ldbp, int ldc, int ldcin,
          float alpha, float beta, int act)
{
    constexpr int WM = TBM / 2;
    constexpr int WN = TBN / 4;
    constexpr int MM = WM / 16;
    constexpr int NN = WN / 8;
    constexpr int APT = TBM * KCH / 256;
    constexpr int BPT = TBN * KCH / 256;
    constexpr int ALD = TBM + 4;
    constexpr int BLD = TBN + 4;

    extern __shared__ uint2 smu[];
    uint2* As = smu;                      // [2][KCH][ALD]
    uint2* Bs = smu + 2 * KCH * ALD;      // [2][KCH][BLD]

    const int tid = threadIdx.x;
    const int wid = tid >> 5;
    const int lane = tid & 31;
    const int lr = lane >> 2;
    const int lc = lane & 3;
    const int warp_m = wid >> 2;
    const int warp_n = wid & 3;
    const int m0 = blockIdx.y * TBM;
    const int n0 = blockIdx.x * TBN;

    float acc[MM][NN][4];
#pragma unroll
    for (int i = 0; i < MM; i++)
#pragma unroll
        for (int j = 0; j < NN; j++)
#pragma unroll
            for (int q = 0; q < 4; q++) acc[i][j][q] = 0.f;

    const int nchunks = (Kp + KCH - 1) / KCH;
    const uint2 z2 = make_uint2(0u, 0u);
    uint2 ra[APT], rb[BPT];

    // ---- prologue: load chunk 0 ----
    {
#pragma unroll
        for (int i = 0; i < APT; i++) {
            int e = tid + i * 256;
            int row = e >> 4, kp = e & 15;
            int gm = m0 + row;
            ra[i] = (gm < M && kp < Kp) ? A[gm * ldap + kp] : z2;
        }
#pragma unroll
        for (int i = 0; i < BPT; i++) {
            int e = tid + i * 256;
            int row = e >> 4, kp = e & 15;
            int gn = n0 + row;
            rb[i] = (gn < N && kp < Kp) ? B[gn * ldbp + kp] : z2;
        }
#pragma unroll
        for (int i = 0; i < APT; i++) {
            int e = tid + i * 256;
            As[(e & 15) * ALD + (e >> 4)] = ra[i];
        }
#pragma unroll
        for (int i = 0; i < BPT; i++) {
            int e = tid + i * 256;
            Bs[(e & 15) * BLD + (e >> 4)] = rb[i];
        }
        __syncthreads();
    }

    for (int ch = 0; ch < nchunks; ch++) {
        const int cur = ch & 1;
        const bool have_next = (ch + 1 < nchunks);

        if (have_next) {
            const int kk = (ch + 1) * KCH;
#pragma unroll
            for (int i = 0; i < APT; i++) {
                int e = tid + i * 256;
                int row = e >> 4, kp = e & 15;
                int gm = m0 + row, gk = kk + kp;
                ra[i] = (gm < M && gk < Kp) ? A[gm * ldap + gk] : z2;
            }
#pragma unroll
            for (int i = 0; i < BPT; i++) {
                int e = tid + i * 256;
                int row = e >> 4, kp = e & 15;
                int gn = n0 + row, gk = kk + kp;
                rb[i] = (gn < N && gk < Kp) ? B[gn * ldbp + gk] : z2;
            }
        }

        // ---- compute: 2 sub-chunks of 8 kpairs (one m16n8k16 set each) ----
#pragma unroll
        for (int kb = 0; kb < 2; kb++) {
            uint2 af[MM][4];
            uint2 bf[NN][2];
            const int kof = (cur * KCH + kb * 8);
#pragma unroll
            for (int mm = 0; mm < MM; mm++) {
                int mrow = warp_m * WM + mm * 16 + lr;
                af[mm][0] = As[(kof + lc) * ALD + mrow];
                af[mm][1] = As[(kof + lc) * ALD + mrow + 8];
                af[mm][2] = As[(kof + 4 + lc) * ALD + mrow];
                af[mm][3] = As[(kof + 4 + lc) * ALD + mrow + 8];
            }
#pragma unroll
            for (int nn = 0; nn < NN; nn++) {
                int ncol = warp_n * WN + nn * 8 + lr;
                bf[nn][0] = Bs[(kof + lc) * BLD + ncol];
                bf[nn][1] = Bs[(kof + 4 + lc) * BLD + ncol];
            }
            // pass 1: a_lo * b_hi
#pragma unroll
            for (int mm = 0; mm < MM; mm++)
#pragma unroll
                for (int nn = 0; nn < NN; nn++)
                    MMA_BF16(acc[mm][nn], af[mm][0].y, af[mm][1].y, af[mm][2].y, af[mm][3].y,
                             bf[nn][0].x, bf[nn][1].x);
            // pass 2: a_hi * b_lo
#pragma unroll
            for (int mm = 0; mm < MM; mm++)
#pragma unroll
                for (int nn = 0; nn < NN; nn++)
                    MMA_BF16(acc[mm][nn], af[mm][0].x, af[mm][1].x, af[mm][2].x, af[mm][3].x,
                             bf[nn][0].y, bf[nn][1].y);
            // pass 3: a_hi * b_hi
#pragma unroll
            for (int mm = 0; mm < MM; mm++)
#pragma unroll
                for (int nn = 0; nn < NN; nn++)
                    MMA_BF16(acc[mm][nn], af[mm][0].x, af[mm][1].x, af[mm][2].x, af[mm][3].x,
                             bf[nn][0].x, bf[nn][1].x);
        }

        if (have_next) {
            const int nxt = cur ^ 1;
#pragma unroll
            for (int i = 0; i < APT; i++) {
                int e = tid + i * 256;
                As[(nxt * KCH + (e & 15)) * ALD + (e >> 4)] = ra[i];
            }
#pragma unroll
            for (int i = 0; i < BPT; i++) {
                int e = tid + i * 256;
                Bs[(nxt * KCH + (e & 15)) * BLD + (e >> 4)] = rb[i];
            }
        }
        __syncthreads();
    }

    // ---- epilogue ----
    const int ldcp = ldc >> 1;
#pragma unroll
    for (int mm = 0; mm < MM; mm++) {
        int r0 = m0 + warp_m * WM + mm * 16 + lr;
#pragma unroll
        for (int nn = 0; nn < NN; nn++) {
            int c0 = n0 + warp_n * WN + nn * 8 + lc * 2;
            if (c0 >= N) continue;
            float v[4];
#pragma unroll
            for (int q = 0; q < 4; q++) {
                int row = r0 + (q >> 1) * 8;
                int col = c0 + (q & 1);
                float x = alpha * acc[mm][nn][q];
                if (beta != 0.f) x += beta * Cin[row * ldcin + col];
                v[q] = x;
            }
            if (act == 3) {
                float cc0 = bias[c0], cc1 = bias[c0 + 1];
                float s0 = fmaxf(cc0 - v[0], 0.f), s1 = fmaxf(cc1 - v[1], 0.f);
                float s2 = fmaxf(cc0 - v[2], 0.f), s3 = fmaxf(cc1 - v[3], 0.f);
                float r0v = fmaxf(v[0] - cc0, 0.f), r1v = fmaxf(v[1] - cc1, 0.f);
                float r2v = fmaxf(v[2] - cc0, 0.f), r3v = fmaxf(v[3] - cc1, 0.f);
                C[r0 * ldc + c0] = s0;       C[r0 * ldc + c0 + 1] = s1;
                C[(r0 + 8) * ldc + c0] = s2; C[(r0 + 8) * ldc + c0 + 1] = s3;
                C2[r0 * ldc + c0] = r0v;       C2[r0 * ldc + c0 + 1] = r1v;
                C2[(r0 + 8) * ldc + c0] = r2v; C2[(r0 + 8) * ldc + c0 + 1] = r3v;
                if (Csp2) {
                    Csp2[r0 * ldcp + (c0 >> 1)] = packsplit(r0v, r1v);
                    Csp2[(r0 + 8) * ldcp + (c0 >> 1)] = packsplit(r2v, r3v);
                }
            } else {
                if (bias) { v[0] += bias[c0]; v[1] += bias[c0 + 1]; v[2] += bias[c0]; v[3] += bias[c0 + 1]; }
                if (act == 1) {
#pragma unroll
                    for (int q = 0; q < 4; q++) v[q] = fmaxf(v[q], 0.f);
                } else if (act == 2) {
#pragma unroll
                    for (int q = 0; q < 4; q++) v[q] = tanhf(v[q]);
                }
                C[r0 * ldc + c0] = v[0];       C[r0 * ldc + c0 + 1] = v[1];
                C[(r0 + 8) * ldc + c0] = v[2]; C[(r0 + 8) * ldc + c0 + 1] = v[3];
                if (Csp) {
                    Csp[r0 * ldcp + (c0 >> 1)] = packsplit(v[0], v[1]);
                    Csp[(r0 + 8) * ldcp + (c0 >> 1)] = packsplit(v[2], v[3]);
                }
            }
        }
    }
}

// ---------------- fp32 SIMT GEMM (KKT pipeline only) --------
#define BM 64
#define BN 64
#define BKK 16

__global__ void gemm_k(const float* __restrict__ A, const float* __restrict__ B,
                       float* __restrict__ C, const float* __restrict__ Cin,
                       int M, int N, int K, int lda, int ldb, int ldc, int ldcin,
                       int transB, float alpha, float beta)
{
    __shared__ float As[BKK][BM];
    __shared__ float Bs[BKK][BN];
    const int tid = threadIdx.x;
    const int tx = tid & 15, ty = tid >> 4;
    const int m0 = blockIdx.y * BM, n0 = blockIdx.x * BN;
    float acc[4][4] = {};

    for (int kk = 0; kk < K; kk += BKK) {
#pragma unroll
        for (int i = 0; i < 4; i++) {
            int e = tid + i * 256;
            int m = e >> 4, k = e & 15;
            int gm = m0 + m, gk = kk + k;
            As[k][m] = (gm < M && gk < K) ? A[gm * lda + gk] : 0.f;
        }
        if (transB) {
#pragma unroll
            for (int i = 0; i < 4; i++) {
                int e = tid + i * 256;
                int n = e >> 4, k = e & 15;
                int gn = n0 + n, gk = kk + k;
                Bs[k][n] = (gn < N && gk < K) ? B[gn * ldb + gk] : 0.f;
            }
        } else {
#pragma unroll
            for (int i = 0; i < 4; i++) {
                int e = tid + i * 256;
                int k = e >> 6, n = e & 63;
                int gn = n0 + n, gk = kk + k;
                Bs[k][n] = (gn < N && gk < K) ? B[gk * ldb + gn] : 0.f;
            }
        }
        __syncthreads();
#pragma unroll
        for (int k = 0; k < BKK; k++) {
            float a0 = As[k][ty*4+0], a1 = As[k][ty*4+1], a2 = As[k][ty*4+2], a3 = As[k][ty*4+3];
            float b0 = Bs[k][tx*4+0], b1 = Bs[k][tx*4+1], b2 = Bs[k][tx*4+2], b3 = Bs[k][tx*4+3];
            acc[0][0] += a0*b0; acc[0][1] += a0*b1; acc[0][2] += a0*b2; acc[0][3] += a0*b3;
            acc[1][0] += a1*b0; acc[1][1] += a1*b1; acc[1][2] += a1*b2; acc[1][3] += a1*b3;
            acc[2][0] += a2*b0; acc[2][1] += a2*b1; acc[2][2] += a2*b2; acc[2][3] += a2*b3;
            acc[3][0] += a3*b0; acc[3][1] += a3*b1; acc[3][2] += a3*b2; acc[3][3] += a3*b3;
        }
        __syncthreads();
    }

#pragma unroll
    for (int i = 0; i < 4; i++) {
        int row = m0 + ty*4 + i;
        if (row >= M) continue;
#pragma unroll
        for (int j = 0; j < 4; j++) {
            int col = n0 + tx*4 + j;
            if (col >= N) continue;
            float v = alpha * acc[i][j];
            if (beta != 0.f) v += beta * Cin[row * ldcin + col];
            C[row * ldc + col] = v;
        }
    }
}

// ---------------- split / setup kernels ----------------
__global__ void splitpair_k(const float* __restrict__ x, uint2* __restrict__ y, int npairs) {
    int i = blockIdx.x * blockDim.x + threadIdx.x;
    if (i < npairs) y[i] = packsplit(x[2*i], x[2*i+1]);
}

__global__ void combine_Wih_k(const float* __restrict__ W) {
    int idx = blockIdx.x * blockDim.x + threadIdx.x;
    if (idx >= 3 * HIDD * GIND4 / 2) return;
    int i = idx / (GIND4/2), pp = idx % (GIND4/2);
    int j = 2 * pp;
    const float* row = W + i * 4800;
    float v0, v1;
    if (j < 1000)       { v0 = row[j] - row[3200 + j];           v1 = row[j+1] - row[3200 + j + 1]; }
    else if (j < 1600)  { v0 = row[j] - row[4200 + (j - 1000)];  v1 = row[j+1] - row[4200 + (j - 999)]; }
    else if (j < 2600)  { v0 = row[j] + row[3200 + (j - 1600)];  v1 = row[j+1] + row[3200 + (j - 1599)]; }
    else                { v0 = row[j] + row[4200 + (j - 2600)];  v1 = row[j+1] + row[4200 + (j - 2599)]; }
    sWih4[idx] = packsplit(v0, v1);
}

__global__ void build_Bxi_k(const float* __restrict__ CM) {
    int idx = blockIdx.x * blockDim.x + threadIdx.x;
    if (idx >= NVARD * XBL / 2) return;
    int n = idx / (XBL/2), kp = idx % (XBL/2);
    int k0 = 2 * kp;
    float v0, v1;
    if (k0 < 1000) { v0 = CM[k0 * NVARD + n]; v1 = CM[(k0+1) * NVARD + n]; }
    else { v0 = g_G[(k0 - 1000) * GLD + 750 + n]; v1 = g_G[(k0 - 999) * GLD + 750 + n]; }
    sBxi[idx] = packsplit(v0, v1);
}

__global__ void bias_xi_k(const float* __restrict__ gv) {
    int n = blockIdx.x * blockDim.x + threadIdx.x;
    if (n >= NVARD) return;
    float acc = 0.f;
    for (int k = 0; k < NVARD; k++) acc += gv[k] * g_G[k * GLD + 750 + n];
    g_bxi[n] = g_v0[n] - acc;
}

// ---------------- statistics / normalization ----------------
__global__ void stats_zero_k() { g_sum2[0] = 0.0; g_sum2[1] = 0.0; }

__global__ void stats_k(const float* __restrict__ x, int n) {
    float s = 0.f, ss = 0.f;
    for (int i = blockIdx.x * blockDim.x + threadIdx.x; i < n; i += gridDim.x * blockDim.x) {
        float v = x[i]; s += v; ss += v * v;
    }
    __shared__ float s1[256], s2[256];
    s1[threadIdx.x] = s; s2[threadIdx.x] = ss;
    __syncthreads();
    for (int o = 128; o > 0; o >>= 1) {
        if (threadIdx.x < o) { s1[threadIdx.x] += s1[threadIdx.x+o]; s2[threadIdx.x] += s2[threadIdx.x+o]; }
        __syncthreads();
    }
    if (threadIdx.x == 0) {
        atomicAdd(&g_sum2[0], (double)s1[0]);
        atomicAdd(&g_sum2[1], (double)s2[0]);
    }
}

__global__ void normalize_k(const float* __restrict__ x, int npairs) {
    double sum = g_sum2[0], sumsq = g_sum2[1];
    const double nn = (double)(2 * npairs);
    double mean = sum / nn;
    double var = (sumsq - sum * sum / nn) / (nn - 1.0);
    float istd = 1.0f / ((float)sqrt(var) + 1e-8f);
    float m = (float)mean;
    for (int i = blockIdx.x * blockDim.x + threadIdx.x; i < npairs; i += gridDim.x * blockDim.x) {
        float v0 = (x[2*i] - m) * istd;
        float v1 = (x[2*i+1] - m) * istd;
        g_inp[2*i] = v0; g_inp[2*i+1] = v1;
        sinp[i] = packsplit(v0, v1);
    }
}

// ---------------- small setup kernels ----------------
__global__ void split_nnout2_k(const float* __restrict__ cvec) {
    int idx = blockIdx.x * blockDim.x + threadIdx.x;
    if (idx >= BATCHD * 800) return;
    int b = idx / 800, pp = idx % 800;
    if (pp < 500) {
        int j = 2 * pp;
        float s0 = fmaxf(g_nnout[b * MLPOUTD + 1200 + j], 0.f);
        float s1 = fmaxf(g_nnout[b * MLPOUTD + 1200 + j + 1], 0.f);
        g_s[b * NCD + j] = s0; g_s[b * NCD + j + 1] = s1;
        sbl[b * 800 + pp] = packsplit(cvec[j] - s0, cvec[j+1] - s1);
    } else {
        int r = 2 * (pp - 500);
        float l0 = g_nnout[b * MLPOUTD + 600 + r];
        float l1 = g_nnout[b * MLPOUTD + 600 + r + 1];
        g_lam[b * NVARD + r] = l0; g_lam[b * NVARD + r + 1] = l1;
        sbl[b * 800 + pp] = packsplit(l0, l1);
    }
}

__global__ void transpose_C_k(const float* __restrict__ Cm) {
    int idx = blockIdx.x * blockDim.x + threadIdx.x;
    if (idx >= NVARD * NCD / 2) return;
    int i = idx / (NCD/2), kp = idx % (NCD/2);
    float v0 = Cm[(2*kp) * NVARD + i];
    float v1 = Cm[(2*kp+1) * NVARD + i];
    g_Ct[i * NCD + 2*kp] = v0;
    g_Ct[i * NCD + 2*kp+1] = v1;
    sCt[idx] = packsplit(v0, v1);
}

__global__ void init_G_k() {
    int idx = blockIdx.x * blockDim.x + threadIdx.x;
    if (idx >= KKTN * GLD) return;
    int r = idx / GLD, c = idx % GLD;
    float v = 0.f;
    if (c >= 750) {
        if (c - 750 == r) v = 1.f;
    } else if (r >= 600 && c < 600) {
        int rr = r - 600, t = rr / 3, i = rr % 3;
        if (c / 12 == t && (c % 12) % 3 == i) v = 1.f;
    } else if (r < 600 && c >= 600) {
        int cc = c - 600, t = cc / 3, i = cc % 3;
        if (r / 12 == t && (r % 12) % 3 == i) v = 1.f;
    }
    g_G[idx] = v;
}

__global__ void v0_k() {
    int j = blockIdx.x * blockDim.x + threadIdx.x;
    if (j >= NVARD) return;
    float beq = 30.0f * 9.81f;
    float acc = 0.f;
    for (int t = 0; t < 50; t++) acc += g_G[j * GLD + 750 + 600 + 3 * t + 2];
    g_v0[j] = beq * acc;
}

// ---------------- blocked Gauss-Jordan helpers ----------------
__global__ void copy_cols_k(int kb) {
    int idx = blockIdx.x * blockDim.x + threadIdx.x;
    if (idx >= KKTN * BLKD) return;
    int r = idx / BLKD, j = idx % BLKD;
    g_Ucol[r * BILD + j] = g_G[r * GLD + kb * BLKD + j];
}

__global__ void inv_block_k(int kb) {
    extern __shared__ float s[];
    const int n = BLKD, ld = BILD;
    int tid = threadIdx.x, nt = blockDim.x;
    for (int e = tid; e < n * n; e += nt)
        s[(e / n) * ld + (e % n)] = g_Ucol[(kb * BLKD + e / n) * BILD + (e % n)];
    __shared__ float fcol[BLKD];
    __shared__ float s_ipiv;
    __syncthreads();
    for (int p = 0; p < n; p++) {
        if (tid == 0) s_ipiv = 1.0f / s[p * ld + p];
        __syncthreads();
        float ipiv = s_ipiv;
        for (int j = tid; j < n; j += nt) if (j != p) s[p * ld + j] *= ipiv;
        for (int r = tid; r < n; r += nt) fcol[r] = (r == p) ? 0.f : s[r * ld + p];
        __syncthreads();
        for (int e = tid; e < n * n; e += nt) {
            int r = e / n, j = e % n;
            if (r != p && j != p) s[r * ld + j] -= fcol[r] * s[p * ld + j];
        }
        __syncthreads();
        for (int r = tid; r < n; r += nt) {
            if (r == p) s[p * ld + p] = ipiv;
            else s[r * ld + p] = -fcol[r] * ipiv;
        }
        __syncthreads();
    }
    for (int e = tid; e < n * n; e += nt)
        g_Einv[(e / n) * BILD + (e % n)] = s[(e / n) * ld + (e % n)];
}

__global__ void writeback_k(int kb) {
    int idx = blockIdx.x * blockDim.x + threadIdx.x;
    if (idx >= BLKD * GLD) return;
    int r = idx / GLD, j = idx % GLD;
    g_G[(kb * BLKD + r) * GLD + j] = g_P[idx];
    if (j < BILD) g_Ucol[(kb * BLKD + r) * BILD + j] = 0.f;
}

// ---------------- iteration elementwise kernels ----------------
__global__ void rownorm_k(const float* __restrict__ v, int ncols, float* __restrict__ out) {
    int b = blockIdx.x;
    float acc = 0.f;
    for (int j = threadIdx.x; j < ncols; j += blockDim.x) {
        float t = v[b * ncols + j]; acc += t * t;
    }
    __shared__ float sm[256];
    sm[threadIdx.x] = acc; __syncthreads();
    for (int o = 128; o > 0; o >>= 1) {
        if (threadIdx.x < o) sm[threadIdx.x] += sm[threadIdx.x + o];
        __syncthreads();
    }
    if (threadIdx.x == 0) out[b] = sqrtf(sm[0]);
}

__global__ void concat_r4_k() {
    int idx = blockIdx.x * blockDim.x + threadIdx.x;
    if (idx >= BATCHD * GIND4 / 2) return;
    int b = idx / (GIND4/2), pp = idx % (GIND4/2);
    int q = 2 * pp;
    float v0, v1;
    if (q < 1000)       { v0 = g_s[b * NCD + q];              v1 = g_s[b * NCD + q + 1]; }
    else if (q < 1600)  { v0 = g_lam[b * NVARD + q - 1000];   v1 = g_lam[b * NVARD + q - 999]; }
    else if (q < 2600)  { v0 = g_snew[b * NCD + q - 1600];    v1 = g_snew[b * NCD + q - 1599]; }
    else                { v0 = g_lamnew[b * NVARD + q - 2600];v1 = g_lamnew[b * NVARD + q - 2599]; }
    sr4[idx] = packsplit(v0, v1);
}

__device__ __forceinline__ float sigmoidf(float x) { return 1.0f / (1.0f + expf(-x)); }

__global__ void gru_k() {
    int p = blockIdx.x * blockDim.x + threadIdx.x;
    if (p >= BATCHD * HIDD / 2) return;
    int b = p / 512, jp = p % 512;
    int j = 2 * jp;
    int base = b * 3 * HIDD + j;
    float h0, h1;
#pragma unroll
    for (int e = 0; e < 2; e++) {
        float ir = g_gi[base + e], iz = g_gi[base + HIDD + e], in_ = g_gi[base + 2 * HIDD + e];
        float hr = g_gh[base + e], hz = g_gh[base + HIDD + e], hn = g_gh[base + 2 * HIDD + e];
        float rg = sigmoidf(ir + hr);
        float z  = sigmoidf(iz + hz);
        float nv = tanhf(in_ + rg * hn);
        float h  = g_hst[b * HIDD + j + e];
        float hnew = (1.f - z) * nv + z * h;
        g_hst[b * HIDD + j + e] = hnew;
        if (e == 0) h0 = hnew; else h1 = hnew;
    }
    shst[b * 512 + jp] = packsplit(h0, h1);
}

// finalize: s/lam update + fp norm + next-iteration [baug|lam] packed splits
__global__ void finalize2_k(int t, const float* __restrict__ cvec) {
    int b = blockIdx.x;
    float accs = 0.f, accl = 0.f;
    for (int pj = threadIdx.x; pj < 800; pj += blockDim.x) {
        int j = 2 * pj;
        if (j < NCD) {
            float go0 = g_gout[b * GOUTD + j], go1 = g_gout[b * GOUTD + j + 1];
            float sf0 = fmaxf(g_snew[b * NCD + j] + go0, 0.f);
            float sf1 = fmaxf(g_snew[b * NCD + j + 1] + go1, 0.f);
            float d0 = sf0 - g_s[b * NCD + j], d1 = sf1 - g_s[b * NCD + j + 1];
            accs += d0 * d0 + d1 * d1;
            g_s[b * NCD + j] = sf0; g_s[b * NCD + j + 1] = sf1;
            sbl[b * 800 + pj] = packsplit(cvec[j] - sf0, cvec[j+1] - sf1);
        } else {
            int j2 = j - NCD;
            float go0 = g_gout[b * GOUTD + j], go1 = g_gout[b * GOUTD + j + 1];
            float lf0 = g_lamnew[b * NVARD + j2] + go0;
            float lf1 = g_lamnew[b * NVARD + j2 + 1] + go1;
            float d0 = lf0 - g_lam[b * NVARD + j2], d1 = lf1 - g_lam[b * NVARD + j2 + 1];
            accl += d0 * d0 + d1 * d1;
            g_lam[b * NVARD + j2] = lf0; g_lam[b * NVARD + j2 + 1] = lf1;
            sbl[b * 800 + pj] = packsplit(lf0, lf1);
        }
    }
    __shared__ float sm1[256], sm2[256];
    sm1[threadIdx.x] = accs; sm2[threadIdx.x] = accl;
    __syncthreads();
    for (int o = 128; o > 0; o >>= 1) {
        if (threadIdx.x < o) { sm1[threadIdx.x] += sm1[threadIdx.x+o]; sm2[threadIdx.x] += sm2[threadIdx.x+o]; }
        __syncthreads();
    }
    if (threadIdx.x == 0)
        g_fp[t * BATCHD + b] = sqrtf(sm2[0]) + sqrtf(sm1[0]);
}

// ---------------- output assembly ----------------
__global__ void output_k(float* __restrict__ out) {
    int idx = blockIdx.x * blockDim.x + threadIdx.x;
    if (idx >= OUT_TOTAL) return;
    const int XI_END = BATCHD * NVARD;
    const int AFP_END = XI_END + BATCHD;
    const int APR_END = AFP_END + BATCHD;
    const int PH_END = APR_END + MAXITERD * BATCHD;
    if (idx < XI_END) out[idx] = g_xi[idx];
    else if (idx < AFP_END) {
        int b = idx - XI_END;
        float a = 0.f;
        for (int t = 0; t < MAXITERD; t++) a += g_fp[t * BATCHD + b];
        out[idx] = a / (float)MAXITERD;
    } else if (idx < APR_END) {
        int b = idx - AFP_END;
        float a = 0.f;
        for (int t = 0; t < MAXITERD; t++) a += g_prim[t * BATCHD + b];
        out[idx] = a / (float)MAXITERD;
    } else if (idx < PH_END) out[idx] = g_prim[idx - APR_END];
    else out[idx] = g_fp[idx - PH_END];
}

// ---------------- host side ----------------
static inline int ceil_div(int a, int b) { return (a + b - 1) / b; }

static void gemm(const float* A, const float* B, float* C, const float* Cin,
                 int M, int N, int K, int lda, int ldb, int ldc, int ldcin,
                 int transB, float alpha, float beta)
{
    dim3 grid((N + BN - 1) / BN, (M + BM - 1) / BM);
    gemm_k<<<grid, 256>>>(A, B, C, Cin, M, N, K, lda, ldb, ldc, ldcin, transB, alpha, beta);
}

template<int TBM, int TBN>
static void gemm_bf(const uint2* A, const uint2* B, float* C, float* C2,
                    uint2* Csp, uint2* Csp2, const float* Cin, const float* bias,
                    int M, int N, int Kp, int ldap, int ldbp, int ldc, int ldcin,
                    float alpha, float beta, int act)
{
    size_t smem = (size_t)(2 * KCH * (TBM + 4) + 2 * KCH * (TBN + 4)) * sizeof(uint2);
    dim3 grid((N + TBN - 1) / TBN, (M + TBM - 1) / TBM);
    gemm_bf_k<TBM, TBN><<<grid, 256, smem>>>(A, B, C, C2, Csp, Csp2, Cin, bias,
                                             M, N, Kp, ldap, ldbp, ldc, ldcin, alpha, beta, act);
}

extern "C" void kernel_launch(void* const* d_in, const int* in_sizes, int n_in,
                              void* d_out, int out_size) {
    const float* X    = (const float*)d_in[0];
    const float* Hm   = (const float*)d_in[1];
    const float* gv   = (const float*)d_in[2];
    const float* Cm   = (const float*)d_in[3];
    const float* cvec = (const float*)d_in[4];
    const float* W1   = (const float*)d_in[5];
    const float* b1   = (const float*)d_in[6];
    const float* W2   = (const float*)d_in[7];
    const float* b2   = (const float*)d_in[8];
    const float* W3   = (const float*)d_in[9];
    const float* b3   = (const float*)d_in[10];
    const float* Wg   = (const float*)d_in[11];
    const float* bg   = (const float*)d_in[12];
    const float* W_ih = (const float*)d_in[13];
    const float* W_hh = (const float*)d_in[14];
    const float* b_ih = (const float*)d_in[15];
    const float* b_hh = (const float*)d_in[16];
    const float* W_out= (const float*)d_in[17];
    const float* b_out= (const float*)d_in[18];
    float* out = (float*)d_out;

    float *nnout, *hst, *lam, *lamnew, *s, *snew, *res, *xi, *gi, *gh, *gout,
          *G, *P, *Ucol, *Einv, *Ct, *prim, *fp, *bxi;
    uint2 *pW1, *pW2, *pW3, *pWg, *pWih4, *pWhh, *pWout, *pC, *pCt, *pBxi,
          *pbl, *pinp, *ph1, *ph2, *phst, *pxi, *pres, *pr4;
    cudaGetSymbolAddress((void**)&nnout, g_nnout);
    cudaGetSymbolAddress((void**)&hst, g_hst);
    cudaGetSymbolAddress((void**)&lam, g_lam);
    cudaGetSymbolAddress((void**)&lamnew, g_lamnew);
    cudaGetSymbolAddress((void**)&s, g_s);
    cudaGetSymbolAddress((void**)&snew, g_snew);
    cudaGetSymbolAddress((void**)&res, g_res);
    cudaGetSymbolAddress((void**)&xi, g_xi);
    cudaGetSymbolAddress((void**)&gi, g_gi);
    cudaGetSymbolAddress((void**)&gh, g_gh);
    cudaGetSymbolAddress((void**)&gout, g_gout);
    cudaGetSymbolAddress((void**)&G, g_G);
    cudaGetSymbolAddress((void**)&P, g_P);
    cudaGetSymbolAddress((void**)&Ucol, g_Ucol);
    cudaGetSymbolAddress((void**)&Einv, g_Einv);
    cudaGetSymbolAddress((void**)&Ct, g_Ct);
    cudaGetSymbolAddress((void**)&prim, g_prim);
    cudaGetSymbolAddress((void**)&fp, g_fp);
    cudaGetSymbolAddress((void**)&bxi, g_bxi);
    cudaGetSymbolAddress((void**)&pW1, sW1);
    cudaGetSymbolAddress((void**)&pW2, sW2);
    cudaGetSymbolAddress((void**)&pW3, sW3);
    cudaGetSymbolAddress((void**)&pWg, sWg);
    cudaGetSymbolAddress((void**)&pWih4, sWih4);
    cudaGetSymbolAddress((void**)&pWhh, sWhh);
    cudaGetSymbolAddress((void**)&pWout, sWout);
    cudaGetSymbolAddress((void**)&pC, sC);
    cudaGetSymbolAddress((void**)&pCt, sCt);
    cudaGetSymbolAddress((void**)&pBxi, sBxi);
    cudaGetSymbolAddress((void**)&pbl, sbl);
    cudaGetSymbolAddress((void**)&pinp, sinp);
    cudaGetSymbolAddress((void**)&ph1, sh1);
    cudaGetSymbolAddress((void**)&ph2, sh2);
    cudaGetSymbolAddress((void**)&phst, shst);
    cudaGetSymbolAddress((void**)&pxi, sxi);
    cudaGetSymbolAddress((void**)&pres, sres);
    cudaGetSymbolAddress((void**)&pr4, sr4);

    float* h1f = gi;    // fp32 staging (only split output is consumed)
    float* h2f = gh;
    float* CMf = gi;    // C@M computed after MLP phase

    cudaFuncSetAttribute(inv_block_k, cudaFuncAttributeMaxDynamicSharedMemorySize,
                         BLKD * BILD * (int)sizeof(float));
    cudaFuncSetAttribute(gemm_bf_k<128, 128>, cudaFuncAttributeMaxDynamicSharedMemorySize,
                         (2 * KCH * 132 + 2 * KCH * 132) * (int)sizeof(uint2));
    cudaFuncSetAttribute(gemm_bf_k<128, 64>, cudaFuncAttributeMaxDynamicSharedMemorySize,
                         (2 * KCH * 132 + 2 * KCH * 68) * (int)sizeof(uint2));

    const int TPB = 256;
    const int NTOT = BATCHD * NVARD;

    // ---- weight packing ----
    splitpair_k<<<ceil_div(HIDD * NVARD / 2, TPB), TPB>>>(W1, pW1, HIDD * NVARD / 2);
    splitpair_k<<<ceil_div(HIDD * HIDD / 2, TPB), TPB>>>(W2, pW2, HIDD * HIDD / 2);
    splitpair_k<<<ceil_div(MLPOUTD * HIDD / 2, TPB), TPB>>>(W3, pW3, MLPOUTD * HIDD / 2);
    splitpair_k<<<ceil_div(HIDD * NVARD / 2, TPB), TPB>>>(Wg, pWg, HIDD * NVARD / 2);
    combine_Wih_k<<<ceil_div(3 * HIDD * GIND4 / 2, TPB), TPB>>>(W_ih);
    splitpair_k<<<ceil_div(3 * HIDD * HIDD / 2, TPB), TPB>>>(W_hh, pWhh, 3 * HIDD * HIDD / 2);
    splitpair_k<<<ceil_div(GOUTD * HIDD / 2, TPB), TPB>>>(W_out, pWout, GOUTD * HIDD / 2);
    splitpair_k<<<ceil_div(NCD * NVARD / 2, TPB), TPB>>>(Cm, pC, NCD * NVARD / 2);
    transpose_C_k<<<ceil_div(NVARD * NCD / 2, TPB), TPB>>>(Cm);

    // ---- input normalization (+ pack) ----
    stats_zero_k<<<1, 1>>>();
    stats_k<<<512, TPB>>>(X, NTOT);
    normalize_k<<<ceil_div(NTOT / 2, TPB), TPB>>>(X, NTOT / 2);

    // ---- MLP warm start ----
    gemm_bf<128, 64>(pinp, pW1, h1f, nullptr, ph1, nullptr, nullptr, b1,
                     BATCHD, HIDD, 300, 300, 300, HIDD, HIDD, 1.f, 0.f, 1);
    gemm_bf<128, 64>(ph1, pW2, h2f, nullptr, ph2, nullptr, nullptr, b2,
                     BATCHD, HIDD, 512, 512, 512, HIDD, HIDD, 1.f, 0.f, 1);
    gemm_bf<128, 128>(ph2, pW3, nnout, nullptr, nullptr, nullptr, nullptr, b3,
                      BATCHD, MLPOUTD, 512, 512, 512, MLPOUTD, MLPOUTD, 1.f, 0.f, 0);
    split_nnout2_k<<<ceil_div(BATCHD * 800, TPB), TPB>>>(cvec);
    gemm_bf<128, 64>(pinp, pWg, hst, nullptr, phst, nullptr, nullptr, bg,
                     BATCHD, HIDD, 300, 300, 300, HIDD, HIDD, 1.f, 0.f, 2);

    // ---- KKT build + blocked Gauss-Jordan inverse (fp32 SIMT) ----
    init_G_k<<<ceil_div(KKTN * GLD, TPB), TPB>>>();
    gemm(Ct, Ct, G, Hm, NVARD, NVARD, NCD, NCD, NCD, GLD, NVARD, 1, 1.f, 1.f);
    for (int kb = 0; kb < KKTN / BLKD; kb++) {
        copy_cols_k<<<ceil_div(KKTN * BLKD, TPB), TPB>>>(kb);
        inv_block_k<<<1, 1024, BLKD * BILD * sizeof(float)>>>(kb);
        gemm(Einv, G + kb * BLKD * GLD, P, nullptr,
             BLKD, GLD, BLKD, BILD, GLD, GLD, 0, 0, 1.f, 0.f);
        writeback_k<<<ceil_div(BLKD * GLD, TPB), TPB>>>(kb);
        gemm(Ucol, P, G, G, KKTN, GLD, BLKD, BILD, GLD, GLD, GLD, 0, -1.f, 1.f);
    }
    v0_k<<<ceil_div(NVARD, TPB), TPB>>>();
    bias_xi_k<<<ceil_div(NVARD, TPB), TPB>>>(gv);
    gemm(Cm, G + 750, CMf, nullptr, NCD, NVARD, NVARD, NVARD, GLD, NVARD, 0, 0, 1.f, 0.f);
    build_Bxi_k<<<ceil_div(NVARD * XBL / 2, TPB), TPB>>>(CMf);

    // ---- 15 fixed-point iterations ----
    for (int t = 0; t < MAXITERD; t++) {
        // xi = [c-s | lam] @ [CM ; M]^T + (v0 - g@M)
        gemm_bf<128, 64>(pbl, pBxi, xi, nullptr, pxi, nullptr, nullptr, bxi,
                         BATCHD, NVARD, 800, 800, 800, NVARD, NVARD, 1.f, 0.f, 0);
        // Cx = xi @ C^T ; s_new = relu(c - Cx), res = relu(Cx - c)
        gemm_bf<128, 64>(pxi, pC, snew, res, nullptr, pres, nullptr, cvec,
                         BATCHD, NCD, 300, 300, 300, NCD, NCD, 1.f, 0.f, 3);
        rownorm_k<<<BATCHD, 256>>>(res, NCD, prim + t * BATCHD);
        // lam_new = lam - res @ C
        gemm_bf<128, 64>(pres, pCt, lamnew, nullptr, nullptr, nullptr, lam, nullptr,
                         BATCHD, NVARD, 500, 500, 500, NVARD, NVARD, -1.f, 1.f, 0);
        concat_r4_k<<<ceil_div(BATCHD * GIND4 / 2, TPB), TPB>>>();
        // GRU gates (combined W_ih, K=3200)
        gemm_bf<128, 128>(pr4, pWih4, gi, nullptr, nullptr, nullptr, nullptr, b_ih,
                          BATCHD, 3 * HIDD, 1600, 1600, 1600, 3 * HIDD, 3 * HIDD, 1.f, 0.f, 0);
        gemm_bf<128, 128>(phst, pWhh, gh, nullptr, nullptr, nullptr, nullptr, b_hh,
                          BATCHD, 3 * HIDD, 512, 512, 512, 3 * HIDD, 3 * HIDD, 1.f, 0.f, 0);
        gru_k<<<ceil_div(BATCHD * HIDD / 2, TPB), TPB>>>();
        // output head
        gemm_bf<128, 64>(phst, pWout, gout, nullptr, nullptr, nullptr, nullptr, b_out,
                         BATCHD, GOUTD, 512, 512, 512, GOUTD, GOUTD, 1.f, 0.f, 0);
        finalize2_k<<<BATCHD, 256>>>(t, cvec);
    }

    output_k<<<ceil_div(OUT_TOTAL, TPB), TPB>>>(out);
    (void)in_sizes; (void)n_in; (void)out_size;
}

// round 8
// speedup vs baseline: 2.5606x; 1.1521x over previous
#include <cuda_runtime.h>
#include <cuda_bf16.h>
#include <math.h>
#include <stdint.h>

#define NVARD 600
#define NCD   1000
#define HIDD  1024
#define BATCHD 1024
#define MLPOUTD 2200
#define GIND4 3200
#define GOUTD 1600
#define MAXITERD 15
#define KKTN  750
#define GLD   1504
#define BLKD  150
#define BILD  152
#define XBL   1600
#define OUT_TOTAL (BATCHD*NVARD + BATCHD + BATCHD + MAXITERD*BATCHD + MAXITERD*BATCHD)

// ---------------- fp32 scratch ----------------
__device__ float g_inp[BATCHD*NVARD];
__device__ float g_nnout[BATCHD*MLPOUTD];
__device__ float g_hst[BATCHD*HIDD];
__device__ float g_lam[BATCHD*NVARD];
__device__ float g_lamnew[BATCHD*NVARD];
__device__ float g_s[BATCHD*NCD];
__device__ float g_snew[BATCHD*NCD];
__device__ float g_res[BATCHD*NCD];
__device__ float g_xi[BATCHD*NVARD];
__device__ float g_gi[BATCHD*3*HIDD];
__device__ float g_gh[BATCHD*3*HIDD];
__device__ float g_gout[BATCHD*GOUTD];
__device__ float g_G[KKTN*GLD];
__device__ float g_P[BLKD*GLD];
__device__ float g_Ucol[KKTN*BILD];
__device__ float g_Einv[BLKD*BILD];
__device__ float g_Ct[NVARD*NCD];
__device__ float g_v0[NVARD];
__device__ float g_bxi[NVARD];
__device__ float g_prim[MAXITERD*BATCHD];
__device__ float g_fp[MAXITERD*BATCHD];
__device__ double g_sum2[2];

// ---------------- packed bf16 (hi,lo) planes: uint2 per k-pair ----------------
__device__ uint2 sW1[HIDD*NVARD/2];
__device__ uint2 sW2[HIDD*HIDD/2];
__device__ uint2 sW3[MLPOUTD*HIDD/2];
__device__ uint2 sWg[HIDD*NVARD/2];
__device__ uint2 sWih4[3*HIDD*GIND4/2];
__device__ uint2 sWhh[3*HIDD*HIDD/2];
__device__ uint2 sWout[GOUTD*HIDD/2];
__device__ uint2 sC[NCD*NVARD/2];
__device__ uint2 sCt[NVARD*NCD/2];
__device__ uint2 sBxi[NVARD*XBL/2];
__device__ uint2 sbl[BATCHD*XBL/2];
__device__ uint2 sinp[BATCHD*NVARD/2];
__device__ uint2 sh1[BATCHD*HIDD/2];
__device__ uint2 sh2[BATCHD*HIDD/2];
__device__ uint2 shst[BATCHD*HIDD/2];
__device__ uint2 sxi[BATCHD*NVARD/2];
__device__ uint2 sres[BATCHD*NCD/2];
__device__ uint2 sr4[BATCHD*GIND4/2];   // [s(500p) | lam(300p) | s'(500p) | lam'(300p)] ld=1600

__device__ __forceinline__ uint2 packsplit(float x0, float x1) {
    __nv_bfloat16 h0 = __float2bfloat16(x0);
    __nv_bfloat16 h1 = __float2bfloat16(x1);
    float r0 = x0 - __bfloat162float(h0);
    float r1 = x1 - __bfloat162float(h1);
    __nv_bfloat16 l0 = __float2bfloat16(r0);
    __nv_bfloat16 l1 = __float2bfloat16(r1);
    uint2 o;
    o.x = (uint32_t)__bfloat16_as_ushort(h0) | ((uint32_t)__bfloat16_as_ushort(h1) << 16);
    o.y = (uint32_t)__bfloat16_as_ushort(l0) | ((uint32_t)__bfloat16_as_ushort(l1) << 16);
    return o;
}

#define MMA_BF16(ac, a0, a1, a2, a3, b0, b1) \
    asm volatile("mma.sync.aligned.m16n8k16.row.col.f32.bf16.bf16.f32 " \
                 "{%0,%1,%2,%3},{%4,%5,%6,%7},{%8,%9},{%0,%1,%2,%3};" \
                 : "+f"(ac[0]), "+f"(ac[1]), "+f"(ac[2]), "+f"(ac[3]) \
                 : "r"(a0), "r"(a1), "r"(a2), "r"(a3), "r"(b0), "r"(b1))

// ===================================================================
// 3xBF16 tensor-core GEMM. B is [N,K] (i.e. B^T applied). Kp = K/2 pairs.
// C = act(alpha*A@B^T + beta*Cin + bias)
// act: 0 none, 1 relu, 2 tanh, 3 dual: C=relu(bias-acc), C2=relu(acc-bias)
// Csp: packed split of C (act!=3) or of the s-output (act==3), pair-ld = ldsp
// Csp2: packed split of C2 (act==3 only), pair-ld = ldsp2
// ===================================================================
#define KCH 16

template<int TBM, int TBN>
__global__ void __launch_bounds__(256)
gemm_bf_k(const uint2* __restrict__ A, const uint2* __restrict__ B,
          float* __restrict__ C, float* __restrict__ C2,
          uint2* __restrict__ Csp, uint2* __restrict__ Csp2,
          const float* __restrict__ Cin, const float* __restrict__ bias,
          int M, int N, int Kp, int ldap, int ldbp, int ldc, int ldcin,
          int ldsp, int ldsp2, float alpha, float beta, int act)
{
    constexpr int WM = TBM / 2;
    constexpr int WN = TBN / 4;
    constexpr int MM = WM / 16;
    constexpr int NN = WN / 8;
    constexpr int APT = TBM * KCH / 256;
    constexpr int BPT = TBN * KCH / 256;
    constexpr int ALD = TBM + 4;
    constexpr int BLD = TBN + 4;

    extern __shared__ uint2 smu[];
    uint2* As = smu;
    uint2* Bs = smu + 2 * KCH * ALD;

    const int tid = threadIdx.x;
    const int wid = tid >> 5;
    const int lane = tid & 31;
    const int lr = lane >> 2;
    const int lc = lane & 3;
    const int warp_m = wid >> 2;
    const int warp_n = wid & 3;
    const int m0 = blockIdx.y * TBM;
    const int n0 = blockIdx.x * TBN;

    float acc[MM][NN][4];
#pragma unroll
    for (int i = 0; i < MM; i++)
#pragma unroll
        for (int j = 0; j < NN; j++)
#pragma unroll
            for (int q = 0; q < 4; q++) acc[i][j][q] = 0.f;

    const int nchunks = (Kp + KCH - 1) / KCH;
    const uint2 z2 = make_uint2(0u, 0u);
    uint2 ra[APT], rb[BPT];

    // prologue: chunk 0
    {
#pragma unroll
        for (int i = 0; i < APT; i++) {
            int e = tid + i * 256;
            int row = e >> 4, kp = e & 15;
            int gm = m0 + row;
            ra[i] = (gm < M && kp < Kp) ? A[gm * ldap + kp] : z2;
        }
#pragma unroll
        for (int i = 0; i < BPT; i++) {
            int e = tid + i * 256;
            int row = e >> 4, kp = e & 15;
            int gn = n0 + row;
            rb[i] = (gn < N && kp < Kp) ? B[gn * ldbp + kp] : z2;
        }
#pragma unroll
        for (int i = 0; i < APT; i++) {
            int e = tid + i * 256;
            As[(e & 15) * ALD + (e >> 4)] = ra[i];
        }
#pragma unroll
        for (int i = 0; i < BPT; i++) {
            int e = tid + i * 256;
            Bs[(e & 15) * BLD + (e >> 4)] = rb[i];
        }
        __syncthreads();
    }

    for (int ch = 0; ch < nchunks; ch++) {
        const int cur = ch & 1;
        const bool have_next = (ch + 1 < nchunks);

        if (have_next) {
            const int kk = (ch + 1) * KCH;
#pragma unroll
            for (int i = 0; i < APT; i++) {
                int e = tid + i * 256;
                int row = e >> 4, kp = e & 15;
                int gm = m0 + row, gk = kk + kp;
                ra[i] = (gm < M && gk < Kp) ? A[gm * ldap + gk] : z2;
            }
#pragma unroll
            for (int i = 0; i < BPT; i++) {
                int e = tid + i * 256;
                int row = e >> 4, kp = e & 15;
                int gn = n0 + row, gk = kk + kp;
                rb[i] = (gn < N && gk < Kp) ? B[gn * ldbp + gk] : z2;
            }
        }

#pragma unroll
        for (int kb = 0; kb < 2; kb++) {
            uint2 af[MM][4];
            uint2 bf[NN][2];
            const int kof = (cur * KCH + kb * 8);
#pragma unroll
            for (int mm = 0; mm < MM; mm++) {
                int mrow = warp_m * WM + mm * 16 + lr;
                af[mm][0] = As[(kof + lc) * ALD + mrow];
                af[mm][1] = As[(kof + lc) * ALD + mrow + 8];
                af[mm][2] = As[(kof + 4 + lc) * ALD + mrow];
                af[mm][3] = As[(kof + 4 + lc) * ALD + mrow + 8];
            }
#pragma unroll
            for (int nn = 0; nn < NN; nn++) {
                int ncol = warp_n * WN + nn * 8 + lr;
                bf[nn][0] = Bs[(kof + lc) * BLD + ncol];
                bf[nn][1] = Bs[(kof + 4 + lc) * BLD + ncol];
            }
#pragma unroll
            for (int mm = 0; mm < MM; mm++)
#pragma unroll
                for (int nn = 0; nn < NN; nn++)
                    MMA_BF16(acc[mm][nn], af[mm][0].y, af[mm][1].y, af[mm][2].y, af[mm][3].y,
                             bf[nn][0].x, bf[nn][1].x);
#pragma unroll
            for (int mm = 0; mm < MM; mm++)
#pragma unroll
                for (int nn = 0; nn < NN; nn++)
                    MMA_BF16(acc[mm][nn], af[mm][0].x, af[mm][1].x, af[mm][2].x, af[mm][3].x,
                             bf[nn][0].y, bf[nn][1].y);
#pragma unroll
            for (int mm = 0; mm < MM; mm++)
#pragma unroll
                for (int nn = 0; nn < NN; nn++)
                    MMA_BF16(acc[mm][nn], af[mm][0].x, af[mm][1].x, af[mm][2].x, af[mm][3].x,
                             bf[nn][0].x, bf[nn][1].x);
        }

        if (have_next) {
            const int nxt = cur ^ 1;
#pragma unroll
            for (int i = 0; i < APT; i++) {
                int e = tid + i * 256;
                As[(nxt * KCH + (e & 15)) * ALD + (e >> 4)] = ra[i];
            }
#pragma unroll
            for (int i = 0; i < BPT; i++) {
                int e = tid + i * 256;
                Bs[(nxt * KCH + (e & 15)) * BLD + (e >> 4)] = rb[i];
            }
        }
        __syncthreads();
    }

    // epilogue
#pragma unroll
    for (int mm = 0; mm < MM; mm++) {
        int r0 = m0 + warp_m * WM + mm * 16 + lr;
#pragma unroll
        for (int nn = 0; nn < NN; nn++) {
            int c0 = n0 + warp_n * WN + nn * 8 + lc * 2;
            if (c0 >= N) continue;
            float v[4];
#pragma unroll
            for (int q = 0; q < 4; q++) {
                int row = r0 + (q >> 1) * 8;
                int col = c0 + (q & 1);
                float x = alpha * acc[mm][nn][q];
                if (beta != 0.f) x += beta * Cin[row * ldcin + col];
                v[q] = x;
            }
            if (act == 3) {
                float cc0 = bias[c0], cc1 = bias[c0 + 1];
                float s0 = fmaxf(cc0 - v[0], 0.f), s1 = fmaxf(cc1 - v[1], 0.f);
                float s2 = fmaxf(cc0 - v[2], 0.f), s3 = fmaxf(cc1 - v[3], 0.f);
                float r0v = fmaxf(v[0] - cc0, 0.f), r1v = fmaxf(v[1] - cc1, 0.f);
                float r2v = fmaxf(v[2] - cc0, 0.f), r3v = fmaxf(v[3] - cc1, 0.f);
                C[r0 * ldc + c0] = s0;       C[r0 * ldc + c0 + 1] = s1;
                C[(r0 + 8) * ldc + c0] = s2; C[(r0 + 8) * ldc + c0 + 1] = s3;
                C2[r0 * ldc + c0] = r0v;       C2[r0 * ldc + c0 + 1] = r1v;
                C2[(r0 + 8) * ldc + c0] = r2v; C2[(r0 + 8) * ldc + c0 + 1] = r3v;
                if (Csp) {
                    Csp[r0 * ldsp + (c0 >> 1)] = packsplit(s0, s1);
                    Csp[(r0 + 8) * ldsp + (c0 >> 1)] = packsplit(s2, s3);
                }
                if (Csp2) {
                    Csp2[r0 * ldsp2 + (c0 >> 1)] = packsplit(r0v, r1v);
                    Csp2[(r0 + 8) * ldsp2 + (c0 >> 1)] = packsplit(r2v, r3v);
                }
            } else {
                if (bias) { v[0] += bias[c0]; v[1] += bias[c0 + 1]; v[2] += bias[c0]; v[3] += bias[c0 + 1]; }
                if (act == 1) {
#pragma unroll
                    for (int q = 0; q < 4; q++) v[q] = fmaxf(v[q], 0.f);
                } else if (act == 2) {
#pragma unroll
                    for (int q = 0; q < 4; q++) v[q] = tanhf(v[q]);
                }
                C[r0 * ldc + c0] = v[0];       C[r0 * ldc + c0 + 1] = v[1];
                C[(r0 + 8) * ldc + c0] = v[2]; C[(r0 + 8) * ldc + c0 + 1] = v[3];
                if (Csp) {
                    Csp[r0 * ldsp + (c0 >> 1)] = packsplit(v[0], v[1]);
                    Csp[(r0 + 8) * ldsp + (c0 >> 1)] = packsplit(v[2], v[3]);
                }
            }
        }
    }
}

// ---------------- fp32 SIMT GEMM (KKT pipeline only) --------
#define BM 64
#define BN 64
#define BKK 16

__global__ void gemm_k(const float* __restrict__ A, const float* __restrict__ B,
                       float* __restrict__ C, const float* __restrict__ Cin,
                       int M, int N, int K, int lda, int ldb, int ldc, int ldcin,
                       int transB, float alpha, float beta)
{
    __shared__ float As[BKK][BM];
    __shared__ float Bs[BKK][BN];
    const int tid = threadIdx.x;
    const int tx = tid & 15, ty = tid >> 4;
    const int m0 = blockIdx.y * BM, n0 = blockIdx.x * BN;
    float acc[4][4] = {};

    for (int kk = 0; kk < K; kk += BKK) {
#pragma unroll
        for (int i = 0; i < 4; i++) {
            int e = tid + i * 256;
            int m = e >> 4, k = e & 15;
            int gm = m0 + m, gk = kk + k;
            As[k][m] = (gm < M && gk < K) ? A[gm * lda + gk] : 0.f;
        }
        if (transB) {
#pragma unroll
            for (int i = 0; i < 4; i++) {
                int e = tid + i * 256;
                int n = e >> 4, k = e & 15;
                int gn = n0 + n, gk = kk + k;
                Bs[k][n] = (gn < N && gk < K) ? B[gn * ldb + gk] : 0.f;
            }
        } else {
#pragma unroll
            for (int i = 0; i < 4; i++) {
                int e = tid + i * 256;
                int k = e >> 6, n = e & 63;
                int gn = n0 + n, gk = kk + k;
                Bs[k][n] = (gn < N && gk < K) ? B[gk * ldb + gn] : 0.f;
            }
        }
        __syncthreads();
#pragma unroll
        for (int k = 0; k < BKK; k++) {
            float a0 = As[k][ty*4+0], a1 = As[k][ty*4+1], a2 = As[k][ty*4+2], a3 = As[k][ty*4+3];
            float b0 = Bs[k][tx*4+0], b1 = Bs[k][tx*4+1], b2 = Bs[k][tx*4+2], b3 = Bs[k][tx*4+3];
            acc[0][0] += a0*b0; acc[0][1] += a0*b1; acc[0][2] += a0*b2; acc[0][3] += a0*b3;
            acc[1][0] += a1*b0; acc[1][1] += a1*b1; acc[1][2] += a1*b2; acc[1][3] += a1*b3;
            acc[2][0] += a2*b0; acc[2][1] += a2*b1; acc[2][2] += a2*b2; acc[2][3] += a2*b3;
            acc[3][0] += a3*b0; acc[3][1] += a3*b1; acc[3][2] += a3*b2; acc[3][3] += a3*b3;
        }
        __syncthreads();
    }

#pragma unroll
    for (int i = 0; i < 4; i++) {
        int row = m0 + ty*4 + i;
        if (row >= M) continue;
#pragma unroll
        for (int j = 0; j < 4; j++) {
            int col = n0 + tx*4 + j;
            if (col >= N) continue;
            float v = alpha * acc[i][j];
            if (beta != 0.f) v += beta * Cin[row * ldcin + col];
            C[row * ldc + col] = v;
        }
    }
}

// ---------------- split / setup kernels ----------------
__global__ void splitpair_k(const float* __restrict__ x, uint2* __restrict__ y, int npairs) {
    int i = blockIdx.x * blockDim.x + threadIdx.x;
    if (i < npairs) y[i] = packsplit(x[2*i], x[2*i+1]);
}

__global__ void combine_Wih_k(const float* __restrict__ W) {
    int idx = blockIdx.x * blockDim.x + threadIdx.x;
    if (idx >= 3 * HIDD * GIND4 / 2) return;
    int i = idx / (GIND4/2), pp = idx % (GIND4/2);
    int j = 2 * pp;
    const float* row = W + i * 4800;
    float v0, v1;
    if (j < 1000)       { v0 = row[j] - row[3200 + j];           v1 = row[j+1] - row[3200 + j + 1]; }
    else if (j < 1600)  { v0 = row[j] - row[4200 + (j - 1000)];  v1 = row[j+1] - row[4200 + (j - 999)]; }
    else if (j < 2600)  { v0 = row[j] + row[3200 + (j - 1600)];  v1 = row[j+1] + row[3200 + (j - 1599)]; }
    else                { v0 = row[j] + row[4200 + (j - 2600)];  v1 = row[j+1] + row[4200 + (j - 2599)]; }
    sWih4[idx] = packsplit(v0, v1);
}

__global__ void build_Bxi_k(const float* __restrict__ CM) {
    int idx = blockIdx.x * blockDim.x + threadIdx.x;
    if (idx >= NVARD * XBL / 2) return;
    int n = idx / (XBL/2), kp = idx % (XBL/2);
    int k0 = 2 * kp;
    float v0, v1;
    if (k0 < 1000) { v0 = CM[k0 * NVARD + n]; v1 = CM[(k0+1) * NVARD + n]; }
    else { v0 = g_G[(k0 - 1000) * GLD + 750 + n]; v1 = g_G[(k0 - 999) * GLD + 750 + n]; }
    sBxi[idx] = packsplit(v0, v1);
}

__global__ void bias_xi_k(const float* __restrict__ gv) {
    int n = blockIdx.x * blockDim.x + threadIdx.x;
    if (n >= NVARD) return;
    float acc = 0.f;
    for (int k = 0; k < NVARD; k++) acc += gv[k] * g_G[k * GLD + 750 + n];
    g_bxi[n] = g_v0[n] - acc;
}

// ---------------- statistics / normalization ----------------
__global__ void stats_zero_k() { g_sum2[0] = 0.0; g_sum2[1] = 0.0; }

__global__ void stats_k(const float* __restrict__ x, int n) {
    float s = 0.f, ss = 0.f;
    for (int i = blockIdx.x * blockDim.x + threadIdx.x; i < n; i += gridDim.x * blockDim.x) {
        float v = x[i]; s += v; ss += v * v;
    }
    __shared__ float s1[256], s2[256];
    s1[threadIdx.x] = s; s2[threadIdx.x] = ss;
    __syncthreads();
    for (int o = 128; o > 0; o >>= 1) {
        if (threadIdx.x < o) { s1[threadIdx.x] += s1[threadIdx.x+o]; s2[threadIdx.x] += s2[threadIdx.x+o]; }
        __syncthreads();
    }
    if (threadIdx.x == 0) {
        atomicAdd(&g_sum2[0], (double)s1[0]);
        atomicAdd(&g_sum2[1], (double)s2[0]);
    }
}

__global__ void normalize_k(const float* __restrict__ x, int npairs) {
    double sum = g_sum2[0], sumsq = g_sum2[1];
    const double nn = (double)(2 * npairs);
    double mean = sum / nn;
    double var = (sumsq - sum * sum / nn) / (nn - 1.0);
    float istd = 1.0f / ((float)sqrt(var) + 1e-8f);
    float m = (float)mean;
    for (int i = blockIdx.x * blockDim.x + threadIdx.x; i < npairs; i += gridDim.x * blockDim.x) {
        float v0 = (x[2*i] - m) * istd;
        float v1 = (x[2*i+1] - m) * istd;
        g_inp[2*i] = v0; g_inp[2*i+1] = v1;
        sinp[i] = packsplit(v0, v1);
    }
}

// ---------------- small setup kernels ----------------
// writes s, lam (fp32), packed [c-s|lam] into sbl, and packed s,lam into sr4 seg0/seg1
__global__ void split_nnout2_k(const float* __restrict__ cvec) {
    int idx = blockIdx.x * blockDim.x + threadIdx.x;
    if (idx >= BATCHD * 800) return;
    int b = idx / 800, pp = idx % 800;
    if (pp < 500) {
        int j = 2 * pp;
        float s0 = fmaxf(g_nnout[b * MLPOUTD + 1200 + j], 0.f);
        float s1 = fmaxf(g_nnout[b * MLPOUTD + 1200 + j + 1], 0.f);
        g_s[b * NCD + j] = s0; g_s[b * NCD + j + 1] = s1;
        sbl[b * 800 + pp] = packsplit(cvec[j] - s0, cvec[j+1] - s1);
        sr4[b * 1600 + pp] = packsplit(s0, s1);
    } else {
        int r = 2 * (pp - 500);
        float l0 = g_nnout[b * MLPOUTD + 600 + r];
        float l1 = g_nnout[b * MLPOUTD + 600 + r + 1];
        g_lam[b * NVARD + r] = l0; g_lam[b * NVARD + r + 1] = l1;
        uint2 pk = packsplit(l0, l1);
        sbl[b * 800 + pp] = pk;
        sr4[b * 1600 + pp] = pk;   // seg1 at pair offset 500..799
    }
}

__global__ void transpose_C_k(const float* __restrict__ Cm) {
    int idx = blockIdx.x * blockDim.x + threadIdx.x;
    if (idx >= NVARD * NCD / 2) return;
    int i = idx / (NCD/2), kp = idx % (NCD/2);
    float v0 = Cm[(2*kp) * NVARD + i];
    float v1 = Cm[(2*kp+1) * NVARD + i];
    g_Ct[i * NCD + 2*kp] = v0;
    g_Ct[i * NCD + 2*kp+1] = v1;
    sCt[idx] = packsplit(v0, v1);
}

__global__ void init_G_k() {
    int idx = blockIdx.x * blockDim.x + threadIdx.x;
    if (idx >= KKTN * GLD) return;
    int r = idx / GLD, c = idx % GLD;
    float v = 0.f;
    if (c >= 750) {
        if (c - 750 == r) v = 1.f;
    } else if (r >= 600 && c < 600) {
        int rr = r - 600, t = rr / 3, i = rr % 3;
        if (c / 12 == t && (c % 12) % 3 == i) v = 1.f;
    } else if (r < 600 && c >= 600) {
        int cc = c - 600, t = cc / 3, i = cc % 3;
        if (r / 12 == t && (r % 12) % 3 == i) v = 1.f;
    }
    g_G[idx] = v;
}

__global__ void v0_k() {
    int j = blockIdx.x * blockDim.x + threadIdx.x;
    if (j >= NVARD) return;
    float acc = 0.f;
    for (int t = 0; t < 50; t++) acc += g_G[j * GLD + 750 + 600 + 3 * t + 2];
    g_v0[j] = 30.0f * 9.81f * acc;
}

// ---------------- blocked Gauss-Jordan helpers ----------------
__global__ void copy_cols_k(int kb) {
    int idx = blockIdx.x * blockDim.x + threadIdx.x;
    if (idx >= KKTN * BLKD) return;
    int r = idx / BLKD, j = idx % BLKD;
    g_Ucol[r * BILD + j] = g_G[r * GLD + kb * BLKD + j];
}

__global__ void inv_block_k(int kb) {
    extern __shared__ float s[];
    const int n = BLKD, ld = BILD;
    int tid = threadIdx.x, nt = blockDim.x;
    for (int e = tid; e < n * n; e += nt)
        s[(e / n) * ld + (e % n)] = g_Ucol[(kb * BLKD + e / n) * BILD + (e % n)];
    __shared__ float fcol[BLKD];
    __shared__ float s_ipiv;
    __syncthreads();
    for (int p = 0; p < n; p++) {
        if (tid == 0) s_ipiv = 1.0f / s[p * ld + p];
        __syncthreads();
        float ipiv = s_ipiv;
        for (int j = tid; j < n; j += nt) if (j != p) s[p * ld + j] *= ipiv;
        for (int r = tid; r < n; r += nt) fcol[r] = (r == p) ? 0.f : s[r * ld + p];
        __syncthreads();
        for (int e = tid; e < n * n; e += nt) {
            int r = e / n, j = e % n;
            if (r != p && j != p) s[r * ld + j] -= fcol[r] * s[p * ld + j];
        }
        __syncthreads();
        for (int r = tid; r < n; r += nt) {
            if (r == p) s[p * ld + p] = ipiv;
            else s[r * ld + p] = -fcol[r] * ipiv;
        }
        __syncthreads();
    }
    for (int e = tid; e < n * n; e += nt)
        g_Einv[(e / n) * BILD + (e % n)] = s[(e / n) * ld + (e % n)];
}

__global__ void writeback_k(int kb) {
    int idx = blockIdx.x * blockDim.x + threadIdx.x;
    if (idx >= BLKD * GLD) return;
    int r = idx / GLD, j = idx % GLD;
    g_G[(kb * BLKD + r) * GLD + j] = g_P[idx];
    if (j < BILD) g_Ucol[(kb * BLKD + r) * BILD + j] = 0.f;
}

// ---------------- iteration elementwise kernels ----------------
__global__ void rownorm_k(const float* __restrict__ v, int ncols, float* __restrict__ out) {
    int b = blockIdx.x;
    float acc = 0.f;
    for (int j = threadIdx.x; j < ncols; j += blockDim.x) {
        float t = v[b * ncols + j]; acc += t * t;
    }
    __shared__ float sm[256];
    sm[threadIdx.x] = acc; __syncthreads();
    for (int o = 128; o > 0; o >>= 1) {
        if (threadIdx.x < o) sm[threadIdx.x] += sm[threadIdx.x + o];
        __syncthreads();
    }
    if (threadIdx.x == 0) out[b] = sqrtf(sm[0]);
}

__device__ __forceinline__ float sigmoidf(float x) { return 1.0f / (1.0f + expf(-x)); }

__global__ void gru_k() {
    int p = blockIdx.x * blockDim.x + threadIdx.x;
    if (p >= BATCHD * HIDD / 2) return;
    int b = p / 512, jp = p % 512;
    int j = 2 * jp;
    int base = b * 3 * HIDD + j;
    float h0, h1;
#pragma unroll
    for (int e = 0; e < 2; e++) {
        float ir = g_gi[base + e], iz = g_gi[base + HIDD + e], in_ = g_gi[base + 2 * HIDD + e];
        float hr = g_gh[base + e], hz = g_gh[base + HIDD + e], hn = g_gh[base + 2 * HIDD + e];
        float rg = sigmoidf(ir + hr);
        float z  = sigmoidf(iz + hz);
        float nv = tanhf(in_ + rg * hn);
        float h  = g_hst[b * HIDD + j + e];
        float hnew = (1.f - z) * nv + z * h;
        g_hst[b * HIDD + j + e] = hnew;
        if (e == 0) h0 = hnew; else h1 = hnew;
    }
    shst[b * 512 + jp] = packsplit(h0, h1);
}

// s/lam update + fp norm + packed [c-s|lam] (sbl) + packed s,lam (sr4 seg0/seg1)
__global__ void finalize2_k(int t, const float* __restrict__ cvec) {
    int b = blockIdx.x;
    float accs = 0.f, accl = 0.f;
    for (int pj = threadIdx.x; pj < 800; pj += blockDim.x) {
        int j = 2 * pj;
        if (j < NCD) {
            float go0 = g_gout[b * GOUTD + j], go1 = g_gout[b * GOUTD + j + 1];
            float sf0 = fmaxf(g_snew[b * NCD + j] + go0, 0.f);
            float sf1 = fmaxf(g_snew[b * NCD + j + 1] + go1, 0.f);
            float d0 = sf0 - g_s[b * NCD + j], d1 = sf1 - g_s[b * NCD + j + 1];
            accs += d0 * d0 + d1 * d1;
            g_s[b * NCD + j] = sf0; g_s[b * NCD + j + 1] = sf1;
            sbl[b * 800 + pj] = packsplit(cvec[j] - sf0, cvec[j+1] - sf1);
            sr4[b * 1600 + pj] = packsplit(sf0, sf1);
        } else {
            int j2 = j - NCD;
            float go0 = g_gout[b * GOUTD + j], go1 = g_gout[b * GOUTD + j + 1];
            float lf0 = g_lamnew[b * NVARD + j2] + go0;
            float lf1 = g_lamnew[b * NVARD + j2 + 1] + go1;
            float d0 = lf0 - g_lam[b * NVARD + j2], d1 = lf1 - g_lam[b * NVARD + j2 + 1];
            accl += d0 * d0 + d1 * d1;
            g_lam[b * NVARD + j2] = lf0; g_lam[b * NVARD + j2 + 1] = lf1;
            uint2 pk = packsplit(lf0, lf1);
            sbl[b * 800 + pj] = pk;
            sr4[b * 1600 + pj] = pk;   // seg1 pairs 500..799
        }
    }
    __shared__ float sm1[256], sm2[256];
    sm1[threadIdx.x] = accs; sm2[threadIdx.x] = accl;
    __syncthreads();
    for (int o = 128; o > 0; o >>= 1) {
        if (threadIdx.x < o) { sm1[threadIdx.x] += sm1[threadIdx.x+o]; sm2[threadIdx.x] += sm2[threadIdx.x+o]; }
        __syncthreads();
    }
    if (threadIdx.x == 0)
        g_fp[t * BATCHD + b] = sqrtf(sm2[0]) + sqrtf(sm1[0]);
}

// ---------------- output assembly ----------------
__global__ void output_k(float* __restrict__ out) {
    int idx = blockIdx.x * blockDim.x + threadIdx.x;
    if (idx >= OUT_TOTAL) return;
    const int XI_END = BATCHD * NVARD;
    const int AFP_END = XI_END + BATCHD;
    const int APR_END = AFP_END + BATCHD;
    const int PH_END = APR_END + MAXITERD * BATCHD;
    if (idx < XI_END) out[idx] = g_xi[idx];
    else if (idx < AFP_END) {
        int b = idx - XI_END;
        float a = 0.f;
        for (int t = 0; t < MAXITERD; t++) a += g_fp[t * BATCHD + b];
        out[idx] = a / (float)MAXITERD;
    } else if (idx < APR_END) {
        int b = idx - AFP_END;
        float a = 0.f;
        for (int t = 0; t < MAXITERD; t++) a += g_prim[t * BATCHD + b];
        out[idx] = a / (float)MAXITERD;
    } else if (idx < PH_END) out[idx] = g_prim[idx - APR_END];
    else out[idx] = g_fp[idx - PH_END];
}

// ---------------- host side ----------------
static inline int ceil_div(int a, int b) { return (a + b - 1) / b; }

static void gemm(const float* A, const float* B, float* C, const float* Cin,
                 int M, int N, int K, int lda, int ldb, int ldc, int ldcin,
                 int transB, float alpha, float beta)
{
    dim3 grid((N + BN - 1) / BN, (M + BM - 1) / BM);
    gemm_k<<<grid, 256>>>(A, B, C, Cin, M, N, K, lda, ldb, ldc, ldcin, transB, alpha, beta);
}

template<int TBM, int TBN>
static void gemm_bf(const uint2* A, const uint2* B, float* C, float* C2,
                    uint2* Csp, uint2* Csp2, const float* Cin, const float* bias,
                    int M, int N, int Kp, int ldap, int ldbp, int ldc, int ldcin,
                    int ldsp, int ldsp2, float alpha, float beta, int act)
{
    size_t smem = (size_t)(2 * KCH * (TBM + 4) + 2 * KCH * (TBN + 4)) * sizeof(uint2);
    dim3 grid((N + TBN - 1) / TBN, (M + TBM - 1) / TBM);
    gemm_bf_k<TBM, TBN><<<grid, 256, smem>>>(A, B, C, C2, Csp, Csp2, Cin, bias,
                                             M, N, Kp, ldap, ldbp, ldc, ldcin,
                                             ldsp, ldsp2, alpha, beta, act);
}

extern "C" void kernel_launch(void* const* d_in, const int* in_sizes, int n_in,
                              void* d_out, int out_size) {
    const float* X    = (const float*)d_in[0];
    const float* Hm   = (const float*)d_in[1];
    const float* gv   = (const float*)d_in[2];
    const float* Cm   = (const float*)d_in[3];
    const float* cvec = (const float*)d_in[4];
    const float* W1   = (const float*)d_in[5];
    const float* b1   = (const float*)d_in[6];
    const float* W2   = (const float*)d_in[7];
    const float* b2   = (const float*)d_in[8];
    const float* W3   = (const float*)d_in[9];
    const float* b3   = (const float*)d_in[10];
    const float* Wg   = (const float*)d_in[11];
    const float* bg   = (const float*)d_in[12];
    const float* W_ih = (const float*)d_in[13];
    const float* W_hh = (const float*)d_in[14];
    const float* b_ih = (const float*)d_in[15];
    const float* b_hh = (const float*)d_in[16];
    const float* W_out= (const float*)d_in[17];
    const float* b_out= (const float*)d_in[18];
    float* out = (float*)d_out;

    float *nnout, *hst, *lam, *lamnew, *s, *snew, *res, *xi, *gi, *gh, *gout,
          *G, *P, *Ucol, *Einv, *Ct, *prim, *fp, *bxi;
    uint2 *pW1, *pW2, *pW3, *pWg, *pWih4, *pWhh, *pWout, *pC, *pCt, *pBxi,
          *pbl, *pinp, *ph1, *ph2, *phst, *pxi, *pres, *pr4;
    cudaGetSymbolAddress((void**)&nnout, g_nnout);
    cudaGetSymbolAddress((void**)&hst, g_hst);
    cudaGetSymbolAddress((void**)&lam, g_lam);
    cudaGetSymbolAddress((void**)&lamnew, g_lamnew);
    cudaGetSymbolAddress((void**)&s, g_s);
    cudaGetSymbolAddress((void**)&snew, g_snew);
    cudaGetSymbolAddress((void**)&res, g_res);
    cudaGetSymbolAddress((void**)&xi, g_xi);
    cudaGetSymbolAddress((void**)&gi, g_gi);
    cudaGetSymbolAddress((void**)&gh, g_gh);
    cudaGetSymbolAddress((void**)&gout, g_gout);
    cudaGetSymbolAddress((void**)&G, g_G);
    cudaGetSymbolAddress((void**)&P, g_P);
    cudaGetSymbolAddress((void**)&Ucol, g_Ucol);
    cudaGetSymbolAddress((void**)&Einv, g_Einv);
    cudaGetSymbolAddress((void**)&Ct, g_Ct);
    cudaGetSymbolAddress((void**)&prim, g_prim);
    cudaGetSymbolAddress((void**)&fp, g_fp);
    cudaGetSymbolAddress((void**)&bxi, g_bxi);
    cudaGetSymbolAddress((void**)&pW1, sW1);
    cudaGetSymbolAddress((void**)&pW2, sW2);
    cudaGetSymbolAddress((void**)&pW3, sW3);
    cudaGetSymbolAddress((void**)&pWg, sWg);
    cudaGetSymbolAddress((void**)&pWih4, sWih4);
    cudaGetSymbolAddress((void**)&pWhh, sWhh);
    cudaGetSymbolAddress((void**)&pWout, sWout);
    cudaGetSymbolAddress((void**)&pC, sC);
    cudaGetSymbolAddress((void**)&pCt, sCt);
    cudaGetSymbolAddress((void**)&pBxi, sBxi);
    cudaGetSymbolAddress((void**)&pbl, sbl);
    cudaGetSymbolAddress((void**)&pinp, sinp);
    cudaGetSymbolAddress((void**)&ph1, sh1);
    cudaGetSymbolAddress((void**)&ph2, sh2);
    cudaGetSymbolAddress((void**)&phst, shst);
    cudaGetSymbolAddress((void**)&pxi, sxi);
    cudaGetSymbolAddress((void**)&pres, sres);
    cudaGetSymbolAddress((void**)&pr4, sr4);

    float* h1f = gi;    // fp32 staging (only the split output is consumed)
    float* h2f = gh;
    float* CMf = gi;    // C@M computed after MLP phase

    cudaFuncSetAttribute(inv_block_k, cudaFuncAttributeMaxDynamicSharedMemorySize,
                         BLKD * BILD * (int)sizeof(float));
    cudaFuncSetAttribute(gemm_bf_k<128, 128>, cudaFuncAttributeMaxDynamicSharedMemorySize,
                         (2 * KCH * 132 + 2 * KCH * 132) * (int)sizeof(uint2));
    cudaFuncSetAttribute(gemm_bf_k<128, 64>, cudaFuncAttributeMaxDynamicSharedMemorySize,
                         (2 * KCH * 132 + 2 * KCH * 68) * (int)sizeof(uint2));

    const int TPB = 256;
    const int NTOT = BATCHD * NVARD;

    // ---- launches ordered so #5 (profiled) is gemm_bf_k ----
    stats_zero_k<<<1, 1>>>();                                                       // 0
    stats_k<<<512, TPB>>>(X, NTOT);                                                 // 1
    splitpair_k<<<ceil_div(HIDD * NVARD / 2, TPB), TPB>>>(W1, pW1, HIDD * NVARD / 2); // 2
    normalize_k<<<ceil_div(NTOT / 2, TPB), TPB>>>(X, NTOT / 2);                     // 3
    splitpair_k<<<ceil_div(HIDD * HIDD / 2, TPB), TPB>>>(W2, pW2, HIDD * HIDD / 2); // 4
    gemm_bf<128, 64>(pinp, pW1, h1f, nullptr, ph1, nullptr, nullptr, b1,            // 5
                     BATCHD, HIDD, 300, 300, 300, HIDD, HIDD, 512, 0, 1.f, 0.f, 1);
    splitpair_k<<<ceil_div(MLPOUTD * HIDD / 2, TPB), TPB>>>(W3, pW3, MLPOUTD * HIDD / 2);
    gemm_bf<128, 64>(ph1, pW2, h2f, nullptr, ph2, nullptr, nullptr, b2,
                     BATCHD, HIDD, 512, 512, 512, HIDD, HIDD, 512, 0, 1.f, 0.f, 1);
    splitpair_k<<<ceil_div(HIDD * NVARD / 2, TPB), TPB>>>(Wg, pWg, HIDD * NVARD / 2);
    gemm_bf<128, 128>(ph2, pW3, nnout, nullptr, nullptr, nullptr, nullptr, b3,
                      BATCHD, MLPOUTD, 512, 512, 512, MLPOUTD, MLPOUTD, 0, 0, 1.f, 0.f, 0);
    split_nnout2_k<<<ceil_div(BATCHD * 800, TPB), TPB>>>(cvec);
    gemm_bf<128, 64>(pinp, pWg, hst, nullptr, phst, nullptr, nullptr, bg,
                     BATCHD, HIDD, 300, 300, 300, HIDD, HIDD, 512, 0, 1.f, 0.f, 2);

    combine_Wih_k<<<ceil_div(3 * HIDD * GIND4 / 2, TPB), TPB>>>(W_ih);
    splitpair_k<<<ceil_div(3 * HIDD * HIDD / 2, TPB), TPB>>>(W_hh, pWhh, 3 * HIDD * HIDD / 2);
    splitpair_k<<<ceil_div(GOUTD * HIDD / 2, TPB), TPB>>>(W_out, pWout, GOUTD * HIDD / 2);
    splitpair_k<<<ceil_div(NCD * NVARD / 2, TPB), TPB>>>(Cm, pC, NCD * NVARD / 2);
    transpose_C_k<<<ceil_div(NVARD * NCD / 2, TPB), TPB>>>(Cm);

    // ---- KKT build + blocked Gauss-Jordan inverse (fp32 SIMT) ----
    init_G_k<<<ceil_div(KKTN * GLD, TPB), TPB>>>();
    gemm(Ct, Ct, G, Hm, NVARD, NVARD, NCD, NCD, NCD, GLD, NVARD, 1, 1.f, 1.f);
    for (int kb = 0; kb < KKTN / BLKD; kb++) {
        copy_cols_k<<<ceil_div(KKTN * BLKD, TPB), TPB>>>(kb);
        inv_block_k<<<1, 1024, BLKD * BILD * sizeof(float)>>>(kb);
        gemm(Einv, G + kb * BLKD * GLD, P, nullptr,
             BLKD, GLD, BLKD, BILD, GLD, GLD, 0, 0, 1.f, 0.f);
        writeback_k<<<ceil_div(BLKD * GLD, TPB), TPB>>>(kb);
        gemm(Ucol, P, G, G, KKTN, GLD, BLKD, BILD, GLD, GLD, GLD, 0, -1.f, 1.f);
    }
    v0_k<<<ceil_div(NVARD, TPB), TPB>>>();
    bias_xi_k<<<ceil_div(NVARD, TPB), TPB>>>(gv);
    gemm(Cm, G + 750, CMf, nullptr, NCD, NVARD, NVARD, NVARD, GLD, NVARD, 0, 0, 1.f, 0.f);
    build_Bxi_k<<<ceil_div(NVARD * XBL / 2, TPB), TPB>>>(CMf);

    // ---- 15 fixed-point iterations ----
    for (int t = 0; t < MAXITERD; t++) {
        // xi = [c-s | lam] @ [CM ; M]^T + (v0 - g@M)
        gemm_bf<128, 64>(pbl, pBxi, xi, nullptr, pxi, nullptr, nullptr, bxi,
                         BATCHD, NVARD, 800, 800, 800, NVARD, NVARD, 300, 0, 1.f, 0.f, 0);
        // Cx; s_new=relu(c-Cx) -> snew (+pack into sr4 seg2); res=relu(Cx-c) -> res (+pack pres)
        gemm_bf<128, 64>(pxi, pC, snew, res, pr4 + 800, pres, nullptr, cvec,
                         BATCHD, NCD, 300, 300, 300, NCD, NCD, 1600, 500, 1.f, 0.f, 3);
        rownorm_k<<<BATCHD, 256>>>(res, NCD, prim + t * BATCHD);
        // lam_new = lam - res @ C  (+pack into sr4 seg3)
        gemm_bf<128, 64>(pres, pCt, lamnew, nullptr, pr4 + 1300, nullptr, lam, nullptr,
                         BATCHD, NVARD, 500, 500, 500, NVARD, NVARD, 1600, 0, -1.f, 1.f, 0);
        // GRU gates: gi = r4 @ Wih4^T (K=3200)
        gemm_bf<128, 64>(pr4, pWih4, gi, nullptr, nullptr, nullptr, nullptr, b_ih,
                         BATCHD, 3 * HIDD, 1600, 1600, 1600, 3 * HIDD, 3 * HIDD, 0, 0, 1.f, 0.f, 0);
        gemm_bf<128, 64>(phst, pWhh, gh, nullptr, nullptr, nullptr, nullptr, b_hh,
                         BATCHD, 3 * HIDD, 512, 512, 512, 3 * HIDD, 3 * HIDD, 0, 0, 1.f, 0.f, 0);
        gru_k<<<ceil_div(BATCHD * HIDD / 2, TPB), TPB>>>();
        // output head
        gemm_bf<128, 64>(phst, pWout, gout, nullptr, nullptr, nullptr, nullptr, b_out,
                         BATCHD, GOUTD, 512, 512, 512, GOUTD, GOUTD, 0, 0, 1.f, 0.f, 0);
        finalize2_k<<<BATCHD, 256>>>(t, cvec);
    }

    output_k<<<ceil_div(OUT_TOTAL, TPB), TPB>>>(out);
    (void)in_sizes; (void)n_in; (void)out_size;
}